// round 3
// baseline (speedup 1.0000x reference)
#include <cuda_runtime.h>
#include <math.h>
#include <math_constants.h>

// Problem constants
#define BB    2
#define CC    256
#define NTOK  32768      // 32*32*32
#define SS    256
#define TDIM  512
#define NHD   8
#define HDIM  32

// ---------------- scratch (single __device__ array, no allocations) ----------------
#define OFF_H1    0                         // [B*S*256]      = 131072
#define OFF_KRAW  (OFF_H1   + 131072)       // [B*S*C]
#define OFF_VRAW  (OFF_KRAW + 131072)
#define OFF_PHASE (OFF_VRAW + 131072)
#define OFF_KROT  (OFF_PHASE+ 131072)       // [B,NH,S,HD]
#define OFF_VT    (OFF_KROT + 131072)
#define OFF_Q     (OFF_VT   + 131072)       // [B,N,C] = 16777216
#define OFF_AO    (OFF_Q    + 16777216)     // [B,N,C]
#define OFF_INVF  (OFF_AO   + 16777216)     // [32]
#define SCR_TOTAL (OFF_INVF + 32)

__device__ float g_scr[SCR_TOTAL];

// packed f32x2 helpers
#define FMA2(acc, a, b) asm("fma.rn.f32x2 %0, %1, %2, %0;" : "+l"(acc) : "l"(a), "l"(b))
__device__ __forceinline__ float2 u2f2(unsigned long long u) {
    float2 r;
    r.x = __uint_as_float((unsigned)(u & 0xffffffffull));
    r.y = __uint_as_float((unsigned)(u >> 32));
    return r;
}
typedef unsigned long long ull;

// ---------------- rope inverse-frequency table ----------------
__global__ void init_invf_kernel() {
    int d = threadIdx.x;
    if (d < 32) {
        float e;
        if (d < 10)       e = (float)(2 * (d % 5)) / 10.f;        // z section (zd=10)
        else if (d < 20)  e = (float)(2 * ((d - 10) % 5)) / 10.f; // y section (yd=10)
        else              e = (float)(2 * ((d - 20) % 6)) / 12.f; // x section (xd=12)
        g_scr[OFF_INVF + d] = powf(10000.f, -e);
    }
}

// ---------------- small GEMM body: BM=32, BN=64, BK=16, 256 thr, 2x4 micro ----------------
__device__ __forceinline__ void gemm32x64_body(const float* __restrict__ A,
                                               const float* __restrict__ W,
                                               const float* __restrict__ bias,
                                               float* __restrict__ Y,
                                               int K, int N, int act,
                                               int m0, int j0,
                                               float* As, float* Ws) {
    int t = threadIdx.x;
    int tx = t & 15, ty = t >> 4;
    float acc[2][4] = {};
    for (int k0 = 0; k0 < K; k0 += 16) {
        if (t < 128) {
            int m = t >> 2, kq = (t & 3) * 4;
            float4 av = *(const float4*)&A[(size_t)(m0 + m) * K + k0 + kq];
            As[(kq + 0) * 33 + m] = av.x;
            As[(kq + 1) * 33 + m] = av.y;
            As[(kq + 2) * 33 + m] = av.z;
            As[(kq + 3) * 33 + m] = av.w;
        }
        {
            int kk = t >> 4, j4 = (t & 15) * 4;
            *(float4*)&Ws[kk * 64 + j4] = *(const float4*)&W[(size_t)(k0 + kk) * N + j0 + j4];
        }
        __syncthreads();
        #pragma unroll
        for (int kk = 0; kk < 16; kk++) {
            float a0 = As[kk * 33 + ty * 2], a1 = As[kk * 33 + ty * 2 + 1];
            #pragma unroll
            for (int j = 0; j < 4; j++) {
                float w = Ws[kk * 64 + tx + 16 * j];
                acc[0][j] += a0 * w;
                acc[1][j] += a1 * w;
            }
        }
        __syncthreads();
    }
    #pragma unroll
    for (int j = 0; j < 4; j++) {
        int jj = j0 + tx + 16 * j;
        float bv = bias[jj];
        #pragma unroll
        for (int i = 0; i < 2; i++) {
            float v = acc[i][j] + bv;
            if (act) v = 0.5f * v * (1.f + erff(v * 0.70710678118654752f));  // exact GELU
            Y[(size_t)(m0 + ty * 2 + i) * N + jj] = v;
        }
    }
}

// fused 3-way text GEMM (k_w / v_w / m1_w all: M=512, K=512, N=256)
__global__ void text3_kernel(const float* __restrict__ text,
                             const float* __restrict__ kw, const float* __restrict__ kb,
                             const float* __restrict__ vw, const float* __restrict__ vb,
                             const float* __restrict__ m1w, const float* __restrict__ m1b) {
    __shared__ float As[16 * 33];
    __shared__ float Ws[16 * 64];
    const float *W, *bias;
    float* Y;
    int act = 0;
    if (blockIdx.z == 0)      { W = kw;  bias = kb;  Y = g_scr + OFF_KRAW; }
    else if (blockIdx.z == 1) { W = vw;  bias = vb;  Y = g_scr + OFF_VRAW; }
    else                      { W = m1w; bias = m1b; Y = g_scr + OFF_H1; act = 1; }
    gemm32x64_body(text, W, bias, Y, 512, 256, act, blockIdx.y * 32, blockIdx.x * 64, As, Ws);
}

// phase GEMM: H1[512,256] @ m2_w[256,256]
__global__ void phase_gemm_kernel(const float* __restrict__ m2w, const float* __restrict__ m2b) {
    __shared__ float As[16 * 33];
    __shared__ float Ws[16 * 64];
    gemm32x64_body(g_scr + OFF_H1, m2w, m2b, g_scr + OFF_PHASE, 256, 256, 0,
                   blockIdx.y * 32, blockIdx.x * 64, As, Ws);
}

// ---------------- text rope + [B,S,NH,HD] -> [B,NH,S,HD] transpose ----------------
__global__ void text_rope_kernel() {
    int idx = blockIdx.x * blockDim.x + threadIdx.x;  // < B*S*NH*16 = 65536
    int p = idx & 15;
    int h = (idx >> 4) & 7;
    int s = (idx >> 7) & 255;
    int b = idx >> 15;
    const float* kraw = g_scr + OFF_KRAW;
    const float* vraw = g_scr + OFF_VRAW;
    const float* ph   = g_scr + OFF_PHASE;
    float* krot = g_scr + OFF_KROT;
    float* vt   = g_scr + OFF_VT;
    int base = (b * SS + s) * CC + h * HDIM;
    int out  = ((b * NHD + h) * SS + s) * HDIM;
    float k0 = kraw[base + p], k1 = kraw[base + p + 16];
    float p0 = ph[base + p],   p1 = ph[base + p + 16];
    float c0, s0, c1, s1;
    sincosf(p0, &s0, &c0);
    sincosf(p1, &s1, &c1);
    krot[out + p]      = k0 * c0 - k1 * s0;
    krot[out + p + 16] = k1 * c1 + k0 * s1;
    vt[out + p]        = vraw[base + p];
    vt[out + p + 16]   = vraw[base + p + 16];
}

// ---------------- Q projection with fused 3D rope epilogue ----------------
// Q[b,n,j] = rope( sum_c fv[b,c,n] * W[c,j] + bias[j] ).
// 128x128x8 tile, 256 threads. Thread columns: c1 = h*32 + p + {0..3}, c2 = c1+16
// (both halves of every rope pair owned by the same thread).
// Inner loop: FFMA2 with i(token)-pairs packed, W duplicated in smem for LDS.64 (w,w).
__global__ void qproj_kernel(const float* __restrict__ A, const float* __restrict__ W,
                             const float* __restrict__ bias) {
    __shared__ float As[8 * 128];
    __shared__ float Wd[8 * 256];   // duplicated: Wd[k][2j] = Wd[k][2j+1] = W[k][j]
    float* Y = g_scr + OFF_Q;
    const float* invf = g_scr + OFF_INVF;
    int b = blockIdx.z;
    int n0 = blockIdx.y * 128, j0 = blockIdx.x * 128;
    int t = threadIdx.x;
    int tx = t & 15, ty = t >> 4;
    int hh = tx >> 2, p = (tx & 3) * 4;
    int c1 = hh * 32 + p, c2 = c1 + 16;
    const float* Ab = A + (size_t)b * CC * NTOK;
    ull acc[4][8] = {};
    int lk = t >> 5, lc = (t & 31) * 4;
    for (int k0 = 0; k0 < CC; k0 += 8) {
        *(float4*)&As[lk * 128 + lc] = *(const float4*)&Ab[(size_t)(k0 + lk) * NTOK + n0 + lc];
        {
            float4 w = *(const float4*)&W[(size_t)(k0 + lk) * CC + j0 + lc];
            *(float2*)&Wd[lk * 256 + 2 * lc + 0] = make_float2(w.x, w.x);
            *(float2*)&Wd[lk * 256 + 2 * lc + 2] = make_float2(w.y, w.y);
            *(float2*)&Wd[lk * 256 + 2 * lc + 4] = make_float2(w.z, w.z);
            *(float2*)&Wd[lk * 256 + 2 * lc + 6] = make_float2(w.w, w.w);
        }
        __syncthreads();
        #pragma unroll
        for (int kk = 0; kk < 8; kk++) {
            ulonglong2 a01 = *(ulonglong2*)&As[kk * 128 + ty * 4];
            ulonglong2 a23 = *(ulonglong2*)&As[kk * 128 + 64 + ty * 4];
            ull ap[4] = {a01.x, a01.y, a23.x, a23.y};
            ulonglong2 w01 = *(ulonglong2*)&Wd[kk * 256 + 2 * c1];
            ulonglong2 w23 = *(ulonglong2*)&Wd[kk * 256 + 2 * c1 + 4];
            ulonglong2 w45 = *(ulonglong2*)&Wd[kk * 256 + 2 * c2];
            ulonglong2 w67 = *(ulonglong2*)&Wd[kk * 256 + 2 * c2 + 4];
            ull wd[8] = {w01.x, w01.y, w23.x, w23.y, w45.x, w45.y, w67.x, w67.y};
            #pragma unroll
            for (int ip = 0; ip < 4; ip++)
                #pragma unroll
                for (int jj = 0; jj < 8; jj++)
                    FMA2(acc[ip][jj], ap[ip], wd[jj]);
        }
        __syncthreads();
    }
    // epilogue: bias + 3D rope, then store
    float b_lo[4], b_hi[4], if0[4], if1[4];
    #pragma unroll
    for (int jc = 0; jc < 4; jc++) {
        b_lo[jc] = bias[j0 + c1 + jc];
        b_hi[jc] = bias[j0 + c2 + jc];
        if0[jc] = invf[p + jc];
        if1[jc] = invf[p + jc + 16];
    }
    #pragma unroll
    for (int i = 0; i < 8; i++) {
        int mloc = (i < 4) ? (ty * 4 + i) : (64 + ty * 4 + (i - 4));
        int n = n0 + mloc;
        int wx = n & 31, hy = (n >> 5) & 31, dz = n >> 10;
        int ip = i >> 1, half = i & 1;
        float v1[4], v2[4];
        #pragma unroll
        for (int jc = 0; jc < 4; jc++) {
            float2 alo = u2f2(acc[ip][jc]);
            float2 ahi = u2f2(acc[ip][4 + jc]);
            float q0 = (half ? alo.y : alo.x) + b_lo[jc];
            float q1 = (half ? ahi.y : ahi.x) + b_hi[jc];
            int dd = p + jc;
            float pos0 = (dd < 10) ? (float)dz : (float)hy;
            float pos1 = (dd + 16 < 20) ? (float)hy : (float)wx;
            float f0 = pos0 * if0[jc], f1 = pos1 * if1[jc];
            float cs0, sn0, cs1, sn1;
            sincosf(f0, &sn0, &cs0);
            sincosf(f1, &sn1, &cs1);
            v1[jc] = q0 * cs0 - q1 * sn0;
            v2[jc] = q1 * cs1 + q0 * sn1;
        }
        float* yp = Y + ((size_t)b * NTOK + n) * CC;
        *(float4*)&yp[j0 + c1] = *(float4*)v1;
        *(float4*)&yp[j0 + c2] = *(float4*)v2;
    }
}

// ---------------- attention: per (b,h), 64 tokens/block, FFMA2 throughout ----------------
// smem: Qst[32][68] (d-major, scale folded), Ksd[32][512] (d-major, s duplicated),
//       Vsd[256][64] (s-major, d duplicated), Pt[256][68] ([s][m]), Pm/Psum[256]
#define ATT_SMEM_FLOATS (32*68 + 32*512 + 256*64 + 256*68 + 256 + 256)
__global__ void attn_kernel() {
    extern __shared__ float sm[];
    float* Qst  = sm;                  // [32][68]
    float* Ksd  = Qst + 32 * 68;       // [32][512]
    float* Vsd  = Ksd + 32 * 512;      // [256][64]
    float* Pt   = Vsd + 256 * 64;      // [256][68]
    float* Pm   = Pt + 256 * 68;       // [4][64]
    float* Psum = Pm + 256;            // [4][64]
    const float* q    = g_scr + OFF_Q;
    const float* krot = g_scr + OFF_KROT;
    const float* vt   = g_scr + OFF_VT;
    float* ao = g_scr + OFF_AO;
    int b = blockIdx.z, h = blockIdx.y;
    int n0 = blockIdx.x * 64;
    int t = threadIdx.x;
    const float scale = 0.17677669529663687f;  // 32^-0.5

    // pass 1: coalesced loads. K staged into Pt[s*33+d] (temp); V duplicated directly.
    size_t kvbase = (size_t)(b * NHD + h) * SS * HDIM;
    for (int idx = t; idx < 64 * 32; idx += 256) {
        int tok = idx >> 5, d = idx & 31;
        Qst[d * 68 + tok] = q[((size_t)b * NTOK + n0 + tok) * CC + h * HDIM + d] * scale;
    }
    for (int idx = t; idx < 256 * 32; idx += 256) {
        int s = idx >> 5, d = idx & 31;
        Pt[s * 33 + d] = krot[kvbase + idx];
        float vv = vt[kvbase + idx];
        *(float2*)&Vsd[s * 64 + 2 * d] = make_float2(vv, vv);
    }
    __syncthreads();
    // pass 2: build Ksd[d][2s] (duplicated, s-major) from staged K, conflict-free
    #pragma unroll 4
    for (int i = 0; i < 32; i++) {
        float kv = Pt[t * 33 + i];
        *(float2*)&Ksd[i * 512 + 2 * t] = make_float2(kv, kv);
    }
    __syncthreads();

    // Phase A: Pt[s][m] = (Q*scale) . K   via FFMA2 (token pairs x dup K)
    int tx4 = (t & 15) * 4, ty = t >> 4;
    #pragma unroll 1
    for (int sc = 0; sc < 4; sc++) {
        ull acc[2][4] = {};
        #pragma unroll 8
        for (int d = 0; d < 32; d++) {
            ulonglong2 qp = *(ulonglong2*)&Qst[d * 68 + ty * 4];
            ulonglong2 k01 = *(ulonglong2*)&Ksd[d * 512 + 2 * (sc * 64 + tx4)];
            ulonglong2 k23 = *(ulonglong2*)&Ksd[d * 512 + 2 * (sc * 64 + tx4) + 4];
            ull kd[4] = {k01.x, k01.y, k23.x, k23.y};
            #pragma unroll
            for (int jc = 0; jc < 4; jc++) {
                FMA2(acc[0][jc], qp.x, kd[jc]);
                FMA2(acc[1][jc], qp.y, kd[jc]);
            }
        }
        #pragma unroll
        for (int pp = 0; pp < 2; pp++)
            #pragma unroll
            for (int jc = 0; jc < 4; jc++)
                *(float2*)&Pt[(sc * 64 + tx4 + jc) * 68 + ty * 4 + 2 * pp] = u2f2(acc[pp][jc]);
    }
    __syncthreads();

    // Softmax over s: thread owns (row m = t&63, quarter qd = t>>6); Z folded into phase B
    {
        int m = t & 63, qd = t >> 6;
        float mx = -CUDART_INF_F;
        #pragma unroll 4
        for (int k = 0; k < 64; k++) mx = fmaxf(mx, Pt[(qd * 64 + k) * 68 + m]);
        Pm[qd * 64 + m] = mx;
        __syncthreads();
        float rmx = fmaxf(fmaxf(Pm[m], Pm[64 + m]), fmaxf(Pm[128 + m], Pm[192 + m]));
        float lsum = 0.f;
        #pragma unroll 4
        for (int k = 0; k < 64; k++) {
            float e = __expf(Pt[(qd * 64 + k) * 68 + m] - rmx);
            Pt[(qd * 64 + k) * 68 + m] = e;
            lsum += e;
        }
        Psum[qd * 64 + m] = lsum;
    }
    __syncthreads();

    // Phase B: O[64 x 32] = P @ V via FFMA2 (token pairs x dup V)
    {
        int d = t & 31, mg = t >> 5;
        ull o[4] = {};
        #pragma unroll 2
        for (int s = 0; s < 256; s++) {
            ulonglong2 p01 = *(ulonglong2*)&Pt[s * 68 + mg * 8];
            ulonglong2 p23 = *(ulonglong2*)&Pt[s * 68 + mg * 8 + 4];
            ull vv = *(ull*)&Vsd[s * 64 + 2 * d];
            FMA2(o[0], p01.x, vv);
            FMA2(o[1], p01.y, vv);
            FMA2(o[2], p23.x, vv);
            FMA2(o[3], p23.y, vv);
        }
        #pragma unroll
        for (int qq = 0; qq < 4; qq++) {
            float2 f = u2f2(o[qq]);
            int m = mg * 8 + 2 * qq;
            float Z0 = Psum[m] + Psum[64 + m] + Psum[128 + m] + Psum[192 + m];
            float Z1 = Psum[m + 1] + Psum[64 + m + 1] + Psum[128 + m + 1] + Psum[192 + m + 1];
            ao[((size_t)b * NTOK + n0 + m) * CC + h * HDIM + d]     = f.x / Z0;
            ao[((size_t)b * NTOK + n0 + m + 1) * CC + h * HDIM + d] = f.y / Z1;
        }
    }
}

// ---------------- O projection + transpose, FFMA2 ----------------
__global__ void oproj_kernel(const float* __restrict__ W, const float* __restrict__ bias,
                             float* __restrict__ Out) {
    __shared__ float As[8 * 132];   // transposed on load
    __shared__ float Wd[8 * 256];   // duplicated
    const float* Ain = g_scr + OFF_AO;
    int b = blockIdx.z;
    int n0 = blockIdx.y * 128, j0 = blockIdx.x * 128;
    int t = threadIdx.x;
    int tx = t & 15, ty = t >> 4;
    int c1 = tx * 4, c2 = 64 + tx * 4;
    ull acc[4][8] = {};
    int lm = t >> 1, lkq = (t & 1) * 4;
    int lk = t >> 5, lc = (t & 31) * 4;
    for (int k0 = 0; k0 < CC; k0 += 8) {
        float4 av = *(const float4*)&Ain[((size_t)b * NTOK + n0 + lm) * CC + k0 + lkq];
        As[(lkq + 0) * 132 + lm] = av.x;
        As[(lkq + 1) * 132 + lm] = av.y;
        As[(lkq + 2) * 132 + lm] = av.z;
        As[(lkq + 3) * 132 + lm] = av.w;
        {
            float4 w = *(const float4*)&W[(size_t)(k0 + lk) * CC + j0 + lc];
            *(float2*)&Wd[lk * 256 + 2 * lc + 0] = make_float2(w.x, w.x);
            *(float2*)&Wd[lk * 256 + 2 * lc + 2] = make_float2(w.y, w.y);
            *(float2*)&Wd[lk * 256 + 2 * lc + 4] = make_float2(w.z, w.z);
            *(float2*)&Wd[lk * 256 + 2 * lc + 6] = make_float2(w.w, w.w);
        }
        __syncthreads();
        #pragma unroll
        for (int kk = 0; kk < 8; kk++) {
            ulonglong2 a01 = *(ulonglong2*)&As[kk * 132 + ty * 4];
            ulonglong2 a23 = *(ulonglong2*)&As[kk * 132 + 64 + ty * 4];
            ull ap[4] = {a01.x, a01.y, a23.x, a23.y};
            ulonglong2 w01 = *(ulonglong2*)&Wd[kk * 256 + 2 * c1];
            ulonglong2 w23 = *(ulonglong2*)&Wd[kk * 256 + 2 * c1 + 4];
            ulonglong2 w45 = *(ulonglong2*)&Wd[kk * 256 + 2 * c2];
            ulonglong2 w67 = *(ulonglong2*)&Wd[kk * 256 + 2 * c2 + 4];
            ull wd[8] = {w01.x, w01.y, w23.x, w23.y, w45.x, w45.y, w67.x, w67.y};
            #pragma unroll
            for (int ip = 0; ip < 4; ip++)
                #pragma unroll
                for (int jj = 0; jj < 8; jj++)
                    FMA2(acc[ip][jj], ap[ip], wd[jj]);
        }
        __syncthreads();
    }
    #pragma unroll
    for (int jj = 0; jj < 8; jj++) {
        int col = j0 + ((jj < 4) ? (c1 + jj) : (c2 + jj - 4));
        float bv = bias[col];
        float2 f0 = u2f2(acc[0][jj]);
        float2 f1 = u2f2(acc[1][jj]);
        float2 f2 = u2f2(acc[2][jj]);
        float2 f3 = u2f2(acc[3][jj]);
        float4 v1 = make_float4(f0.x + bv, f0.y + bv, f1.x + bv, f1.y + bv);
        float4 v2 = make_float4(f2.x + bv, f2.y + bv, f3.x + bv, f3.y + bv);
        float* outp = Out + (size_t)b * CC * NTOK + (size_t)col * NTOK;
        *(float4*)&outp[n0 + ty * 4]      = v1;
        *(float4*)&outp[n0 + 64 + ty * 4] = v2;
    }
}

// ---------------- launch ----------------
extern "C" void kernel_launch(void* const* d_in, const int* in_sizes, int n_in,
                              void* d_out, int out_size) {
    const float* fv   = (const float*)d_in[0];
    const float* text = (const float*)d_in[1];
    const float* q_w  = (const float*)d_in[2];
    const float* q_b  = (const float*)d_in[3];
    const float* k_w  = (const float*)d_in[4];
    const float* k_b  = (const float*)d_in[5];
    const float* v_w  = (const float*)d_in[6];
    const float* v_b  = (const float*)d_in[7];
    const float* o_w  = (const float*)d_in[8];
    const float* o_b  = (const float*)d_in[9];
    const float* m1_w = (const float*)d_in[10];
    const float* m1_b = (const float*)d_in[11];
    const float* m2_w = (const float*)d_in[12];
    const float* m2_b = (const float*)d_in[13];
    float* out = (float*)d_out;

    init_invf_kernel<<<1, 32>>>();

    // Text side
    text3_kernel<<<dim3(4, 16, 3), 256>>>(text, k_w, k_b, v_w, v_b, m1_w, m1_b);
    phase_gemm_kernel<<<dim3(4, 16), 256>>>(m2_w, m2_b);
    text_rope_kernel<<<256, 256>>>();

    // Visual side: Q projection with fused rope
    qproj_kernel<<<dim3(2, 256, 2), 256>>>(fv, q_w, q_b);

    cudaFuncSetAttribute(attn_kernel, cudaFuncAttributeMaxDynamicSharedMemorySize,
                         ATT_SMEM_FLOATS * (int)sizeof(float));
    attn_kernel<<<dim3(512, 8, 2), 256, ATT_SMEM_FLOATS * sizeof(float)>>>();

    oproj_kernel<<<dim3(2, 256, 2), 256>>>(o_w, o_b, out);
}

// round 4
// speedup vs baseline: 4.2433x; 4.2433x over previous
#include <cuda_runtime.h>
#include <cuda_bf16.h>
#include <math.h>
#include <math_constants.h>

#define BB    2
#define CC    256
#define NTOK  32768
#define SS    256
#define TDIM  512
#define NHD   8
#define HDIM  32

typedef unsigned u32;
typedef unsigned long long ull;

// ---------------- scratch ----------------
#define OFF_H1    0
#define OFF_KRAW  (OFF_H1   + 131072)
#define OFF_VRAW  (OFF_KRAW + 131072)
#define OFF_PHASE (OFF_VRAW + 131072)
#define OFF_KROT  (OFF_PHASE+ 131072)      // fp32 [b,h][d=32][s=256]
#define OFF_VT    (OFF_KROT + 131072)      // fp32 [b,h][s=256][d=32]
#define OFF_Q     (OFF_VT   + 131072)      // fp32 [b][n][256]
#define OFF_AO    (OFF_Q    + 16777216)    // fp32 [b][n][256]
#define OFF_INVF  (OFF_AO   + 16777216)
#define SCR_TOTAL (OFF_INVF + 32)
__device__ float g_scr[SCR_TOTAL];

// ---------------- helpers ----------------
__device__ __forceinline__ void ldsm4(u32& r0, u32& r1, u32& r2, u32& r3, u32 addr) {
    asm volatile("ldmatrix.sync.aligned.m8n8.x4.shared.b16 {%0,%1,%2,%3}, [%4];"
                 : "=r"(r0), "=r"(r1), "=r"(r2), "=r"(r3) : "r"(addr));
}
__device__ __forceinline__ void ldsm4t(u32& r0, u32& r1, u32& r2, u32& r3, u32 addr) {
    asm volatile("ldmatrix.sync.aligned.m8n8.x4.trans.shared.b16 {%0,%1,%2,%3}, [%4];"
                 : "=r"(r0), "=r"(r1), "=r"(r2), "=r"(r3) : "r"(addr));
}
__device__ __forceinline__ void mma_bf16(float* d, const u32* a, u32 b0, u32 b1) {
    asm volatile("mma.sync.aligned.m16n8k16.row.col.f32.bf16.bf16.f32 "
                 "{%0,%1,%2,%3}, {%4,%5,%6,%7}, {%8,%9}, {%0,%1,%2,%3};"
                 : "+f"(d[0]), "+f"(d[1]), "+f"(d[2]), "+f"(d[3])
                 : "r"(a[0]), "r"(a[1]), "r"(a[2]), "r"(a[3]), "r"(b0), "r"(b1));
}
// split (x,y) into hi bf16x2 + residual-lo bf16x2  (x -> low half)
__device__ __forceinline__ void bf16split2(float x, float y, u32& hi, u32& lo) {
    asm("cvt.rn.bf16x2.f32 %0, %1, %2;" : "=r"(hi) : "f"(y), "f"(x));
    float hx = __uint_as_float(hi << 16);
    float hy = __uint_as_float(hi & 0xffff0000u);
    asm("cvt.rn.bf16x2.f32 %0, %1, %2;" : "=r"(lo) : "f"(y - hy), "f"(x - hx));
}
// A fragment (m16k16) from [m][k] row-major smem, non-trans ldmatrix
__device__ __forceinline__ void ldA_mk(u32* f, u32 base, int stride, int m0, int k0, int lane) {
    int m = m0 + (lane & 15);
    int k = k0 + ((lane >> 4) << 3);
    ldsm4(f[0], f[1], f[2], f[3], base + (u32)((m * stride + k) * 2));
}
// A fragment (m16k16) from [k][m] row-major smem, trans ldmatrix
__device__ __forceinline__ void ldA_km(u32* f, u32 base, int stride, int k0, int m0, int lane) {
    int k = k0 + (lane & 7) + ((lane >> 4) << 3);
    int m = m0 + (((lane >> 3) & 1) << 3);
    ldsm4t(f[0], f[1], f[2], f[3], base + (u32)((k * stride + m) * 2));
}
// B fragments (k16n8 x2: tiles n0, n0+8) from [k][n] row-major smem, trans ldmatrix
__device__ __forceinline__ void ldB_kn(u32* f, u32 base, int stride, int k0, int n0, int lane) {
    int k = k0 + (lane & 7) + (((lane >> 3) & 1) << 3);
    int n = n0 + ((lane >> 4) << 3);
    ldsm4t(f[0], f[1], f[2], f[3], base + (u32)((k * stride + n) * 2));
}
// stage 32(k) x 128(cols) fp32 tile -> split bf16 [k][136] hi/lo
__device__ __forceinline__ void stage_km(const float* g, int gstride, char* smH, char* smL, int t) {
    #pragma unroll
    for (int i = 0; i < 4; i++) {
        int lin = i * 256 + t;
        int kr = lin >> 5, mq = (lin & 31) * 4;
        float4 v = *(const float4*)(g + (size_t)kr * gstride + mq);
        u32 h0, l0, h1, l1;
        bf16split2(v.x, v.y, h0, l0);
        bf16split2(v.z, v.w, h1, l1);
        *(ull*)(smH + (size_t)(kr * 68 + (mq >> 1)) * 4) = (ull)h0 | ((ull)h1 << 32);
        *(ull*)(smL + (size_t)(kr * 68 + (mq >> 1)) * 4) = (ull)l0 | ((ull)l1 << 32);
    }
}
// stage 128(m) x 32(k) fp32 tile -> split bf16 [m][40] hi/lo
__device__ __forceinline__ void stage_mk(const float* g, int gstride, char* smH, char* smL, int t) {
    #pragma unroll
    for (int i = 0; i < 4; i++) {
        int lin = i * 256 + t;
        int mr = lin >> 3, kq = (lin & 7) * 4;
        float4 v = *(const float4*)(g + (size_t)mr * gstride + kq);
        u32 h0, l0, h1, l1;
        bf16split2(v.x, v.y, h0, l0);
        bf16split2(v.z, v.w, h1, l1);
        *(ull*)(smH + (size_t)(mr * 20 + (kq >> 1)) * 4) = (ull)h0 | ((ull)h1 << 32);
        *(ull*)(smL + (size_t)(mr * 20 + (kq >> 1)) * 4) = (ull)l0 | ((ull)l1 << 32);
    }
}

// ---------------- rope inverse-frequency table ----------------
__global__ void init_invf_kernel() {
    int d = threadIdx.x;
    if (d < 32) {
        float e;
        if (d < 10)       e = (float)(2 * (d % 5)) / 10.f;
        else if (d < 20)  e = (float)(2 * ((d - 10) % 5)) / 10.f;
        else              e = (float)(2 * ((d - 20) % 6)) / 12.f;
        g_scr[OFF_INVF + d] = powf(10000.f, -e);
    }
}

// ---------------- fp32 text GEMMs (proven) ----------------
__device__ __forceinline__ void gemm32x64_body(const float* __restrict__ A,
                                               const float* __restrict__ W,
                                               const float* __restrict__ bias,
                                               float* __restrict__ Y,
                                               int K, int N, int act,
                                               int m0, int j0,
                                               float* As, float* Ws) {
    int t = threadIdx.x;
    int tx = t & 15, ty = t >> 4;
    float acc[2][4] = {};
    for (int k0 = 0; k0 < K; k0 += 16) {
        if (t < 128) {
            int m = t >> 2, kq = (t & 3) * 4;
            float4 av = *(const float4*)&A[(size_t)(m0 + m) * K + k0 + kq];
            As[(kq + 0) * 33 + m] = av.x;
            As[(kq + 1) * 33 + m] = av.y;
            As[(kq + 2) * 33 + m] = av.z;
            As[(kq + 3) * 33 + m] = av.w;
        }
        {
            int kk = t >> 4, j4 = (t & 15) * 4;
            *(float4*)&Ws[kk * 64 + j4] = *(const float4*)&W[(size_t)(k0 + kk) * N + j0 + j4];
        }
        __syncthreads();
        #pragma unroll
        for (int kk = 0; kk < 16; kk++) {
            float a0 = As[kk * 33 + ty * 2], a1 = As[kk * 33 + ty * 2 + 1];
            #pragma unroll
            for (int j = 0; j < 4; j++) {
                float w = Ws[kk * 64 + tx + 16 * j];
                acc[0][j] += a0 * w;
                acc[1][j] += a1 * w;
            }
        }
        __syncthreads();
    }
    #pragma unroll
    for (int j = 0; j < 4; j++) {
        int jj = j0 + tx + 16 * j;
        float bv = bias[jj];
        #pragma unroll
        for (int i = 0; i < 2; i++) {
            float v = acc[i][j] + bv;
            if (act) v = 0.5f * v * (1.f + erff(v * 0.70710678118654752f));
            Y[(size_t)(m0 + ty * 2 + i) * N + jj] = v;
        }
    }
}

__global__ void text3_kernel(const float* __restrict__ text,
                             const float* __restrict__ kw, const float* __restrict__ kb,
                             const float* __restrict__ vw, const float* __restrict__ vb,
                             const float* __restrict__ m1w, const float* __restrict__ m1b) {
    __shared__ float As[16 * 33];
    __shared__ float Ws[16 * 64];
    const float *W, *bias;
    float* Y;
    int act = 0;
    if (blockIdx.z == 0)      { W = kw;  bias = kb;  Y = g_scr + OFF_KRAW; }
    else if (blockIdx.z == 1) { W = vw;  bias = vb;  Y = g_scr + OFF_VRAW; }
    else                      { W = m1w; bias = m1b; Y = g_scr + OFF_H1; act = 1; }
    gemm32x64_body(text, W, bias, Y, 512, 256, act, blockIdx.y * 32, blockIdx.x * 64, As, Ws);
}

__global__ void phase_gemm_kernel(const float* __restrict__ m2w, const float* __restrict__ m2b) {
    __shared__ float As[16 * 33];
    __shared__ float Ws[16 * 64];
    gemm32x64_body(g_scr + OFF_H1, m2w, m2b, g_scr + OFF_PHASE, 256, 256, 0,
                   blockIdx.y * 32, blockIdx.x * 64, As, Ws);
}

// ---------------- text rope: krot -> [b,h][d][s], vt -> [b,h][s][d] ----------------
__global__ void text_rope_kernel() {
    int idx = blockIdx.x * blockDim.x + threadIdx.x;  // < 65536
    int p = idx & 15;
    int h = (idx >> 4) & 7;
    int s = (idx >> 7) & 255;
    int b = idx >> 15;
    const float* kraw = g_scr + OFF_KRAW;
    const float* vraw = g_scr + OFF_VRAW;
    const float* ph   = g_scr + OFF_PHASE;
    float* krot = g_scr + OFF_KROT;
    float* vt   = g_scr + OFF_VT;
    int base = (b * SS + s) * CC + h * HDIM;
    int bh = b * NHD + h;
    float k0 = kraw[base + p], k1 = kraw[base + p + 16];
    float p0 = ph[base + p],   p1 = ph[base + p + 16];
    float c0, s0, c1, s1;
    sincosf(p0, &s0, &c0);
    sincosf(p1, &s1, &c1);
    krot[(bh * HDIM + p) * SS + s]        = k0 * c0 - k1 * s0;
    krot[(bh * HDIM + p + 16) * SS + s]   = k1 * c1 + k0 * s1;
    vt[(bh * SS + s) * HDIM + p]          = vraw[base + p];
    vt[(bh * SS + s) * HDIM + p + 16]     = vraw[base + p + 16];
}

// ================= Q projection (tensor) with fused 3D rope =================
// BM=128(n) BN=128(j) BK=32, 8 warps (wm 0..1 x 64 rows, wn 0..3 x 32 cols = 1 head)
#define QP_AH 0
#define QP_AL 8704
#define QP_BH 17408
#define QP_BL 26112
__global__ __launch_bounds__(256, 1) void qproj_mma_kernel(
        const float* __restrict__ A, const float* __restrict__ W,
        const float* __restrict__ bias) {
    __shared__ char sm[34816];
    float* Y = g_scr + OFF_Q;
    const float* invf = g_scr + OFF_INVF;
    int b = blockIdx.z;
    int n0 = blockIdx.y * 128, j0 = blockIdx.x * 128;
    int t = threadIdx.x;
    int w = t >> 5, lane = t & 31;
    int wm = w & 1, wn = w >> 1;
    int mu = lane & 3, r = lane >> 2;
    const float* Ab = A + (size_t)b * CC * NTOK;
    u32 aH = (u32)__cvta_generic_to_shared(sm + QP_AH);
    u32 aL = (u32)__cvta_generic_to_shared(sm + QP_AL);
    u32 bH = (u32)__cvta_generic_to_shared(sm + QP_BH);
    u32 bL = (u32)__cvta_generic_to_shared(sm + QP_BL);
    float acc[4][4][4] = {};
    for (int k0 = 0; k0 < CC; k0 += 32) {
        stage_km(Ab + (size_t)k0 * NTOK + n0, NTOK, sm + QP_AH, sm + QP_AL, t);
        stage_km(W + (size_t)k0 * CC + j0, CC, sm + QP_BH, sm + QP_BL, t);
        __syncthreads();
        #pragma unroll
        for (int kt = 0; kt < 2; kt++) {
            u32 ah[4][4], al[4][4];
            #pragma unroll
            for (int mt = 0; mt < 4; mt++) {
                ldA_km(ah[mt], aH, 136, kt * 16, wm * 64 + mt * 16, lane);
                ldA_km(al[mt], aL, 136, kt * 16, wm * 64 + mt * 16, lane);
            }
            #pragma unroll
            for (int ng = 0; ng < 2; ng++) {
                u32 bh[4], bl[4];
                ldB_kn(bh, bH, 136, kt * 16, wn * 32 + ng * 16, lane);
                ldB_kn(bl, bL, 136, kt * 16, wn * 32 + ng * 16, lane);
                #pragma unroll
                for (int mt = 0; mt < 4; mt++) {
                    mma_bf16(acc[mt][ng * 2],     ah[mt], bh[0], bh[1]);
                    mma_bf16(acc[mt][ng * 2],     ah[mt], bl[0], bl[1]);
                    mma_bf16(acc[mt][ng * 2],     al[mt], bh[0], bh[1]);
                    mma_bf16(acc[mt][ng * 2 + 1], ah[mt], bh[2], bh[3]);
                    mma_bf16(acc[mt][ng * 2 + 1], ah[mt], bl[2], bl[3]);
                    mma_bf16(acc[mt][ng * 2 + 1], al[mt], bh[2], bh[3]);
                }
            }
        }
        __syncthreads();
    }
    // epilogue: bias + rope, store fp32 Q
    float blo[2][2], bhi[2][2], fl0[2][2], fl1[2][2];
    int zsel[2][2], xsel[2][2];
    #pragma unroll
    for (int tn = 0; tn < 2; tn++)
        #pragma unroll
        for (int cc = 0; cc < 2; cc++) {
            int d = tn * 8 + 2 * mu + cc;
            blo[tn][cc] = bias[j0 + wn * 32 + d];
            bhi[tn][cc] = bias[j0 + wn * 32 + d + 16];
            fl0[tn][cc] = invf[d];
            fl1[tn][cc] = invf[d + 16];
            zsel[tn][cc] = (d < 10);
            xsel[tn][cc] = (d + 16 >= 20);
        }
    #pragma unroll
    for (int mt = 0; mt < 4; mt++)
        #pragma unroll
        for (int half = 0; half < 2; half++) {
            int n = n0 + wm * 64 + mt * 16 + r + half * 8;
            float wx = (float)(n & 31), hy = (float)((n >> 5) & 31), dz = (float)(n >> 10);
            float* yp = Y + ((size_t)b * NTOK + n) * CC + j0 + wn * 32;
            #pragma unroll
            for (int tn = 0; tn < 2; tn++) {
                float v0[2], v1[2];
                #pragma unroll
                for (int cc = 0; cc < 2; cc++) {
                    float q0 = acc[mt][tn][half * 2 + cc] + blo[tn][cc];
                    float q1 = acc[mt][tn + 2][half * 2 + cc] + bhi[tn][cc];
                    float f0 = (zsel[tn][cc] ? dz : hy) * fl0[tn][cc];
                    float f1 = (xsel[tn][cc] ? wx : hy) * fl1[tn][cc];
                    float s0, c0, s1, c1;
                    sincosf(f0, &s0, &c0);
                    sincosf(f1, &s1, &c1);
                    v0[cc] = q0 * c0 - q1 * s0;
                    v1[cc] = q1 * c1 + q0 * s1;
                }
                *(float2*)&yp[tn * 8 + 2 * mu]      = make_float2(v0[0], v0[1]);
                *(float2*)&yp[tn * 8 + 2 * mu + 16] = make_float2(v1[0], v1[1]);
            }
        }
}

// ================= attention (tensor): 128 tokens/block =================
#define AT_QH 0
#define AT_QL 10240
#define AT_KH 20480
#define AT_KL 37376
#define AT_VH 54272
#define AT_VL 74752
#define AT_SMEM 95232
__global__ __launch_bounds__(256, 1) void attn_mma_kernel() {
    extern __shared__ char sm[];
    const float* q    = g_scr + OFF_Q;
    const float* krot = g_scr + OFF_KROT;
    const float* vt   = g_scr + OFF_VT;
    float* ao = g_scr + OFF_AO;
    int b = blockIdx.z, h = blockIdx.y;
    int n0 = blockIdx.x * 128;
    int t = threadIdx.x;
    int w = t >> 5, lane = t & 31;
    int mu = lane & 3, r = lane >> 2;
    const float scale = 0.17677669529663687f;
    u32* QHu = (u32*)(sm + AT_QH);
    u32* QLu = (u32*)(sm + AT_QL);
    u32* KHu = (u32*)(sm + AT_KH);
    u32* KLu = (u32*)(sm + AT_KL);
    u32* VHu = (u32*)(sm + AT_VH);
    u32* VLu = (u32*)(sm + AT_VL);
    // stage Q (x scale)
    #pragma unroll
    for (int i = 0; i < 8; i++) {
        int lin = i * 256 + t;
        int row = lin >> 4, dp = lin & 15;
        float2 v = *(const float2*)&q[((size_t)b * NTOK + n0 + row) * CC + h * HDIM + dp * 2];
        u32 hh, ll;
        bf16split2(v.x * scale, v.y * scale, hh, ll);
        QHu[row * 20 + dp] = hh;
        QLu[row * 20 + dp] = ll;
    }
    // stage K [d][s]
    size_t kb = (size_t)(b * NHD + h) * HDIM * SS;
    #pragma unroll
    for (int i = 0; i < 16; i++) {
        int lin = i * 256 + t;
        int d = lin >> 7, sp = lin & 127;
        float2 v = *(const float2*)&krot[kb + (size_t)d * SS + sp * 2];
        u32 hh, ll;
        bf16split2(v.x, v.y, hh, ll);
        KHu[d * 132 + sp] = hh;
        KLu[d * 132 + sp] = ll;
    }
    // stage V [s][d]
    size_t vb = (size_t)(b * NHD + h) * SS * HDIM;
    #pragma unroll
    for (int i = 0; i < 16; i++) {
        int lin = i * 256 + t;
        int s = lin >> 4, dp = lin & 15;
        float2 v = *(const float2*)&vt[vb + (size_t)s * HDIM + dp * 2];
        u32 hh, ll;
        bf16split2(v.x, v.y, hh, ll);
        VHu[s * 20 + dp] = hh;
        VLu[s * 20 + dp] = ll;
    }
    __syncthreads();
    u32 aQH = (u32)__cvta_generic_to_shared(sm + AT_QH);
    u32 aQL = (u32)__cvta_generic_to_shared(sm + AT_QL);
    u32 aKH = (u32)__cvta_generic_to_shared(sm + AT_KH);
    u32 aKL = (u32)__cvta_generic_to_shared(sm + AT_KL);
    u32 aVH = (u32)__cvta_generic_to_shared(sm + AT_VH);
    u32 aVL = (u32)__cvta_generic_to_shared(sm + AT_VL);
    // QK^T: acc[32 s-tiles][4]
    float acc[32][4];
    #pragma unroll
    for (int i = 0; i < 32; i++)
        #pragma unroll
        for (int j = 0; j < 4; j++) acc[i][j] = 0.f;
    #pragma unroll
    for (int kt = 0; kt < 2; kt++) {
        u32 qh[4], ql[4];
        ldA_mk(qh, aQH, 40, w * 16, kt * 16, lane);
        ldA_mk(ql, aQL, 40, w * 16, kt * 16, lane);
        #pragma unroll
        for (int sg = 0; sg < 16; sg++) {
            u32 kh[4], kl[4];
            ldB_kn(kh, aKH, 264, kt * 16, sg * 16, lane);
            ldB_kn(kl, aKL, 264, kt * 16, sg * 16, lane);
            mma_bf16(acc[sg * 2],     qh, kh[0], kh[1]);
            mma_bf16(acc[sg * 2],     qh, kl[0], kl[1]);
            mma_bf16(acc[sg * 2],     ql, kh[0], kh[1]);
            mma_bf16(acc[sg * 2 + 1], qh, kh[2], kh[3]);
            mma_bf16(acc[sg * 2 + 1], qh, kl[2], kl[3]);
            mma_bf16(acc[sg * 2 + 1], ql, kh[2], kh[3]);
        }
    }
    // softmax in registers (rows r and r+8); quad reduction over lanes mu
    float mx0 = -CUDART_INF_F, mx1 = -CUDART_INF_F;
    #pragma unroll
    for (int i = 0; i < 32; i++) {
        mx0 = fmaxf(mx0, fmaxf(acc[i][0], acc[i][1]));
        mx1 = fmaxf(mx1, fmaxf(acc[i][2], acc[i][3]));
    }
    mx0 = fmaxf(mx0, __shfl_xor_sync(0xffffffffu, mx0, 1));
    mx0 = fmaxf(mx0, __shfl_xor_sync(0xffffffffu, mx0, 2));
    mx1 = fmaxf(mx1, __shfl_xor_sync(0xffffffffu, mx1, 1));
    mx1 = fmaxf(mx1, __shfl_xor_sync(0xffffffffu, mx1, 2));
    float sum0 = 0.f, sum1 = 0.f;
    #pragma unroll
    for (int i = 0; i < 32; i++) {
        acc[i][0] = __expf(acc[i][0] - mx0);
        acc[i][1] = __expf(acc[i][1] - mx0);
        acc[i][2] = __expf(acc[i][2] - mx1);
        acc[i][3] = __expf(acc[i][3] - mx1);
        sum0 += acc[i][0] + acc[i][1];
        sum1 += acc[i][2] + acc[i][3];
    }
    sum0 += __shfl_xor_sync(0xffffffffu, sum0, 1);
    sum0 += __shfl_xor_sync(0xffffffffu, sum0, 2);
    sum1 += __shfl_xor_sync(0xffffffffu, sum1, 1);
    sum1 += __shfl_xor_sync(0xffffffffu, sum1, 2);
    float zi0 = 1.f / sum0, zi1 = 1.f / sum1;
    // PV: P fragments straight from score registers
    float oacc[4][4] = {};
    #pragma unroll
    for (int kt = 0; kt < 16; kt++) {
        u32 ah[4], al[4];
        bf16split2(acc[2 * kt][0],     acc[2 * kt][1],     ah[0], al[0]);
        bf16split2(acc[2 * kt][2],     acc[2 * kt][3],     ah[1], al[1]);
        bf16split2(acc[2 * kt + 1][0], acc[2 * kt + 1][1], ah[2], al[2]);
        bf16split2(acc[2 * kt + 1][2], acc[2 * kt + 1][3], ah[3], al[3]);
        #pragma unroll
        for (int dg = 0; dg < 2; dg++) {
            u32 vh[4], vl[4];
            ldB_kn(vh, aVH, 40, kt * 16, dg * 16, lane);
            ldB_kn(vl, aVL, 40, kt * 16, dg * 16, lane);
            mma_bf16(oacc[dg * 2],     ah, vh[0], vh[1]);
            mma_bf16(oacc[dg * 2],     ah, vl[0], vl[1]);
            mma_bf16(oacc[dg * 2],     al, vh[0], vh[1]);
            mma_bf16(oacc[dg * 2 + 1], ah, vh[2], vh[3]);
            mma_bf16(oacc[dg * 2 + 1], ah, vl[2], vl[3]);
            mma_bf16(oacc[dg * 2 + 1], al, vh[2], vh[3]);
        }
    }
    // output
    #pragma unroll
    for (int dt = 0; dt < 4; dt++) {
        int dcol = dt * 8 + 2 * mu;
        size_t r0 = ((size_t)b * NTOK + n0 + w * 16 + r) * CC + h * HDIM + dcol;
        size_t r1 = ((size_t)b * NTOK + n0 + w * 16 + r + 8) * CC + h * HDIM + dcol;
        *(float2*)&ao[r0] = make_float2(oacc[dt][0] * zi0, oacc[dt][1] * zi0);
        *(float2*)&ao[r1] = make_float2(oacc[dt][2] * zi1, oacc[dt][3] * zi1);
    }
}

// ================= O projection (tensor) + transpose =================
#define OP_AH 0
#define OP_AL 10240
#define OP_BH 20480
#define OP_BL 29184
#define OP_SMEM 67584
__global__ __launch_bounds__(256, 1) void oproj_mma_kernel(
        const float* __restrict__ W, const float* __restrict__ bias,
        float* __restrict__ Out) {
    extern __shared__ char sm[];
    const float* Ain = g_scr + OFF_AO;
    int b = blockIdx.z;
    int n0 = blockIdx.y * 128, j0 = blockIdx.x * 128;
    int t = threadIdx.x;
    int w = t >> 5, lane = t & 31;
    int wm = w & 1, wn = w >> 1;
    int mu = lane & 3, r = lane >> 2;
    u32 aH = (u32)__cvta_generic_to_shared(sm + OP_AH);
    u32 aL = (u32)__cvta_generic_to_shared(sm + OP_AL);
    u32 bH = (u32)__cvta_generic_to_shared(sm + OP_BH);
    u32 bL = (u32)__cvta_generic_to_shared(sm + OP_BL);
    float acc[4][4][4] = {};
    for (int k0 = 0; k0 < CC; k0 += 32) {
        stage_mk(Ain + ((size_t)b * NTOK + n0) * CC + k0, CC, sm + OP_AH, sm + OP_AL, t);
        stage_km(W + (size_t)k0 * CC + j0, CC, sm + OP_BH, sm + OP_BL, t);
        __syncthreads();
        #pragma unroll
        for (int kt = 0; kt < 2; kt++) {
            u32 ah[4][4], al[4][4];
            #pragma unroll
            for (int mt = 0; mt < 4; mt++) {
                ldA_mk(ah[mt], aH, 40, wm * 64 + mt * 16, kt * 16, lane);
                ldA_mk(al[mt], aL, 40, wm * 64 + mt * 16, kt * 16, lane);
            }
            #pragma unroll
            for (int ng = 0; ng < 2; ng++) {
                u32 bh[4], bl[4];
                ldB_kn(bh, bH, 136, kt * 16, wn * 32 + ng * 16, lane);
                ldB_kn(bl, bL, 136, kt * 16, wn * 32 + ng * 16, lane);
                #pragma unroll
                for (int mt = 0; mt < 4; mt++) {
                    mma_bf16(acc[mt][ng * 2],     ah[mt], bh[0], bh[1]);
                    mma_bf16(acc[mt][ng * 2],     ah[mt], bl[0], bl[1]);
                    mma_bf16(acc[mt][ng * 2],     al[mt], bh[0], bh[1]);
                    mma_bf16(acc[mt][ng * 2 + 1], ah[mt], bh[2], bh[3]);
                    mma_bf16(acc[mt][ng * 2 + 1], ah[mt], bl[2], bl[3]);
                    mma_bf16(acc[mt][ng * 2 + 1], al[mt], bh[2], bh[3]);
                }
            }
        }
        __syncthreads();
    }
    // transpose through smem: Cs[j][132]
    float* Cs = (float*)sm;
    #pragma unroll
    for (int mt = 0; mt < 4; mt++)
        #pragma unroll
        for (int tn = 0; tn < 4; tn++)
            #pragma unroll
            for (int half = 0; half < 2; half++) {
                int ml = wm * 64 + mt * 16 + r + half * 8;
                int jl = wn * 32 + tn * 8 + 2 * mu;
                Cs[jl * 132 + ml]       = acc[mt][tn][half * 2];
                Cs[(jl + 1) * 132 + ml] = acc[mt][tn][half * 2 + 1];
            }
    __syncthreads();
    #pragma unroll
    for (int i = 0; i < 16; i++) {
        int lin = i * 256 + t;
        int j = lin >> 5, mq = (lin & 31) * 4;
        float4 v = *(float4*)&Cs[j * 132 + mq];
        float bv = bias[j0 + j];
        v.x += bv; v.y += bv; v.z += bv; v.w += bv;
        *(float4*)&Out[((size_t)b * CC + j0 + j) * NTOK + n0 + mq] = v;
    }
}

// ---------------- launch ----------------
extern "C" void kernel_launch(void* const* d_in, const int* in_sizes, int n_in,
                              void* d_out, int out_size) {
    const float* fv   = (const float*)d_in[0];
    const float* text = (const float*)d_in[1];
    const float* q_w  = (const float*)d_in[2];
    const float* q_b  = (const float*)d_in[3];
    const float* k_w  = (const float*)d_in[4];
    const float* k_b  = (const float*)d_in[5];
    const float* v_w  = (const float*)d_in[6];
    const float* v_b  = (const float*)d_in[7];
    const float* o_w  = (const float*)d_in[8];
    const float* o_b  = (const float*)d_in[9];
    const float* m1_w = (const float*)d_in[10];
    const float* m1_b = (const float*)d_in[11];
    const float* m2_w = (const float*)d_in[12];
    const float* m2_b = (const float*)d_in[13];
    float* out = (float*)d_out;

    init_invf_kernel<<<1, 32>>>();
    text3_kernel<<<dim3(4, 16, 3), 256>>>(text, k_w, k_b, v_w, v_b, m1_w, m1_b);
    phase_gemm_kernel<<<dim3(4, 16), 256>>>(m2_w, m2_b);
    text_rope_kernel<<<256, 256>>>();

    qproj_mma_kernel<<<dim3(2, 256, 2), 256>>>(fv, q_w, q_b);

    cudaFuncSetAttribute(attn_mma_kernel, cudaFuncAttributeMaxDynamicSharedMemorySize, AT_SMEM);
    attn_mma_kernel<<<dim3(256, 8, 2), 256, AT_SMEM>>>();

    cudaFuncSetAttribute(oproj_mma_kernel, cudaFuncAttributeMaxDynamicSharedMemorySize, OP_SMEM);
    oproj_mma_kernel<<<dim3(2, 256, 2), 256, OP_SMEM>>>(o_w, o_b, out);
}

// round 7
// speedup vs baseline: 4.6073x; 1.0858x over previous
#include <cuda_runtime.h>
#include <cuda_bf16.h>
#include <math.h>
#include <math_constants.h>

#define BB    2
#define CC    256
#define NTOK  32768
#define SS    256
#define TDIM  512
#define NHD   8
#define HDIM  32

typedef unsigned u32;
typedef unsigned long long ull;

// ---------------- scratch ----------------
#define OFF_H1    0
#define OFF_KRAW  (OFF_H1   + 131072)
#define OFF_VRAW  (OFF_KRAW + 131072)
#define OFF_PHASE (OFF_VRAW + 131072)
#define OFF_KROT  (OFF_PHASE+ 131072)      // fp32 [b,h][d=32][s=256]
#define OFF_VT    (OFF_KROT + 131072)      // fp32 [b,h][s=256][d=32]
#define OFF_Q     (OFF_VT   + 131072)      // fp32 [b][n][256]
#define OFF_AO    (OFF_Q    + 16777216)    // fp32 [b][n][256]
#define OFF_INVF  (OFF_AO   + 16777216)
#define SCR_TOTAL (OFF_INVF + 32)
__device__ float g_scr[SCR_TOTAL];

// ---------------- helpers ----------------
__device__ __forceinline__ void ldsm4(u32& r0, u32& r1, u32& r2, u32& r3, u32 addr) {
    asm volatile("ldmatrix.sync.aligned.m8n8.x4.shared.b16 {%0,%1,%2,%3}, [%4];"
                 : "=r"(r0), "=r"(r1), "=r"(r2), "=r"(r3) : "r"(addr));
}
__device__ __forceinline__ void ldsm4t(u32& r0, u32& r1, u32& r2, u32& r3, u32 addr) {
    asm volatile("ldmatrix.sync.aligned.m8n8.x4.trans.shared.b16 {%0,%1,%2,%3}, [%4];"
                 : "=r"(r0), "=r"(r1), "=r"(r2), "=r"(r3) : "r"(addr));
}
__device__ __forceinline__ void mma_bf16(float* d, const u32* a, u32 b0, u32 b1) {
    asm volatile("mma.sync.aligned.m16n8k16.row.col.f32.bf16.bf16.f32 "
                 "{%0,%1,%2,%3}, {%4,%5,%6,%7}, {%8,%9}, {%0,%1,%2,%3};"
                 : "+f"(d[0]), "+f"(d[1]), "+f"(d[2]), "+f"(d[3])
                 : "r"(a[0]), "r"(a[1]), "r"(a[2]), "r"(a[3]), "r"(b0), "r"(b1));
}
__device__ __forceinline__ void bf16split2(float x, float y, u32& hi, u32& lo) {
    asm("cvt.rn.bf16x2.f32 %0, %1, %2;" : "=r"(hi) : "f"(y), "f"(x));
    float hx = __uint_as_float(hi << 16);
    float hy = __uint_as_float(hi & 0xffff0000u);
    asm("cvt.rn.bf16x2.f32 %0, %1, %2;" : "=r"(lo) : "f"(y - hy), "f"(x - hx));
}
__device__ __forceinline__ void ldA_mk(u32* f, u32 base, int stride, int m0, int k0, int lane) {
    int m = m0 + (lane & 15);
    int k = k0 + ((lane >> 4) << 3);
    ldsm4(f[0], f[1], f[2], f[3], base + (u32)((m * stride + k) * 2));
}
__device__ __forceinline__ void ldA_km(u32* f, u32 base, int stride, int k0, int m0, int lane) {
    int k = k0 + (lane & 7) + ((lane >> 4) << 3);
    int m = m0 + (((lane >> 3) & 1) << 3);
    ldsm4t(f[0], f[1], f[2], f[3], base + (u32)((k * stride + m) * 2));
}
__device__ __forceinline__ void ldB_kn(u32* f, u32 base, int stride, int k0, int n0, int lane) {
    int k = k0 + (lane & 7) + (((lane >> 3) & 1) << 3);
    int n = n0 + ((lane >> 4) << 3);
    ldsm4t(f[0], f[1], f[2], f[3], base + (u32)((k * stride + n) * 2));
}
// stage 32(k) x 128(cols) fp32 tile -> split bf16 [k][136] hi/lo
__device__ __forceinline__ void stage_km(const float* g, int gstride, char* smH, char* smL, int t) {
    #pragma unroll
    for (int i = 0; i < 4; i++) {
        int lin = i * 256 + t;
        int kr = lin >> 5, mq = (lin & 31) * 4;
        float4 v = *(const float4*)(g + (size_t)kr * gstride + mq);
        u32 h0, l0, h1, l1;
        bf16split2(v.x, v.y, h0, l0);
        bf16split2(v.z, v.w, h1, l1);
        *(ull*)(smH + (size_t)(kr * 68 + (mq >> 1)) * 4) = (ull)h0 | ((ull)h1 << 32);
        *(ull*)(smL + (size_t)(kr * 68 + (mq >> 1)) * 4) = (ull)l0 | ((ull)l1 << 32);
    }
}
// stage 128(m) x 32(k) fp32 tile -> split bf16 [m][40] hi/lo
__device__ __forceinline__ void stage_mk(const float* g, int gstride, char* smH, char* smL, int t) {
    #pragma unroll
    for (int i = 0; i < 4; i++) {
        int lin = i * 256 + t;
        int mr = lin >> 3, kq = (lin & 7) * 4;
        float4 v = *(const float4*)(g + (size_t)mr * gstride + kq);
        u32 h0, l0, h1, l1;
        bf16split2(v.x, v.y, h0, l0);
        bf16split2(v.z, v.w, h1, l1);
        *(ull*)(smH + (size_t)(mr * 20 + (kq >> 1)) * 4) = (ull)h0 | ((ull)h1 << 32);
        *(ull*)(smL + (size_t)(mr * 20 + (kq >> 1)) * 4) = (ull)l0 | ((ull)l1 << 32);
    }
}

// ---------------- rope inverse-frequency table ----------------
__global__ void init_invf_kernel() {
    int d = threadIdx.x;
    if (d < 32) {
        float e;
        if (d < 10)       e = (float)(2 * (d % 5)) / 10.f;
        else if (d < 20)  e = (float)(2 * ((d - 10) % 5)) / 10.f;
        else              e = (float)(2 * ((d - 20) % 6)) / 12.f;
        g_scr[OFF_INVF + d] = powf(10000.f, -e);
    }
}

// ---------------- fp32 text GEMMs (proven) ----------------
__device__ __forceinline__ void gemm32x64_body(const float* __restrict__ A,
                                               const float* __restrict__ W,
                                               const float* __restrict__ bias,
                                               float* __restrict__ Y,
                                               int K, int N, int act,
                                               int m0, int j0,
                                               float* As, float* Ws) {
    int t = threadIdx.x;
    int tx = t & 15, ty = t >> 4;
    float acc[2][4] = {};
    for (int k0 = 0; k0 < K; k0 += 16) {
        if (t < 128) {
            int m = t >> 2, kq = (t & 3) * 4;
            float4 av = *(const float4*)&A[(size_t)(m0 + m) * K + k0 + kq];
            As[(kq + 0) * 33 + m] = av.x;
            As[(kq + 1) * 33 + m] = av.y;
            As[(kq + 2) * 33 + m] = av.z;
            As[(kq + 3) * 33 + m] = av.w;
        }
        {
            int kk = t >> 4, j4 = (t & 15) * 4;
            *(float4*)&Ws[kk * 64 + j4] = *(const float4*)&W[(size_t)(k0 + kk) * N + j0 + j4];
        }
        __syncthreads();
        #pragma unroll
        for (int kk = 0; kk < 16; kk++) {
            float a0 = As[kk * 33 + ty * 2], a1 = As[kk * 33 + ty * 2 + 1];
            #pragma unroll
            for (int j = 0; j < 4; j++) {
                float w = Ws[kk * 64 + tx + 16 * j];
                acc[0][j] += a0 * w;
                acc[1][j] += a1 * w;
            }
        }
        __syncthreads();
    }
    #pragma unroll
    for (int j = 0; j < 4; j++) {
        int jj = j0 + tx + 16 * j;
        float bv = bias[jj];
        #pragma unroll
        for (int i = 0; i < 2; i++) {
            float v = acc[i][j] + bv;
            if (act) v = 0.5f * v * (1.f + erff(v * 0.70710678118654752f));
            Y[(size_t)(m0 + ty * 2 + i) * N + jj] = v;
        }
    }
}

__global__ void text3_kernel(const float* __restrict__ text,
                             const float* __restrict__ kw, const float* __restrict__ kb,
                             const float* __restrict__ vw, const float* __restrict__ vb,
                             const float* __restrict__ m1w, const float* __restrict__ m1b) {
    __shared__ float As[16 * 33];
    __shared__ float Ws[16 * 64];
    const float *W, *bias;
    float* Y;
    int act = 0;
    if (blockIdx.z == 0)      { W = kw;  bias = kb;  Y = g_scr + OFF_KRAW; }
    else if (blockIdx.z == 1) { W = vw;  bias = vb;  Y = g_scr + OFF_VRAW; }
    else                      { W = m1w; bias = m1b; Y = g_scr + OFF_H1; act = 1; }
    gemm32x64_body(text, W, bias, Y, 512, 256, act, blockIdx.y * 32, blockIdx.x * 64, As, Ws);
}

__global__ void phase_gemm_kernel(const float* __restrict__ m2w, const float* __restrict__ m2b) {
    __shared__ float As[16 * 33];
    __shared__ float Ws[16 * 64];
    gemm32x64_body(g_scr + OFF_H1, m2w, m2b, g_scr + OFF_PHASE, 256, 256, 0,
                   blockIdx.y * 32, blockIdx.x * 64, As, Ws);
}

// ---------------- text rope: krot -> [b,h][d][s], vt -> [b,h][s][d] ----------------
__global__ void text_rope_kernel() {
    int idx = blockIdx.x * blockDim.x + threadIdx.x;  // < 65536
    int p = idx & 15;
    int h = (idx >> 4) & 7;
    int s = (idx >> 7) & 255;
    int b = idx >> 15;
    const float* kraw = g_scr + OFF_KRAW;
    const float* vraw = g_scr + OFF_VRAW;
    const float* ph   = g_scr + OFF_PHASE;
    float* krot = g_scr + OFF_KROT;
    float* vt   = g_scr + OFF_VT;
    int base = (b * SS + s) * CC + h * HDIM;
    int bh = b * NHD + h;
    float k0 = kraw[base + p], k1 = kraw[base + p + 16];
    float p0 = ph[base + p],   p1 = ph[base + p + 16];
    float c0, s0, c1, s1;
    __sincosf(p0, &s0, &c0);
    __sincosf(p1, &s1, &c1);
    krot[(bh * HDIM + p) * SS + s]        = k0 * c0 - k1 * s0;
    krot[(bh * HDIM + p + 16) * SS + s]   = k1 * c1 + k0 * s1;
    vt[(bh * SS + s) * HDIM + p]          = vraw[base + p];
    vt[(bh * SS + s) * HDIM + p + 16]     = vraw[base + p + 16];
}

// ================= Q projection (mma.sync) with fused 3D rope =================
#define QP_AH 0
#define QP_AL 8704
#define QP_BH 17408
#define QP_BL 26112
__global__ __launch_bounds__(256, 1) void qproj_mma_kernel(
        const float* __restrict__ A, const float* __restrict__ W,
        const float* __restrict__ bias) {
    __shared__ char sm[34816];
    float* Y = g_scr + OFF_Q;
    const float* invf = g_scr + OFF_INVF;
    int b = blockIdx.z;
    int n0 = blockIdx.y * 128, j0 = blockIdx.x * 128;
    int t = threadIdx.x;
    int w = t >> 5, lane = t & 31;
    int wm = w & 1, wn = w >> 1;
    int mu = lane & 3, r = lane >> 2;
    const float* Ab = A + (size_t)b * CC * NTOK;
    u32 aH = (u32)__cvta_generic_to_shared(sm + QP_AH);
    u32 aL = (u32)__cvta_generic_to_shared(sm + QP_AL);
    u32 bH = (u32)__cvta_generic_to_shared(sm + QP_BH);
    u32 bL = (u32)__cvta_generic_to_shared(sm + QP_BL);
    float acc[4][4][4] = {};
    for (int k0 = 0; k0 < CC; k0 += 32) {
        stage_km(Ab + (size_t)k0 * NTOK + n0, NTOK, sm + QP_AH, sm + QP_AL, t);
        stage_km(W + (size_t)k0 * CC + j0, CC, sm + QP_BH, sm + QP_BL, t);
        __syncthreads();
        #pragma unroll
        for (int kt = 0; kt < 2; kt++) {
            u32 ah[4][4], al[4][4];
            #pragma unroll
            for (int mt = 0; mt < 4; mt++) {
                ldA_km(ah[mt], aH, 136, kt * 16, wm * 64 + mt * 16, lane);
                ldA_km(al[mt], aL, 136, kt * 16, wm * 64 + mt * 16, lane);
            }
            #pragma unroll
            for (int ng = 0; ng < 2; ng++) {
                u32 bh[4], bl[4];
                ldB_kn(bh, bH, 136, kt * 16, wn * 32 + ng * 16, lane);
                ldB_kn(bl, bL, 136, kt * 16, wn * 32 + ng * 16, lane);
                // hh terms: 8 independent accs back-to-back
                #pragma unroll
                for (int mt = 0; mt < 4; mt++) {
                    mma_bf16(acc[mt][ng * 2],     ah[mt], bh[0], bh[1]);
                    mma_bf16(acc[mt][ng * 2 + 1], ah[mt], bh[2], bh[3]);
                }
                // hl terms
                #pragma unroll
                for (int mt = 0; mt < 4; mt++) {
                    mma_bf16(acc[mt][ng * 2],     ah[mt], bl[0], bl[1]);
                    mma_bf16(acc[mt][ng * 2 + 1], ah[mt], bl[2], bl[3]);
                }
                // lh terms
                #pragma unroll
                for (int mt = 0; mt < 4; mt++) {
                    mma_bf16(acc[mt][ng * 2],     al[mt], bh[0], bh[1]);
                    mma_bf16(acc[mt][ng * 2 + 1], al[mt], bh[2], bh[3]);
                }
            }
        }
        __syncthreads();
    }
    // epilogue: bias + rope (MUFU sincos), store fp32 Q
    float blo[2][2], bhi[2][2], fl0[2][2], fl1[2][2];
    int zsel[2][2], xsel[2][2];
    #pragma unroll
    for (int tn = 0; tn < 2; tn++)
        #pragma unroll
        for (int cc = 0; cc < 2; cc++) {
            int d = tn * 8 + 2 * mu + cc;
            blo[tn][cc] = bias[j0 + wn * 32 + d];
            bhi[tn][cc] = bias[j0 + wn * 32 + d + 16];
            fl0[tn][cc] = invf[d];
            fl1[tn][cc] = invf[d + 16];
            zsel[tn][cc] = (d < 10);
            xsel[tn][cc] = (d + 16 >= 20);
        }
    #pragma unroll
    for (int mt = 0; mt < 4; mt++)
        #pragma unroll
        for (int half = 0; half < 2; half++) {
            int n = n0 + wm * 64 + mt * 16 + r + half * 8;
            float wx = (float)(n & 31), hy = (float)((n >> 5) & 31), dz = (float)(n >> 10);
            float* yp = Y + ((size_t)b * NTOK + n) * CC + j0 + wn * 32;
            #pragma unroll
            for (int tn = 0; tn < 2; tn++) {
                float v0[2], v1[2];
                #pragma unroll
                for (int cc = 0; cc < 2; cc++) {
                    float q0 = acc[mt][tn][half * 2 + cc] + blo[tn][cc];
                    float q1 = acc[mt][tn + 2][half * 2 + cc] + bhi[tn][cc];
                    float f0 = (zsel[tn][cc] ? dz : hy) * fl0[tn][cc];
                    float f1 = (xsel[tn][cc] ? wx : hy) * fl1[tn][cc];
                    float s0, c0, s1, c1;
                    __sincosf(f0, &s0, &c0);
                    __sincosf(f1, &s1, &c1);
                    v0[cc] = q0 * c0 - q1 * s0;
                    v1[cc] = q1 * c1 + q0 * s1;
                }
                *(float2*)&yp[tn * 8 + 2 * mu]      = make_float2(v0[0], v0[1]);
                *(float2*)&yp[tn * 8 + 2 * mu + 16] = make_float2(v1[0], v1[1]);
            }
        }
}

// ================= attention (mma.sync): 128 tokens/block =================
#define AT_QH 0
#define AT_QL 10240
#define AT_KH 20480
#define AT_KL 37376
#define AT_VH 54272
#define AT_VL 74752
#define AT_SMEM 95232
__global__ __launch_bounds__(256, 1) void attn_mma_kernel() {
    extern __shared__ char sm[];
    const float* q    = g_scr + OFF_Q;
    const float* krot = g_scr + OFF_KROT;
    const float* vt   = g_scr + OFF_VT;
    float* ao = g_scr + OFF_AO;
    int b = blockIdx.z, h = blockIdx.y;
    int n0 = blockIdx.x * 128;
    int t = threadIdx.x;
    int w = t >> 5, lane = t & 31;
    int mu = lane & 3, r = lane >> 2;
    const float scale = 0.17677669529663687f;
    u32* QHu = (u32*)(sm + AT_QH);
    u32* QLu = (u32*)(sm + AT_QL);
    u32* KHu = (u32*)(sm + AT_KH);
    u32* KLu = (u32*)(sm + AT_KL);
    u32* VHu = (u32*)(sm + AT_VH);
    u32* VLu = (u32*)(sm + AT_VL);
    #pragma unroll
    for (int i = 0; i < 8; i++) {
        int lin = i * 256 + t;
        int row = lin >> 4, dp = lin & 15;
        float2 v = *(const float2*)&q[((size_t)b * NTOK + n0 + row) * CC + h * HDIM + dp * 2];
        u32 hh, ll;
        bf16split2(v.x * scale, v.y * scale, hh, ll);
        QHu[row * 20 + dp] = hh;
        QLu[row * 20 + dp] = ll;
    }
    size_t kb = (size_t)(b * NHD + h) * HDIM * SS;
    #pragma unroll
    for (int i = 0; i < 16; i++) {
        int lin = i * 256 + t;
        int d = lin >> 7, sp = lin & 127;
        float2 v = *(const float2*)&krot[kb + (size_t)d * SS + sp * 2];
        u32 hh, ll;
        bf16split2(v.x, v.y, hh, ll);
        KHu[d * 132 + sp] = hh;
        KLu[d * 132 + sp] = ll;
    }
    size_t vb = (size_t)(b * NHD + h) * SS * HDIM;
    #pragma unroll
    for (int i = 0; i < 16; i++) {
        int lin = i * 256 + t;
        int s = lin >> 4, dp = lin & 15;
        float2 v = *(const float2*)&vt[vb + (size_t)s * HDIM + dp * 2];
        u32 hh, ll;
        bf16split2(v.x, v.y, hh, ll);
        VHu[s * 20 + dp] = hh;
        VLu[s * 20 + dp] = ll;
    }
    __syncthreads();
    u32 aQH = (u32)__cvta_generic_to_shared(sm + AT_QH);
    u32 aQL = (u32)__cvta_generic_to_shared(sm + AT_QL);
    u32 aKH = (u32)__cvta_generic_to_shared(sm + AT_KH);
    u32 aKL = (u32)__cvta_generic_to_shared(sm + AT_KL);
    u32 aVH = (u32)__cvta_generic_to_shared(sm + AT_VH);
    u32 aVL = (u32)__cvta_generic_to_shared(sm + AT_VL);
    float acc[32][4];
    #pragma unroll
    for (int i = 0; i < 32; i++)
        #pragma unroll
        for (int j = 0; j < 4; j++) acc[i][j] = 0.f;
    #pragma unroll
    for (int kt = 0; kt < 2; kt++) {
        u32 qh[4], ql[4];
        ldA_mk(qh, aQH, 40, w * 16, kt * 16, lane);
        ldA_mk(ql, aQL, 40, w * 16, kt * 16, lane);
        #pragma unroll
        for (int sg = 0; sg < 16; sg++) {
            u32 kh[4], kl[4];
            ldB_kn(kh, aKH, 264, kt * 16, sg * 16, lane);
            ldB_kn(kl, aKL, 264, kt * 16, sg * 16, lane);
            // interleave n-tiles per term: dep distance 2
            mma_bf16(acc[sg * 2],     qh, kh[0], kh[1]);
            mma_bf16(acc[sg * 2 + 1], qh, kh[2], kh[3]);
            mma_bf16(acc[sg * 2],     qh, kl[0], kl[1]);
            mma_bf16(acc[sg * 2 + 1], qh, kl[2], kl[3]);
            mma_bf16(acc[sg * 2],     ql, kh[0], kh[1]);
            mma_bf16(acc[sg * 2 + 1], ql, kh[2], kh[3]);
        }
    }
    float mx0 = -CUDART_INF_F, mx1 = -CUDART_INF_F;
    #pragma unroll
    for (int i = 0; i < 32; i++) {
        mx0 = fmaxf(mx0, fmaxf(acc[i][0], acc[i][1]));
        mx1 = fmaxf(mx1, fmaxf(acc[i][2], acc[i][3]));
    }
    mx0 = fmaxf(mx0, __shfl_xor_sync(0xffffffffu, mx0, 1));
    mx0 = fmaxf(mx0, __shfl_xor_sync(0xffffffffu, mx0, 2));
    mx1 = fmaxf(mx1, __shfl_xor_sync(0xffffffffu, mx1, 1));
    mx1 = fmaxf(mx1, __shfl_xor_sync(0xffffffffu, mx1, 2));
    float sum0 = 0.f, sum1 = 0.f;
    #pragma unroll
    for (int i = 0; i < 32; i++) {
        acc[i][0] = __expf(acc[i][0] - mx0);
        acc[i][1] = __expf(acc[i][1] - mx0);
        acc[i][2] = __expf(acc[i][2] - mx1);
        acc[i][3] = __expf(acc[i][3] - mx1);
        sum0 += acc[i][0] + acc[i][1];
        sum1 += acc[i][2] + acc[i][3];
    }
    sum0 += __shfl_xor_sync(0xffffffffu, sum0, 1);
    sum0 += __shfl_xor_sync(0xffffffffu, sum0, 2);
    sum1 += __shfl_xor_sync(0xffffffffu, sum1, 1);
    sum1 += __shfl_xor_sync(0xffffffffu, sum1, 2);
    float zi0 = 1.f / sum0, zi1 = 1.f / sum1;
    float oacc[4][4] = {};
    #pragma unroll
    for (int kt = 0; kt < 16; kt++) {
        u32 ah[4], al[4];
        bf16split2(acc[2 * kt][0],     acc[2 * kt][1],     ah[0], al[0]);
        bf16split2(acc[2 * kt][2],     acc[2 * kt][3],     ah[1], al[1]);
        bf16split2(acc[2 * kt + 1][0], acc[2 * kt + 1][1], ah[2], al[2]);
        bf16split2(acc[2 * kt + 1][2], acc[2 * kt + 1][3], ah[3], al[3]);
        u32 vh[2][4], vl[2][4];
        ldB_kn(vh[0], aVH, 40, kt * 16, 0, lane);
        ldB_kn(vl[0], aVL, 40, kt * 16, 0, lane);
        ldB_kn(vh[1], aVH, 40, kt * 16, 16, lane);
        ldB_kn(vl[1], aVL, 40, kt * 16, 16, lane);
        // term-major sweep over 4 accs: dep distance 4
        #pragma unroll
        for (int dg = 0; dg < 2; dg++) {
            mma_bf16(oacc[dg * 2],     ah, vh[dg][0], vh[dg][1]);
            mma_bf16(oacc[dg * 2 + 1], ah, vh[dg][2], vh[dg][3]);
        }
        #pragma unroll
        for (int dg = 0; dg < 2; dg++) {
            mma_bf16(oacc[dg * 2],     ah, vl[dg][0], vl[dg][1]);
            mma_bf16(oacc[dg * 2 + 1], ah, vl[dg][2], vl[dg][3]);
        }
        #pragma unroll
        for (int dg = 0; dg < 2; dg++) {
            mma_bf16(oacc[dg * 2],     al, vh[dg][0], vh[dg][1]);
            mma_bf16(oacc[dg * 2 + 1], al, vh[dg][2], vh[dg][3]);
        }
    }
    #pragma unroll
    for (int dt = 0; dt < 4; dt++) {
        int dcol = dt * 8 + 2 * mu;
        size_t r0 = ((size_t)b * NTOK + n0 + w * 16 + r) * CC + h * HDIM + dcol;
        size_t r1 = ((size_t)b * NTOK + n0 + w * 16 + r + 8) * CC + h * HDIM + dcol;
        *(float2*)&ao[r0] = make_float2(oacc[dt][0] * zi0, oacc[dt][1] * zi0);
        *(float2*)&ao[r1] = make_float2(oacc[dt][2] * zi1, oacc[dt][3] * zi1);
    }
}

// ================= O projection (mma.sync) + transpose =================
#define OP_AH 0
#define OP_AL 10240
#define OP_BH 20480
#define OP_BL 29184
#define OP_SMEM 67584
__global__ __launch_bounds__(256, 1) void oproj_mma_kernel(
        const float* __restrict__ W, const float* __restrict__ bias,
        float* __restrict__ Out) {
    extern __shared__ char sm[];
    const float* Ain = g_scr + OFF_AO;
    int b = blockIdx.z;
    int n0 = blockIdx.y * 128, j0 = blockIdx.x * 128;
    int t = threadIdx.x;
    int w = t >> 5, lane = t & 31;
    int wm = w & 1, wn = w >> 1;
    int mu = lane & 3, r = lane >> 2;
    u32 aH = (u32)__cvta_generic_to_shared(sm + OP_AH);
    u32 aL = (u32)__cvta_generic_to_shared(sm + OP_AL);
    u32 bH = (u32)__cvta_generic_to_shared(sm + OP_BH);
    u32 bL = (u32)__cvta_generic_to_shared(sm + OP_BL);
    float acc[4][4][4] = {};
    for (int k0 = 0; k0 < CC; k0 += 32) {
        stage_mk(Ain + ((size_t)b * NTOK + n0) * CC + k0, CC, sm + OP_AH, sm + OP_AL, t);
        stage_km(W + (size_t)k0 * CC + j0, CC, sm + OP_BH, sm + OP_BL, t);
        __syncthreads();
        #pragma unroll
        for (int kt = 0; kt < 2; kt++) {
            u32 ah[4][4], al[4][4];
            #pragma unroll
            for (int mt = 0; mt < 4; mt++) {
                ldA_mk(ah[mt], aH, 40, wm * 64 + mt * 16, kt * 16, lane);
                ldA_mk(al[mt], aL, 40, wm * 64 + mt * 16, kt * 16, lane);
            }
            #pragma unroll
            for (int ng = 0; ng < 2; ng++) {
                u32 bh[4], bl[4];
                ldB_kn(bh, bH, 136, kt * 16, wn * 32 + ng * 16, lane);
                ldB_kn(bl, bL, 136, kt * 16, wn * 32 + ng * 16, lane);
                #pragma unroll
                for (int mt = 0; mt < 4; mt++) {
                    mma_bf16(acc[mt][ng * 2],     ah[mt], bh[0], bh[1]);
                    mma_bf16(acc[mt][ng * 2 + 1], ah[mt], bh[2], bh[3]);
                }
                #pragma unroll
                for (int mt = 0; mt < 4; mt++) {
                    mma_bf16(acc[mt][ng * 2],     ah[mt], bl[0], bl[1]);
                    mma_bf16(acc[mt][ng * 2 + 1], ah[mt], bl[2], bl[3]);
                }
                #pragma unroll
                for (int mt = 0; mt < 4; mt++) {
                    mma_bf16(acc[mt][ng * 2],     al[mt], bh[0], bh[1]);
                    mma_bf16(acc[mt][ng * 2 + 1], al[mt], bh[2], bh[3]);
                }
            }
        }
        __syncthreads();
    }
    float* Cs = (float*)sm;
    #pragma unroll
    for (int mt = 0; mt < 4; mt++)
        #pragma unroll
        for (int tn = 0; tn < 4; tn++)
            #pragma unroll
            for (int half = 0; half < 2; half++) {
                int ml = wm * 64 + mt * 16 + r + half * 8;
                int jl = wn * 32 + tn * 8 + 2 * mu;
                Cs[jl * 132 + ml]       = acc[mt][tn][half * 2];
                Cs[(jl + 1) * 132 + ml] = acc[mt][tn][half * 2 + 1];
            }
    __syncthreads();
    #pragma unroll
    for (int i = 0; i < 16; i++) {
        int lin = i * 256 + t;
        int j = lin >> 5, mq = (lin & 31) * 4;
        float4 v = *(float4*)&Cs[j * 132 + mq];
        float bv = bias[j0 + j];
        v.x += bv; v.y += bv; v.z += bv; v.w += bv;
        *(float4*)&Out[((size_t)b * CC + j0 + j) * NTOK + n0 + mq] = v;
    }
}

// ---------------- launch ----------------
extern "C" void kernel_launch(void* const* d_in, const int* in_sizes, int n_in,
                              void* d_out, int out_size) {
    const float* fv   = (const float*)d_in[0];
    const float* text = (const float*)d_in[1];
    const float* q_w  = (const float*)d_in[2];
    const float* q_b  = (const float*)d_in[3];
    const float* k_w  = (const float*)d_in[4];
    const float* k_b  = (const float*)d_in[5];
    const float* v_w  = (const float*)d_in[6];
    const float* v_b  = (const float*)d_in[7];
    const float* o_w  = (const float*)d_in[8];
    const float* o_b  = (const float*)d_in[9];
    const float* m1_w = (const float*)d_in[10];
    const float* m1_b = (const float*)d_in[11];
    const float* m2_w = (const float*)d_in[12];
    const float* m2_b = (const float*)d_in[13];
    float* out = (float*)d_out;

    init_invf_kernel<<<1, 32>>>();
    text3_kernel<<<dim3(4, 16, 3), 256>>>(text, k_w, k_b, v_w, v_b, m1_w, m1_b);
    phase_gemm_kernel<<<dim3(4, 16), 256>>>(m2_w, m2_b);
    text_rope_kernel<<<256, 256>>>();

    qproj_mma_kernel<<<dim3(2, 256, 2), 256>>>(fv, q_w, q_b);

    cudaFuncSetAttribute(attn_mma_kernel, cudaFuncAttributeMaxDynamicSharedMemorySize, AT_SMEM);
    attn_mma_kernel<<<dim3(256, 8, 2), 256, AT_SMEM>>>();

    cudaFuncSetAttribute(oproj_mma_kernel, cudaFuncAttributeMaxDynamicSharedMemorySize, OP_SMEM);
    oproj_mma_kernel<<<dim3(2, 256, 2), 256, OP_SMEM>>>(o_w, o_b, out);
}

// round 8
// speedup vs baseline: 5.4180x; 1.1759x over previous
#include <cuda_runtime.h>
#include <cuda_bf16.h>
#include <cuda_fp16.h>
#include <math.h>
#include <math_constants.h>

#define BB    2
#define CC    256
#define NTOK  32768
#define SS    256
#define TDIM  512
#define NHD   8
#define HDIM  32

typedef unsigned u32;
typedef unsigned long long ull;

// ---------------- scratch ----------------
#define OFF_H1    0
#define OFF_KRAW  (OFF_H1   + 131072)
#define OFF_VRAW  (OFF_KRAW + 131072)
#define OFF_PHASE (OFF_VRAW + 131072)
#define OFF_KROT  (OFF_PHASE+ 131072)      // fp32 [b,h][d=32][s=256]
#define OFF_VT    (OFF_KROT + 131072)      // fp32 [b,h][s=256][d=32]
#define OFF_Q     (OFF_VT   + 131072)      // fp32 [b][n][256]
#define OFF_AO    (OFF_Q    + 16777216)    // fp32 [b][n][256]
#define OFF_INVF  (OFF_AO   + 16777216)
#define SCR_TOTAL (OFF_INVF + 32)
__device__ float g_scr[SCR_TOTAL];

// ---------------- helpers ----------------
__device__ __forceinline__ void ldsm4(u32& r0, u32& r1, u32& r2, u32& r3, u32 addr) {
    asm volatile("ldmatrix.sync.aligned.m8n8.x4.shared.b16 {%0,%1,%2,%3}, [%4];"
                 : "=r"(r0), "=r"(r1), "=r"(r2), "=r"(r3) : "r"(addr));
}
__device__ __forceinline__ void ldsm4t(u32& r0, u32& r1, u32& r2, u32& r3, u32 addr) {
    asm volatile("ldmatrix.sync.aligned.m8n8.x4.trans.shared.b16 {%0,%1,%2,%3}, [%4];"
                 : "=r"(r0), "=r"(r1), "=r"(r2), "=r"(r3) : "r"(addr));
}
__device__ __forceinline__ void mma_bf16(float* d, const u32* a, u32 b0, u32 b1) {
    asm volatile("mma.sync.aligned.m16n8k16.row.col.f32.bf16.bf16.f32 "
                 "{%0,%1,%2,%3}, {%4,%5,%6,%7}, {%8,%9}, {%0,%1,%2,%3};"
                 : "+f"(d[0]), "+f"(d[1]), "+f"(d[2]), "+f"(d[3])
                 : "r"(a[0]), "r"(a[1]), "r"(a[2]), "r"(a[3]), "r"(b0), "r"(b1));
}
__device__ __forceinline__ void mma_f16(float* d, const u32* a, u32 b0, u32 b1) {
    asm volatile("mma.sync.aligned.m16n8k16.row.col.f32.f16.f16.f32 "
                 "{%0,%1,%2,%3}, {%4,%5,%6,%7}, {%8,%9}, {%0,%1,%2,%3};"
                 : "+f"(d[0]), "+f"(d[1]), "+f"(d[2]), "+f"(d[3])
                 : "r"(a[0]), "r"(a[1]), "r"(a[2]), "r"(a[3]), "r"(b0), "r"(b1));
}
__device__ __forceinline__ void bf16split2(float x, float y, u32& hi, u32& lo) {
    asm("cvt.rn.bf16x2.f32 %0, %1, %2;" : "=r"(hi) : "f"(y), "f"(x));
    float hx = __uint_as_float(hi << 16);
    float hy = __uint_as_float(hi & 0xffff0000u);
    asm("cvt.rn.bf16x2.f32 %0, %1, %2;" : "=r"(lo) : "f"(y - hy), "f"(x - hx));
}
// fp16 pack (x -> low half, y -> high half)
__device__ __forceinline__ void f16pack2(float x, float y, u32& h) {
    asm("cvt.rn.f16x2.f32 %0, %1, %2;" : "=r"(h) : "f"(y), "f"(x));
}
// fp16 hi/lo split of (x,y)
__device__ __forceinline__ void f16split2(float x, float y, u32& hi, u32& lo) {
    f16pack2(x, y, hi);
    __half2 hv = *(__half2*)&hi;
    float hx = __low2float(hv), hy = __high2float(hv);
    f16pack2(x - hx, y - hy, lo);
}
__device__ __forceinline__ void ldA_mk(u32* f, u32 base, int stride, int m0, int k0, int lane) {
    int m = m0 + (lane & 15);
    int k = k0 + ((lane >> 4) << 3);
    ldsm4(f[0], f[1], f[2], f[3], base + (u32)((m * stride + k) * 2));
}
__device__ __forceinline__ void ldA_km(u32* f, u32 base, int stride, int k0, int m0, int lane) {
    int k = k0 + (lane & 7) + ((lane >> 4) << 3);
    int m = m0 + (((lane >> 3) & 1) << 3);
    ldsm4t(f[0], f[1], f[2], f[3], base + (u32)((k * stride + m) * 2));
}
__device__ __forceinline__ void ldB_kn(u32* f, u32 base, int stride, int k0, int n0, int lane) {
    int k = k0 + (lane & 7) + (((lane >> 3) & 1) << 3);
    int n = n0 + ((lane >> 4) << 3);
    ldsm4t(f[0], f[1], f[2], f[3], base + (u32)((k * stride + n) * 2));
}
// stage 32(k) x 128(cols) fp32 -> single fp16 [k][136]
__device__ __forceinline__ void stage_km_f16(const float* g, int gstride, char* smH, int t) {
    #pragma unroll
    for (int i = 0; i < 4; i++) {
        int lin = i * 256 + t;
        int kr = lin >> 5, mq = (lin & 31) * 4;
        float4 v = *(const float4*)(g + (size_t)kr * gstride + mq);
        u32 h0, h1;
        f16pack2(v.x, v.y, h0);
        f16pack2(v.z, v.w, h1);
        *(ull*)(smH + (size_t)(kr * 68 + (mq >> 1)) * 4) = (ull)h0 | ((ull)h1 << 32);
    }
}
// stage 32(k) x 128(cols) fp32 -> split bf16 [k][136] hi/lo
__device__ __forceinline__ void stage_km(const float* g, int gstride, char* smH, char* smL, int t) {
    #pragma unroll
    for (int i = 0; i < 4; i++) {
        int lin = i * 256 + t;
        int kr = lin >> 5, mq = (lin & 31) * 4;
        float4 v = *(const float4*)(g + (size_t)kr * gstride + mq);
        u32 h0, l0, h1, l1;
        bf16split2(v.x, v.y, h0, l0);
        bf16split2(v.z, v.w, h1, l1);
        *(ull*)(smH + (size_t)(kr * 68 + (mq >> 1)) * 4) = (ull)h0 | ((ull)h1 << 32);
        *(ull*)(smL + (size_t)(kr * 68 + (mq >> 1)) * 4) = (ull)l0 | ((ull)l1 << 32);
    }
}
// stage 128(m) x 32(k) fp32 -> split bf16 [m][40] hi/lo
__device__ __forceinline__ void stage_mk(const float* g, int gstride, char* smH, char* smL, int t) {
    #pragma unroll
    for (int i = 0; i < 4; i++) {
        int lin = i * 256 + t;
        int mr = lin >> 3, kq = (lin & 7) * 4;
        float4 v = *(const float4*)(g + (size_t)mr * gstride + kq);
        u32 h0, l0, h1, l1;
        bf16split2(v.x, v.y, h0, l0);
        bf16split2(v.z, v.w, h1, l1);
        *(ull*)(smH + (size_t)(mr * 20 + (kq >> 1)) * 4) = (ull)h0 | ((ull)h1 << 32);
        *(ull*)(smL + (size_t)(mr * 20 + (kq >> 1)) * 4) = (ull)l0 | ((ull)l1 << 32);
    }
}

// ---------------- rope inverse-frequency table ----------------
__global__ void init_invf_kernel() {
    int d = threadIdx.x;
    if (d < 32) {
        float e;
        if (d < 10)       e = (float)(2 * (d % 5)) / 10.f;
        else if (d < 20)  e = (float)(2 * ((d - 10) % 5)) / 10.f;
        else              e = (float)(2 * ((d - 20) % 6)) / 12.f;
        g_scr[OFF_INVF + d] = powf(10000.f, -e);
    }
}

// ---------------- fp32 text GEMMs (proven) ----------------
__device__ __forceinline__ void gemm32x64_body(const float* __restrict__ A,
                                               const float* __restrict__ W,
                                               const float* __restrict__ bias,
                                               float* __restrict__ Y,
                                               int K, int N, int act,
                                               int m0, int j0,
                                               float* As, float* Ws) {
    int t = threadIdx.x;
    int tx = t & 15, ty = t >> 4;
    float acc[2][4] = {};
    for (int k0 = 0; k0 < K; k0 += 16) {
        if (t < 128) {
            int m = t >> 2, kq = (t & 3) * 4;
            float4 av = *(const float4*)&A[(size_t)(m0 + m) * K + k0 + kq];
            As[(kq + 0) * 33 + m] = av.x;
            As[(kq + 1) * 33 + m] = av.y;
            As[(kq + 2) * 33 + m] = av.z;
            As[(kq + 3) * 33 + m] = av.w;
        }
        {
            int kk = t >> 4, j4 = (t & 15) * 4;
            *(float4*)&Ws[kk * 64 + j4] = *(const float4*)&W[(size_t)(k0 + kk) * N + j0 + j4];
        }
        __syncthreads();
        #pragma unroll
        for (int kk = 0; kk < 16; kk++) {
            float a0 = As[kk * 33 + ty * 2], a1 = As[kk * 33 + ty * 2 + 1];
            #pragma unroll
            for (int j = 0; j < 4; j++) {
                float w = Ws[kk * 64 + tx + 16 * j];
                acc[0][j] += a0 * w;
                acc[1][j] += a1 * w;
            }
        }
        __syncthreads();
    }
    #pragma unroll
    for (int j = 0; j < 4; j++) {
        int jj = j0 + tx + 16 * j;
        float bv = bias[jj];
        #pragma unroll
        for (int i = 0; i < 2; i++) {
            float v = acc[i][j] + bv;
            if (act) v = 0.5f * v * (1.f + erff(v * 0.70710678118654752f));
            Y[(size_t)(m0 + ty * 2 + i) * N + jj] = v;
        }
    }
}

__global__ void text3_kernel(const float* __restrict__ text,
                             const float* __restrict__ kw, const float* __restrict__ kb,
                             const float* __restrict__ vw, const float* __restrict__ vb,
                             const float* __restrict__ m1w, const float* __restrict__ m1b) {
    __shared__ float As[16 * 33];
    __shared__ float Ws[16 * 64];
    const float *W, *bias;
    float* Y;
    int act = 0;
    if (blockIdx.z == 0)      { W = kw;  bias = kb;  Y = g_scr + OFF_KRAW; }
    else if (blockIdx.z == 1) { W = vw;  bias = vb;  Y = g_scr + OFF_VRAW; }
    else                      { W = m1w; bias = m1b; Y = g_scr + OFF_H1; act = 1; }
    gemm32x64_body(text, W, bias, Y, 512, 256, act, blockIdx.y * 32, blockIdx.x * 64, As, Ws);
}

__global__ void phase_gemm_kernel(const float* __restrict__ m2w, const float* __restrict__ m2b) {
    __shared__ float As[16 * 33];
    __shared__ float Ws[16 * 64];
    gemm32x64_body(g_scr + OFF_H1, m2w, m2b, g_scr + OFF_PHASE, 256, 256, 0,
                   blockIdx.y * 32, blockIdx.x * 64, As, Ws);
}

// ---------------- text rope: krot -> [b,h][d][s], vt -> [b,h][s][d] ----------------
__global__ void text_rope_kernel() {
    int idx = blockIdx.x * blockDim.x + threadIdx.x;  // < 65536
    int p = idx & 15;
    int h = (idx >> 4) & 7;
    int s = (idx >> 7) & 255;
    int b = idx >> 15;
    const float* kraw = g_scr + OFF_KRAW;
    const float* vraw = g_scr + OFF_VRAW;
    const float* ph   = g_scr + OFF_PHASE;
    float* krot = g_scr + OFF_KROT;
    float* vt   = g_scr + OFF_VT;
    int base = (b * SS + s) * CC + h * HDIM;
    int bh = b * NHD + h;
    float k0 = kraw[base + p], k1 = kraw[base + p + 16];
    float p0 = ph[base + p],   p1 = ph[base + p + 16];
    float c0, s0, c1, s1;
    __sincosf(p0, &s0, &c0);
    __sincosf(p1, &s1, &c1);
    krot[(bh * HDIM + p) * SS + s]        = k0 * c0 - k1 * s0;
    krot[(bh * HDIM + p + 16) * SS + s]   = k1 * c1 + k0 * s1;
    vt[(bh * SS + s) * HDIM + p]          = vraw[base + p];
    vt[(bh * SS + s) * HDIM + p + 16]     = vraw[base + p + 16];
}

// ================= Q projection: single-term fp16 mma + fused rope =================
#define QP_AH 0
#define QP_BH 8704
__global__ __launch_bounds__(256, 1) void qproj_mma_kernel(
        const float* __restrict__ A, const float* __restrict__ W,
        const float* __restrict__ bias) {
    __shared__ char sm[17408];
    float* Y = g_scr + OFF_Q;
    const float* invf = g_scr + OFF_INVF;
    int b = blockIdx.z;
    int n0 = blockIdx.y * 128, j0 = blockIdx.x * 128;
    int t = threadIdx.x;
    int w = t >> 5, lane = t & 31;
    int wm = w & 1, wn = w >> 1;
    int mu = lane & 3, r = lane >> 2;
    const float* Ab = A + (size_t)b * CC * NTOK;
    u32 aH = (u32)__cvta_generic_to_shared(sm + QP_AH);
    u32 bH = (u32)__cvta_generic_to_shared(sm + QP_BH);
    float acc[4][4][4] = {};
    for (int k0 = 0; k0 < CC; k0 += 32) {
        stage_km_f16(Ab + (size_t)k0 * NTOK + n0, NTOK, sm + QP_AH, t);
        stage_km_f16(W + (size_t)k0 * CC + j0, CC, sm + QP_BH, t);
        __syncthreads();
        #pragma unroll
        for (int kt = 0; kt < 2; kt++) {
            u32 ah[4][4];
            #pragma unroll
            for (int mt = 0; mt < 4; mt++)
                ldA_km(ah[mt], aH, 136, kt * 16, wm * 64 + mt * 16, lane);
            #pragma unroll
            for (int ng = 0; ng < 2; ng++) {
                u32 bh[4];
                ldB_kn(bh, bH, 136, kt * 16, wn * 32 + ng * 16, lane);
                #pragma unroll
                for (int mt = 0; mt < 4; mt++) {
                    mma_f16(acc[mt][ng * 2],     ah[mt], bh[0], bh[1]);
                    mma_f16(acc[mt][ng * 2 + 1], ah[mt], bh[2], bh[3]);
                }
            }
        }
        __syncthreads();
    }
    // epilogue: bias + rope (MUFU sincos), store fp32 Q
    float blo[2][2], bhi[2][2], fl0[2][2], fl1[2][2];
    int zsel[2][2], xsel[2][2];
    #pragma unroll
    for (int tn = 0; tn < 2; tn++)
        #pragma unroll
        for (int cc = 0; cc < 2; cc++) {
            int d = tn * 8 + 2 * mu + cc;
            blo[tn][cc] = bias[j0 + wn * 32 + d];
            bhi[tn][cc] = bias[j0 + wn * 32 + d + 16];
            fl0[tn][cc] = invf[d];
            fl1[tn][cc] = invf[d + 16];
            zsel[tn][cc] = (d < 10);
            xsel[tn][cc] = (d + 16 >= 20);
        }
    #pragma unroll
    for (int mt = 0; mt < 4; mt++)
        #pragma unroll
        for (int half = 0; half < 2; half++) {
            int n = n0 + wm * 64 + mt * 16 + r + half * 8;
            float wx = (float)(n & 31), hy = (float)((n >> 5) & 31), dz = (float)(n >> 10);
            float* yp = Y + ((size_t)b * NTOK + n) * CC + j0 + wn * 32;
            #pragma unroll
            for (int tn = 0; tn < 2; tn++) {
                float v0[2], v1[2];
                #pragma unroll
                for (int cc = 0; cc < 2; cc++) {
                    float q0 = acc[mt][tn][half * 2 + cc] + blo[tn][cc];
                    float q1 = acc[mt][tn + 2][half * 2 + cc] + bhi[tn][cc];
                    float f0 = (zsel[tn][cc] ? dz : hy) * fl0[tn][cc];
                    float f1 = (xsel[tn][cc] ? wx : hy) * fl1[tn][cc];
                    float s0, c0, s1, c1;
                    __sincosf(f0, &s0, &c0);
                    __sincosf(f1, &s1, &c1);
                    v0[cc] = q0 * c0 - q1 * s0;
                    v1[cc] = q1 * c1 + q0 * s1;
                }
                *(float2*)&yp[tn * 8 + 2 * mu]      = make_float2(v0[0], v0[1]);
                *(float2*)&yp[tn * 8 + 2 * mu + 16] = make_float2(v1[0], v1[1]);
            }
        }
}

// ================= attention: QK single-term fp16, PV 3-term fp16 =================
#define AT_QH 0
#define AT_KH 10240
#define AT_VH 27136
#define AT_VL 47616
#define AT_SMEM 68096
__global__ __launch_bounds__(256, 1) void attn_mma_kernel() {
    extern __shared__ char sm[];
    const float* q    = g_scr + OFF_Q;
    const float* krot = g_scr + OFF_KROT;
    const float* vt   = g_scr + OFF_VT;
    float* ao = g_scr + OFF_AO;
    int b = blockIdx.z, h = blockIdx.y;
    int n0 = blockIdx.x * 128;
    int t = threadIdx.x;
    int w = t >> 5, lane = t & 31;
    int mu = lane & 3, r = lane >> 2;
    const float scale = 0.17677669529663687f;
    u32* QHu = (u32*)(sm + AT_QH);
    u32* KHu = (u32*)(sm + AT_KH);
    u32* VHu = (u32*)(sm + AT_VH);
    u32* VLu = (u32*)(sm + AT_VL);
    // stage Q (x scale) single fp16
    #pragma unroll
    for (int i = 0; i < 8; i++) {
        int lin = i * 256 + t;
        int row = lin >> 4, dp = lin & 15;
        float2 v = *(const float2*)&q[((size_t)b * NTOK + n0 + row) * CC + h * HDIM + dp * 2];
        u32 hh;
        f16pack2(v.x * scale, v.y * scale, hh);
        QHu[row * 20 + dp] = hh;
    }
    // stage K [d][s] single fp16
    size_t kb = (size_t)(b * NHD + h) * HDIM * SS;
    #pragma unroll
    for (int i = 0; i < 16; i++) {
        int lin = i * 256 + t;
        int d = lin >> 7, sp = lin & 127;
        float2 v = *(const float2*)&krot[kb + (size_t)d * SS + sp * 2];
        u32 hh;
        f16pack2(v.x, v.y, hh);
        KHu[d * 132 + sp] = hh;
    }
    // stage V [s][d] fp16 hi/lo
    size_t vb = (size_t)(b * NHD + h) * SS * HDIM;
    #pragma unroll
    for (int i = 0; i < 16; i++) {
        int lin = i * 256 + t;
        int s = lin >> 4, dp = lin & 15;
        float2 v = *(const float2*)&vt[vb + (size_t)s * HDIM + dp * 2];
        u32 hh, ll;
        f16split2(v.x, v.y, hh, ll);
        VHu[s * 20 + dp] = hh;
        VLu[s * 20 + dp] = ll;
    }
    __syncthreads();
    u32 aQH = (u32)__cvta_generic_to_shared(sm + AT_QH);
    u32 aKH = (u32)__cvta_generic_to_shared(sm + AT_KH);
    u32 aVH = (u32)__cvta_generic_to_shared(sm + AT_VH);
    u32 aVL = (u32)__cvta_generic_to_shared(sm + AT_VL);
    // QK^T single-term fp16
    float acc[32][4];
    #pragma unroll
    for (int i = 0; i < 32; i++)
        #pragma unroll
        for (int j = 0; j < 4; j++) acc[i][j] = 0.f;
    #pragma unroll
    for (int kt = 0; kt < 2; kt++) {
        u32 qh[4];
        ldA_mk(qh, aQH, 40, w * 16, kt * 16, lane);
        #pragma unroll
        for (int sg = 0; sg < 16; sg++) {
            u32 kh[4];
            ldB_kn(kh, aKH, 264, kt * 16, sg * 16, lane);
            mma_f16(acc[sg * 2],     qh, kh[0], kh[1]);
            mma_f16(acc[sg * 2 + 1], qh, kh[2], kh[3]);
        }
    }
    // softmax in registers
    float mx0 = -CUDART_INF_F, mx1 = -CUDART_INF_F;
    #pragma unroll
    for (int i = 0; i < 32; i++) {
        mx0 = fmaxf(mx0, fmaxf(acc[i][0], acc[i][1]));
        mx1 = fmaxf(mx1, fmaxf(acc[i][2], acc[i][3]));
    }
    mx0 = fmaxf(mx0, __shfl_xor_sync(0xffffffffu, mx0, 1));
    mx0 = fmaxf(mx0, __shfl_xor_sync(0xffffffffu, mx0, 2));
    mx1 = fmaxf(mx1, __shfl_xor_sync(0xffffffffu, mx1, 1));
    mx1 = fmaxf(mx1, __shfl_xor_sync(0xffffffffu, mx1, 2));
    float sum0 = 0.f, sum1 = 0.f;
    #pragma unroll
    for (int i = 0; i < 32; i++) {
        acc[i][0] = __expf(acc[i][0] - mx0);
        acc[i][1] = __expf(acc[i][1] - mx0);
        acc[i][2] = __expf(acc[i][2] - mx1);
        acc[i][3] = __expf(acc[i][3] - mx1);
        sum0 += acc[i][0] + acc[i][1];
        sum1 += acc[i][2] + acc[i][3];
    }
    sum0 += __shfl_xor_sync(0xffffffffu, sum0, 1);
    sum0 += __shfl_xor_sync(0xffffffffu, sum0, 2);
    sum1 += __shfl_xor_sync(0xffffffffu, sum1, 1);
    sum1 += __shfl_xor_sync(0xffffffffu, sum1, 2);
    float zi0 = 1.f / sum0, zi1 = 1.f / sum1;
    // PV 3-term fp16 (P split hi/lo in register, V split hi/lo in smem)
    float oacc[4][4] = {};
    #pragma unroll
    for (int kt = 0; kt < 16; kt++) {
        u32 ah[4], al[4];
        f16split2(acc[2 * kt][0],     acc[2 * kt][1],     ah[0], al[0]);
        f16split2(acc[2 * kt][2],     acc[2 * kt][3],     ah[1], al[1]);
        f16split2(acc[2 * kt + 1][0], acc[2 * kt + 1][1], ah[2], al[2]);
        f16split2(acc[2 * kt + 1][2], acc[2 * kt + 1][3], ah[3], al[3]);
        u32 vh[2][4], vl[2][4];
        ldB_kn(vh[0], aVH, 40, kt * 16, 0, lane);
        ldB_kn(vl[0], aVL, 40, kt * 16, 0, lane);
        ldB_kn(vh[1], aVH, 40, kt * 16, 16, lane);
        ldB_kn(vl[1], aVL, 40, kt * 16, 16, lane);
        #pragma unroll
        for (int dg = 0; dg < 2; dg++) {
            mma_f16(oacc[dg * 2],     ah, vh[dg][0], vh[dg][1]);
            mma_f16(oacc[dg * 2 + 1], ah, vh[dg][2], vh[dg][3]);
        }
        #pragma unroll
        for (int dg = 0; dg < 2; dg++) {
            mma_f16(oacc[dg * 2],     ah, vl[dg][0], vl[dg][1]);
            mma_f16(oacc[dg * 2 + 1], ah, vl[dg][2], vl[dg][3]);
        }
        #pragma unroll
        for (int dg = 0; dg < 2; dg++) {
            mma_f16(oacc[dg * 2],     al, vh[dg][0], vh[dg][1]);
            mma_f16(oacc[dg * 2 + 1], al, vh[dg][2], vh[dg][3]);
        }
    }
    #pragma unroll
    for (int dt = 0; dt < 4; dt++) {
        int dcol = dt * 8 + 2 * mu;
        size_t r0 = ((size_t)b * NTOK + n0 + w * 16 + r) * CC + h * HDIM + dcol;
        size_t r1 = ((size_t)b * NTOK + n0 + w * 16 + r + 8) * CC + h * HDIM + dcol;
        *(float2*)&ao[r0] = make_float2(oacc[dt][0] * zi0, oacc[dt][1] * zi0);
        *(float2*)&ao[r1] = make_float2(oacc[dt][2] * zi1, oacc[dt][3] * zi1);
    }
}

// ================= O projection (bf16 3-term, proven) + transpose =================
#define OP_AH 0
#define OP_AL 10240
#define OP_BH 20480
#define OP_BL 29184
#define OP_SMEM 67584
__global__ __launch_bounds__(256, 1) void oproj_mma_kernel(
        const float* __restrict__ W, const float* __restrict__ bias,
        float* __restrict__ Out) {
    extern __shared__ char sm[];
    const float* Ain = g_scr + OFF_AO;
    int b = blockIdx.z;
    int n0 = blockIdx.y * 128, j0 = blockIdx.x * 128;
    int t = threadIdx.x;
    int w = t >> 5, lane = t & 31;
    int wm = w & 1, wn = w >> 1;
    int mu = lane & 3, r = lane >> 2;
    u32 aH = (u32)__cvta_generic_to_shared(sm + OP_AH);
    u32 aL = (u32)__cvta_generic_to_shared(sm + OP_AL);
    u32 bH = (u32)__cvta_generic_to_shared(sm + OP_BH);
    u32 bL = (u32)__cvta_generic_to_shared(sm + OP_BL);
    float acc[4][4][4] = {};
    for (int k0 = 0; k0 < CC; k0 += 32) {
        stage_mk(Ain + ((size_t)b * NTOK + n0) * CC + k0, CC, sm + OP_AH, sm + OP_AL, t);
        stage_km(W + (size_t)k0 * CC + j0, CC, sm + OP_BH, sm + OP_BL, t);
        __syncthreads();
        #pragma unroll
        for (int kt = 0; kt < 2; kt++) {
            u32 ah[4][4], al[4][4];
            #pragma unroll
            for (int mt = 0; mt < 4; mt++) {
                ldA_mk(ah[mt], aH, 40, wm * 64 + mt * 16, kt * 16, lane);
                ldA_mk(al[mt], aL, 40, wm * 64 + mt * 16, kt * 16, lane);
            }
            #pragma unroll
            for (int ng = 0; ng < 2; ng++) {
                u32 bh[4], bl[4];
                ldB_kn(bh, bH, 136, kt * 16, wn * 32 + ng * 16, lane);
                ldB_kn(bl, bL, 136, kt * 16, wn * 32 + ng * 16, lane);
                #pragma unroll
                for (int mt = 0; mt < 4; mt++) {
                    mma_bf16(acc[mt][ng * 2],     ah[mt], bh[0], bh[1]);
                    mma_bf16(acc[mt][ng * 2 + 1], ah[mt], bh[2], bh[3]);
                }
                #pragma unroll
                for (int mt = 0; mt < 4; mt++) {
                    mma_bf16(acc[mt][ng * 2],     ah[mt], bl[0], bl[1]);
                    mma_bf16(acc[mt][ng * 2 + 1], ah[mt], bl[2], bl[3]);
                }
                #pragma unroll
                for (int mt = 0; mt < 4; mt++) {
                    mma_bf16(acc[mt][ng * 2],     al[mt], bh[0], bh[1]);
                    mma_bf16(acc[mt][ng * 2 + 1], al[mt], bh[2], bh[3]);
                }
            }
        }
        __syncthreads();
    }
    float* Cs = (float*)sm;
    #pragma unroll
    for (int mt = 0; mt < 4; mt++)
        #pragma unroll
        for (int tn = 0; tn < 4; tn++)
            #pragma unroll
            for (int half = 0; half < 2; half++) {
                int ml = wm * 64 + mt * 16 + r + half * 8;
                int jl = wn * 32 + tn * 8 + 2 * mu;
                Cs[jl * 132 + ml]       = acc[mt][tn][half * 2];
                Cs[(jl + 1) * 132 + ml] = acc[mt][tn][half * 2 + 1];
            }
    __syncthreads();
    #pragma unroll
    for (int i = 0; i < 16; i++) {
        int lin = i * 256 + t;
        int j = lin >> 5, mq = (lin & 31) * 4;
        float4 v = *(float4*)&Cs[j * 132 + mq];
        float bv = bias[j0 + j];
        v.x += bv; v.y += bv; v.z += bv; v.w += bv;
        *(float4*)&Out[((size_t)b * CC + j0 + j) * NTOK + n0 + mq] = v;
    }
}

// ---------------- launch ----------------
extern "C" void kernel_launch(void* const* d_in, const int* in_sizes, int n_in,
                              void* d_out, int out_size) {
    const float* fv   = (const float*)d_in[0];
    const float* text = (const float*)d_in[1];
    const float* q_w  = (const float*)d_in[2];
    const float* q_b  = (const float*)d_in[3];
    const float* k_w  = (const float*)d_in[4];
    const float* k_b  = (const float*)d_in[5];
    const float* v_w  = (const float*)d_in[6];
    const float* v_b  = (const float*)d_in[7];
    const float* o_w  = (const float*)d_in[8];
    const float* o_b  = (const float*)d_in[9];
    const float* m1_w = (const float*)d_in[10];
    const float* m1_b = (const float*)d_in[11];
    const float* m2_w = (const float*)d_in[12];
    const float* m2_b = (const float*)d_in[13];
    float* out = (float*)d_out;

    init_invf_kernel<<<1, 32>>>();
    text3_kernel<<<dim3(4, 16, 3), 256>>>(text, k_w, k_b, v_w, v_b, m1_w, m1_b);
    phase_gemm_kernel<<<dim3(4, 16), 256>>>(m2_w, m2_b);
    text_rope_kernel<<<256, 256>>>();

    qproj_mma_kernel<<<dim3(2, 256, 2), 256>>>(fv, q_w, q_b);

    cudaFuncSetAttribute(attn_mma_kernel, cudaFuncAttributeMaxDynamicSharedMemorySize, AT_SMEM);
    attn_mma_kernel<<<dim3(256, 8, 2), 256, AT_SMEM>>>();

    cudaFuncSetAttribute(oproj_mma_kernel, cudaFuncAttributeMaxDynamicSharedMemorySize, OP_SMEM);
    oproj_mma_kernel<<<dim3(2, 256, 2), 256, OP_SMEM>>>(o_w, o_b, out);
}

// round 9
// speedup vs baseline: 5.8519x; 1.0801x over previous
#include <cuda_runtime.h>
#include <cuda_bf16.h>
#include <cuda_fp16.h>
#include <math.h>
#include <math_constants.h>

#define BB    2
#define CC    256
#define NTOK  32768
#define SS    256
#define TDIM  512
#define NHD   8
#define HDIM  32

typedef unsigned u32;
typedef unsigned long long ull;

// ---------------- scratch ----------------
#define OFF_H1    0
#define OFF_KRAW  (OFF_H1   + 131072)
#define OFF_VRAW  (OFF_KRAW + 131072)
#define OFF_PHASE (OFF_VRAW + 131072)
#define OFF_KROT  (OFF_PHASE+ 131072)      // fp32 [b,h][d=32][s=256]
#define OFF_VT    (OFF_KROT + 131072)      // fp32 [b,h][s=256][d=32]
#define OFF_Q     (OFF_VT   + 131072)      // fp16x2 u32 [b][n][128] (scale folded)
#define OFF_AO    (OFF_Q    + 16777216)    // AOH u32 [b][n][128] ; AOL at +8388608
#define OFF_INVF  (OFF_AO   + 16777216)
#define SCR_TOTAL (OFF_INVF + 32)
__device__ float g_scr[SCR_TOTAL];
#define AOL_DELTA 8388608

// ---------------- helpers ----------------
__device__ __forceinline__ void ldsm4(u32& r0, u32& r1, u32& r2, u32& r3, u32 addr) {
    asm volatile("ldmatrix.sync.aligned.m8n8.x4.shared.b16 {%0,%1,%2,%3}, [%4];"
                 : "=r"(r0), "=r"(r1), "=r"(r2), "=r"(r3) : "r"(addr));
}
__device__ __forceinline__ void ldsm4t(u32& r0, u32& r1, u32& r2, u32& r3, u32 addr) {
    asm volatile("ldmatrix.sync.aligned.m8n8.x4.trans.shared.b16 {%0,%1,%2,%3}, [%4];"
                 : "=r"(r0), "=r"(r1), "=r"(r2), "=r"(r3) : "r"(addr));
}
__device__ __forceinline__ void mma_f16(float* d, const u32* a, u32 b0, u32 b1) {
    asm volatile("mma.sync.aligned.m16n8k16.row.col.f32.f16.f16.f32 "
                 "{%0,%1,%2,%3}, {%4,%5,%6,%7}, {%8,%9}, {%0,%1,%2,%3};"
                 : "+f"(d[0]), "+f"(d[1]), "+f"(d[2]), "+f"(d[3])
                 : "r"(a[0]), "r"(a[1]), "r"(a[2]), "r"(a[3]), "r"(b0), "r"(b1));
}
// fp16 pack (x -> low half, y -> high half)
__device__ __forceinline__ void f16pack2(float x, float y, u32& h) {
    asm("cvt.rn.f16x2.f32 %0, %1, %2;" : "=r"(h) : "f"(y), "f"(x));
}
// fp16 hi/lo split of (x,y)
__device__ __forceinline__ void f16split2(float x, float y, u32& hi, u32& lo) {
    f16pack2(x, y, hi);
    __half2 hv = *(__half2*)&hi;
    float hx = __low2float(hv), hy = __high2float(hv);
    f16pack2(x - hx, y - hy, lo);
}
__device__ __forceinline__ void ldA_mk(u32* f, u32 base, int stride, int m0, int k0, int lane) {
    int m = m0 + (lane & 15);
    int k = k0 + ((lane >> 4) << 3);
    ldsm4(f[0], f[1], f[2], f[3], base + (u32)((m * stride + k) * 2));
}
__device__ __forceinline__ void ldA_km(u32* f, u32 base, int stride, int k0, int m0, int lane) {
    int k = k0 + (lane & 7) + ((lane >> 4) << 3);
    int m = m0 + (((lane >> 3) & 1) << 3);
    ldsm4t(f[0], f[1], f[2], f[3], base + (u32)((k * stride + m) * 2));
}
__device__ __forceinline__ void ldB_kn(u32* f, u32 base, int stride, int k0, int n0, int lane) {
    int k = k0 + (lane & 7) + (((lane >> 3) & 1) << 3);
    int n = n0 + ((lane >> 4) << 3);
    ldsm4t(f[0], f[1], f[2], f[3], base + (u32)((k * stride + n) * 2));
}
// stage 32(k) x 128(cols) fp32 -> single fp16 [k][136]
__device__ __forceinline__ void stage_km_f16(const float* g, int gstride, char* smH, int t) {
    #pragma unroll
    for (int i = 0; i < 4; i++) {
        int lin = i * 256 + t;
        int kr = lin >> 5, mq = (lin & 31) * 4;
        float4 v = *(const float4*)(g + (size_t)kr * gstride + mq);
        u32 h0, h1;
        f16pack2(v.x, v.y, h0);
        f16pack2(v.z, v.w, h1);
        *(ull*)(smH + (size_t)(kr * 68 + (mq >> 1)) * 4) = (ull)h0 | ((ull)h1 << 32);
    }
}

// ---------------- rope inverse-frequency table ----------------
__global__ void init_invf_kernel() {
    int d = threadIdx.x;
    if (d < 32) {
        float e;
        if (d < 10)       e = (float)(2 * (d % 5)) / 10.f;
        else if (d < 20)  e = (float)(2 * ((d - 10) % 5)) / 10.f;
        else              e = (float)(2 * ((d - 20) % 6)) / 12.f;
        g_scr[OFF_INVF + d] = powf(10000.f, -e);
    }
}

// ---------------- fp32 text GEMMs (proven) ----------------
__device__ __forceinline__ void gemm32x64_body(const float* __restrict__ A,
                                               const float* __restrict__ W,
                                               const float* __restrict__ bias,
                                               float* __restrict__ Y,
                                               int K, int N, int act,
                                               int m0, int j0,
                                               float* As, float* Ws) {
    int t = threadIdx.x;
    int tx = t & 15, ty = t >> 4;
    float acc[2][4] = {};
    for (int k0 = 0; k0 < K; k0 += 16) {
        if (t < 128) {
            int m = t >> 2, kq = (t & 3) * 4;
            float4 av = *(const float4*)&A[(size_t)(m0 + m) * K + k0 + kq];
            As[(kq + 0) * 33 + m] = av.x;
            As[(kq + 1) * 33 + m] = av.y;
            As[(kq + 2) * 33 + m] = av.z;
            As[(kq + 3) * 33 + m] = av.w;
        }
        {
            int kk = t >> 4, j4 = (t & 15) * 4;
            *(float4*)&Ws[kk * 64 + j4] = *(const float4*)&W[(size_t)(k0 + kk) * N + j0 + j4];
        }
        __syncthreads();
        #pragma unroll
        for (int kk = 0; kk < 16; kk++) {
            float a0 = As[kk * 33 + ty * 2], a1 = As[kk * 33 + ty * 2 + 1];
            #pragma unroll
            for (int j = 0; j < 4; j++) {
                float w = Ws[kk * 64 + tx + 16 * j];
                acc[0][j] += a0 * w;
                acc[1][j] += a1 * w;
            }
        }
        __syncthreads();
    }
    #pragma unroll
    for (int j = 0; j < 4; j++) {
        int jj = j0 + tx + 16 * j;
        float bv = bias[jj];
        #pragma unroll
        for (int i = 0; i < 2; i++) {
            float v = acc[i][j] + bv;
            if (act) v = 0.5f * v * (1.f + erff(v * 0.70710678118654752f));
            Y[(size_t)(m0 + ty * 2 + i) * N + jj] = v;
        }
    }
}

__global__ void text3_kernel(const float* __restrict__ text,
                             const float* __restrict__ kw, const float* __restrict__ kb,
                             const float* __restrict__ vw, const float* __restrict__ vb,
                             const float* __restrict__ m1w, const float* __restrict__ m1b) {
    __shared__ float As[16 * 33];
    __shared__ float Ws[16 * 64];
    const float *W, *bias;
    float* Y;
    int act = 0;
    if (blockIdx.z == 0)      { W = kw;  bias = kb;  Y = g_scr + OFF_KRAW; }
    else if (blockIdx.z == 1) { W = vw;  bias = vb;  Y = g_scr + OFF_VRAW; }
    else                      { W = m1w; bias = m1b; Y = g_scr + OFF_H1; act = 1; }
    gemm32x64_body(text, W, bias, Y, 512, 256, act, blockIdx.y * 32, blockIdx.x * 64, As, Ws);
}

__global__ void phase_gemm_kernel(const float* __restrict__ m2w, const float* __restrict__ m2b) {
    __shared__ float As[16 * 33];
    __shared__ float Ws[16 * 64];
    gemm32x64_body(g_scr + OFF_H1, m2w, m2b, g_scr + OFF_PHASE, 256, 256, 0,
                   blockIdx.y * 32, blockIdx.x * 64, As, Ws);
}

// ---------------- text rope: krot -> [b,h][d][s], vt -> [b,h][s][d] ----------------
__global__ void text_rope_kernel() {
    int idx = blockIdx.x * blockDim.x + threadIdx.x;  // < 65536
    int p = idx & 15;
    int h = (idx >> 4) & 7;
    int s = (idx >> 7) & 255;
    int b = idx >> 15;
    const float* kraw = g_scr + OFF_KRAW;
    const float* vraw = g_scr + OFF_VRAW;
    const float* ph   = g_scr + OFF_PHASE;
    float* krot = g_scr + OFF_KROT;
    float* vt   = g_scr + OFF_VT;
    int base = (b * SS + s) * CC + h * HDIM;
    int bh = b * NHD + h;
    float k0 = kraw[base + p], k1 = kraw[base + p + 16];
    float p0 = ph[base + p],   p1 = ph[base + p + 16];
    float c0, s0, c1, s1;
    __sincosf(p0, &s0, &c0);
    __sincosf(p1, &s1, &c1);
    krot[(bh * HDIM + p) * SS + s]        = k0 * c0 - k1 * s0;
    krot[(bh * HDIM + p + 16) * SS + s]   = k1 * c1 + k0 * s1;
    vt[(bh * SS + s) * HDIM + p]          = vraw[base + p];
    vt[(bh * SS + s) * HDIM + p + 16]     = vraw[base + p + 16];
}

// ================= Q projection: single-term fp16 mma + fused rope, fp16 out =================
#define QP_AH 0
#define QP_BH 8704
__global__ __launch_bounds__(256, 1) void qproj_mma_kernel(
        const float* __restrict__ A, const float* __restrict__ W,
        const float* __restrict__ bias) {
    __shared__ char sm[17408];
    u32* qp = (u32*)(g_scr + OFF_Q);
    const float* invf = g_scr + OFF_INVF;
    const float scale = 0.17677669529663687f;
    int b = blockIdx.z;
    int n0 = blockIdx.y * 128, j0 = blockIdx.x * 128;
    int t = threadIdx.x;
    int w = t >> 5, lane = t & 31;
    int wm = w & 1, wn = w >> 1;
    int mu = lane & 3, r = lane >> 2;
    const float* Ab = A + (size_t)b * CC * NTOK;
    u32 aH = (u32)__cvta_generic_to_shared(sm + QP_AH);
    u32 bH = (u32)__cvta_generic_to_shared(sm + QP_BH);
    float acc[4][4][4] = {};
    for (int k0 = 0; k0 < CC; k0 += 32) {
        stage_km_f16(Ab + (size_t)k0 * NTOK + n0, NTOK, sm + QP_AH, t);
        stage_km_f16(W + (size_t)k0 * CC + j0, CC, sm + QP_BH, t);
        __syncthreads();
        #pragma unroll
        for (int kt = 0; kt < 2; kt++) {
            u32 ah[4][4];
            #pragma unroll
            for (int mt = 0; mt < 4; mt++)
                ldA_km(ah[mt], aH, 136, kt * 16, wm * 64 + mt * 16, lane);
            #pragma unroll
            for (int ng = 0; ng < 2; ng++) {
                u32 bh[4];
                ldB_kn(bh, bH, 136, kt * 16, wn * 32 + ng * 16, lane);
                #pragma unroll
                for (int mt = 0; mt < 4; mt++) {
                    mma_f16(acc[mt][ng * 2],     ah[mt], bh[0], bh[1]);
                    mma_f16(acc[mt][ng * 2 + 1], ah[mt], bh[2], bh[3]);
                }
            }
        }
        __syncthreads();
    }
    // epilogue: bias + rope (fp32) then pack fp16 with scale folded
    float blo[2][2], bhi[2][2], fl0[2][2], fl1[2][2];
    int zsel[2][2], xsel[2][2];
    #pragma unroll
    for (int tn = 0; tn < 2; tn++)
        #pragma unroll
        for (int cc = 0; cc < 2; cc++) {
            int d = tn * 8 + 2 * mu + cc;
            blo[tn][cc] = bias[j0 + wn * 32 + d];
            bhi[tn][cc] = bias[j0 + wn * 32 + d + 16];
            fl0[tn][cc] = invf[d];
            fl1[tn][cc] = invf[d + 16];
            zsel[tn][cc] = (d < 10);
            xsel[tn][cc] = (d + 16 >= 20);
        }
    #pragma unroll
    for (int mt = 0; mt < 4; mt++)
        #pragma unroll
        for (int half = 0; half < 2; half++) {
            int n = n0 + wm * 64 + mt * 16 + r + half * 8;
            float wx = (float)(n & 31), hy = (float)((n >> 5) & 31), dz = (float)(n >> 10);
            u32* yp = qp + (size_t)(b * NTOK + n) * 128 + (j0 + wn * 32) / 2;
            #pragma unroll
            for (int tn = 0; tn < 2; tn++) {
                float v0[2], v1[2];
                #pragma unroll
                for (int cc = 0; cc < 2; cc++) {
                    float q0 = acc[mt][tn][half * 2 + cc] + blo[tn][cc];
                    float q1 = acc[mt][tn + 2][half * 2 + cc] + bhi[tn][cc];
                    float f0 = (zsel[tn][cc] ? dz : hy) * fl0[tn][cc];
                    float f1 = (xsel[tn][cc] ? wx : hy) * fl1[tn][cc];
                    float s0, c0, s1, c1;
                    __sincosf(f0, &s0, &c0);
                    __sincosf(f1, &s1, &c1);
                    v0[cc] = (q0 * c0 - q1 * s0) * scale;
                    v1[cc] = (q1 * c1 + q0 * s1) * scale;
                }
                u32 u0, u1;
                f16pack2(v0[0], v0[1], u0);
                f16pack2(v1[0], v1[1], u1);
                yp[tn * 4 + mu]     = u0;
                yp[tn * 4 + mu + 8] = u1;
            }
        }
}

// ================= attention: QK 1-term fp16, PV 2-term fp16, fp16 hi/lo out =================
#define AT_QH 0
#define AT_KH 10240
#define AT_VH 27136
#define AT_SMEM 47616
__global__ __launch_bounds__(256, 1) void attn_mma_kernel() {
    extern __shared__ char sm[];
    const u32* qp = (const u32*)(g_scr + OFF_Q);
    const float* krot = g_scr + OFF_KROT;
    const float* vt   = g_scr + OFF_VT;
    u32* aoh = (u32*)(g_scr + OFF_AO);
    u32* aol = aoh + AOL_DELTA;
    int b = blockIdx.z, h = blockIdx.y;
    int n0 = blockIdx.x * 128;
    int t = threadIdx.x;
    int w = t >> 5, lane = t & 31;
    int mu = lane & 3, r = lane >> 2;
    u32* QHu = (u32*)(sm + AT_QH);
    u32* KHu = (u32*)(sm + AT_KH);
    u32* VHu = (u32*)(sm + AT_VH);
    // stage Q (fp16, scale pre-folded): plain copy
    #pragma unroll
    for (int i = 0; i < 8; i++) {
        int lin = i * 256 + t;
        int row = lin >> 4, dp = lin & 15;
        QHu[row * 20 + dp] = qp[(size_t)(b * NTOK + n0 + row) * 128 + h * 16 + dp];
    }
    // stage K [d][s] single fp16
    size_t kb = (size_t)(b * NHD + h) * HDIM * SS;
    #pragma unroll
    for (int i = 0; i < 16; i++) {
        int lin = i * 256 + t;
        int d = lin >> 7, sp = lin & 127;
        float2 v = *(const float2*)&krot[kb + (size_t)d * SS + sp * 2];
        u32 hh;
        f16pack2(v.x, v.y, hh);
        KHu[d * 132 + sp] = hh;
    }
    // stage V [s][d] single fp16
    size_t vb = (size_t)(b * NHD + h) * SS * HDIM;
    #pragma unroll
    for (int i = 0; i < 16; i++) {
        int lin = i * 256 + t;
        int s = lin >> 4, dp = lin & 15;
        float2 v = *(const float2*)&vt[vb + (size_t)s * HDIM + dp * 2];
        u32 hh;
        f16pack2(v.x, v.y, hh);
        VHu[s * 20 + dp] = hh;
    }
    __syncthreads();
    u32 aQH = (u32)__cvta_generic_to_shared(sm + AT_QH);
    u32 aKH = (u32)__cvta_generic_to_shared(sm + AT_KH);
    u32 aVH = (u32)__cvta_generic_to_shared(sm + AT_VH);
    // QK^T single-term fp16 (scale already folded into Q)
    float acc[32][4];
    #pragma unroll
    for (int i = 0; i < 32; i++)
        #pragma unroll
        for (int j = 0; j < 4; j++) acc[i][j] = 0.f;
    #pragma unroll
    for (int kt = 0; kt < 2; kt++) {
        u32 qh[4];
        ldA_mk(qh, aQH, 40, w * 16, kt * 16, lane);
        #pragma unroll
        for (int sg = 0; sg < 16; sg++) {
            u32 kh[4];
            ldB_kn(kh, aKH, 264, kt * 16, sg * 16, lane);
            mma_f16(acc[sg * 2],     qh, kh[0], kh[1]);
            mma_f16(acc[sg * 2 + 1], qh, kh[2], kh[3]);
        }
    }
    // softmax in registers
    float mx0 = -CUDART_INF_F, mx1 = -CUDART_INF_F;
    #pragma unroll
    for (int i = 0; i < 32; i++) {
        mx0 = fmaxf(mx0, fmaxf(acc[i][0], acc[i][1]));
        mx1 = fmaxf(mx1, fmaxf(acc[i][2], acc[i][3]));
    }
    mx0 = fmaxf(mx0, __shfl_xor_sync(0xffffffffu, mx0, 1));
    mx0 = fmaxf(mx0, __shfl_xor_sync(0xffffffffu, mx0, 2));
    mx1 = fmaxf(mx1, __shfl_xor_sync(0xffffffffu, mx1, 1));
    mx1 = fmaxf(mx1, __shfl_xor_sync(0xffffffffu, mx1, 2));
    float sum0 = 0.f, sum1 = 0.f;
    #pragma unroll
    for (int i = 0; i < 32; i++) {
        acc[i][0] = __expf(acc[i][0] - mx0);
        acc[i][1] = __expf(acc[i][1] - mx0);
        acc[i][2] = __expf(acc[i][2] - mx1);
        acc[i][3] = __expf(acc[i][3] - mx1);
        sum0 += acc[i][0] + acc[i][1];
        sum1 += acc[i][2] + acc[i][3];
    }
    sum0 += __shfl_xor_sync(0xffffffffu, sum0, 1);
    sum0 += __shfl_xor_sync(0xffffffffu, sum0, 2);
    sum1 += __shfl_xor_sync(0xffffffffu, sum1, 1);
    sum1 += __shfl_xor_sync(0xffffffffu, sum1, 2);
    float zi0 = 1.f / sum0, zi1 = 1.f / sum1;
    // PV 2-term fp16: P hi/lo (register), V single
    float oacc[4][4] = {};
    #pragma unroll
    for (int kt = 0; kt < 16; kt++) {
        u32 ah[4], al[4];
        f16split2(acc[2 * kt][0],     acc[2 * kt][1],     ah[0], al[0]);
        f16split2(acc[2 * kt][2],     acc[2 * kt][3],     ah[1], al[1]);
        f16split2(acc[2 * kt + 1][0], acc[2 * kt + 1][1], ah[2], al[2]);
        f16split2(acc[2 * kt + 1][2], acc[2 * kt + 1][3], ah[3], al[3]);
        u32 vh[2][4];
        ldB_kn(vh[0], aVH, 40, kt * 16, 0, lane);
        ldB_kn(vh[1], aVH, 40, kt * 16, 16, lane);
        #pragma unroll
        for (int dg = 0; dg < 2; dg++) {
            mma_f16(oacc[dg * 2],     ah, vh[dg][0], vh[dg][1]);
            mma_f16(oacc[dg * 2 + 1], ah, vh[dg][2], vh[dg][3]);
        }
        #pragma unroll
        for (int dg = 0; dg < 2; dg++) {
            mma_f16(oacc[dg * 2],     al, vh[dg][0], vh[dg][1]);
            mma_f16(oacc[dg * 2 + 1], al, vh[dg][2], vh[dg][3]);
        }
    }
    // output: AO as fp16 hi/lo pairs
    #pragma unroll
    for (int dt = 0; dt < 4; dt++) {
        size_t i0 = (size_t)(b * NTOK + n0 + w * 16 + r) * 128 + h * 16 + dt * 4 + mu;
        size_t i1 = (size_t)(b * NTOK + n0 + w * 16 + r + 8) * 128 + h * 16 + dt * 4 + mu;
        u32 hh, ll;
        f16split2(oacc[dt][0] * zi0, oacc[dt][1] * zi0, hh, ll);
        aoh[i0] = hh; aol[i0] = ll;
        f16split2(oacc[dt][2] * zi1, oacc[dt][3] * zi1, hh, ll);
        aoh[i1] = hh; aol[i1] = ll;
    }
}

// ================= O projection: 2-term fp16 (A compensated) + transpose =================
#define OP_AH 0
#define OP_AL 10240
#define OP_BH 20480
#define OP_SMEM 67584
__global__ __launch_bounds__(256, 1) void oproj_mma_kernel(
        const float* __restrict__ W, const float* __restrict__ bias,
        float* __restrict__ Out) {
    extern __shared__ char sm[];
    const u32* aoh = (const u32*)(g_scr + OFF_AO);
    const u32* aol = aoh + AOL_DELTA;
    int b = blockIdx.z;
    int n0 = blockIdx.y * 128, j0 = blockIdx.x * 128;
    int t = threadIdx.x;
    int w = t >> 5, lane = t & 31;
    int wm = w & 1, wn = w >> 1;
    int mu = lane & 3, r = lane >> 2;
    u32* AHs = (u32*)(sm + OP_AH);
    u32* ALs = (u32*)(sm + OP_AL);
    u32 aH = (u32)__cvta_generic_to_shared(sm + OP_AH);
    u32 aL = (u32)__cvta_generic_to_shared(sm + OP_AL);
    u32 bH = (u32)__cvta_generic_to_shared(sm + OP_BH);
    float acc[4][4][4] = {};
    for (int k0 = 0; k0 < CC; k0 += 32) {
        // A: plain u32 copies from AO hi/lo (already fp16)
        #pragma unroll
        for (int i = 0; i < 8; i++) {
            int lin = i * 256 + t;
            int m = lin >> 4, j = lin & 15;
            size_t gidx = (size_t)(b * NTOK + n0 + m) * 128 + (k0 >> 1) + j;
            AHs[m * 20 + j] = aoh[gidx];
            ALs[m * 20 + j] = aol[gidx];
        }
        stage_km_f16(W + (size_t)k0 * CC + j0, CC, sm + OP_BH, t);
        __syncthreads();
        #pragma unroll
        for (int kt = 0; kt < 2; kt++) {
            u32 ah[4][4], al[4][4];
            #pragma unroll
            for (int mt = 0; mt < 4; mt++) {
                ldA_mk(ah[mt], aH, 40, wm * 64 + mt * 16, kt * 16, lane);
                ldA_mk(al[mt], aL, 40, wm * 64 + mt * 16, kt * 16, lane);
            }
            #pragma unroll
            for (int ng = 0; ng < 2; ng++) {
                u32 bh[4];
                ldB_kn(bh, bH, 136, kt * 16, wn * 32 + ng * 16, lane);
                #pragma unroll
                for (int mt = 0; mt < 4; mt++) {
                    mma_f16(acc[mt][ng * 2],     ah[mt], bh[0], bh[1]);
                    mma_f16(acc[mt][ng * 2 + 1], ah[mt], bh[2], bh[3]);
                }
                #pragma unroll
                for (int mt = 0; mt < 4; mt++) {
                    mma_f16(acc[mt][ng * 2],     al[mt], bh[0], bh[1]);
                    mma_f16(acc[mt][ng * 2 + 1], al[mt], bh[2], bh[3]);
                }
            }
        }
        __syncthreads();
    }
    float* Cs = (float*)sm;
    #pragma unroll
    for (int mt = 0; mt < 4; mt++)
        #pragma unroll
        for (int tn = 0; tn < 4; tn++)
            #pragma unroll
            for (int half = 0; half < 2; half++) {
                int ml = wm * 64 + mt * 16 + r + half * 8;
                int jl = wn * 32 + tn * 8 + 2 * mu;
                Cs[jl * 132 + ml]       = acc[mt][tn][half * 2];
                Cs[(jl + 1) * 132 + ml] = acc[mt][tn][half * 2 + 1];
            }
    __syncthreads();
    #pragma unroll
    for (int i = 0; i < 16; i++) {
        int lin = i * 256 + t;
        int j = lin >> 5, mq = (lin & 31) * 4;
        float4 v = *(float4*)&Cs[j * 132 + mq];
        float bv = bias[j0 + j];
        v.x += bv; v.y += bv; v.z += bv; v.w += bv;
        *(float4*)&Out[((size_t)b * CC + j0 + j) * NTOK + n0 + mq] = v;
    }
}

// ---------------- launch ----------------
extern "C" void kernel_launch(void* const* d_in, const int* in_sizes, int n_in,
                              void* d_out, int out_size) {
    const float* fv   = (const float*)d_in[0];
    const float* text = (const float*)d_in[1];
    const float* q_w  = (const float*)d_in[2];
    const float* q_b  = (const float*)d_in[3];
    const float* k_w  = (const float*)d_in[4];
    const float* k_b  = (const float*)d_in[5];
    const float* v_w  = (const float*)d_in[6];
    const float* v_b  = (const float*)d_in[7];
    const float* o_w  = (const float*)d_in[8];
    const float* o_b  = (const float*)d_in[9];
    const float* m1_w = (const float*)d_in[10];
    const float* m1_b = (const float*)d_in[11];
    const float* m2_w = (const float*)d_in[12];
    const float* m2_b = (const float*)d_in[13];
    float* out = (float*)d_out;

    init_invf_kernel<<<1, 32>>>();
    text3_kernel<<<dim3(4, 16, 3), 256>>>(text, k_w, k_b, v_w, v_b, m1_w, m1_b);
    phase_gemm_kernel<<<dim3(4, 16), 256>>>(m2_w, m2_b);
    text_rope_kernel<<<256, 256>>>();

    qproj_mma_kernel<<<dim3(2, 256, 2), 256>>>(fv, q_w, q_b);

    cudaFuncSetAttribute(attn_mma_kernel, cudaFuncAttributeMaxDynamicSharedMemorySize, AT_SMEM);
    attn_mma_kernel<<<dim3(256, 8, 2), 256, AT_SMEM>>>();

    cudaFuncSetAttribute(oproj_mma_kernel, cudaFuncAttributeMaxDynamicSharedMemorySize, OP_SMEM);
    oproj_mma_kernel<<<dim3(2, 256, 2), 256, OP_SMEM>>>(o_w, o_b, out);
}

// round 10
// speedup vs baseline: 6.3894x; 1.0918x over previous
#include <cuda_runtime.h>
#include <cuda_bf16.h>
#include <cuda_fp16.h>
#include <math.h>
#include <math_constants.h>

#define BB    2
#define CC    256
#define NTOK  32768
#define SS    256
#define TDIM  512
#define NHD   8
#define HDIM  32

typedef unsigned u32;
typedef unsigned long long ull;

// ---------------- scratch ----------------
#define OFF_H1    0
#define OFF_KRAW  (OFF_H1   + 131072)
#define OFF_VRAW  (OFF_KRAW + 131072)
#define OFF_PHASE (OFF_VRAW + 131072)
#define OFF_KROT  (OFF_PHASE+ 131072)      // fp32 [b,h][d=32][s=256]
#define OFF_VT    (OFF_KROT + 131072)      // fp32 [b,h][s=256][d=32]
#define OFF_Q     (OFF_VT   + 131072)      // fp16x2 u32 [b][n][128] (scale*log2e folded)
#define OFF_AO    (OFF_Q    + 16777216)    // AOH u32 [b][n][128] ; AOL at +8388608
#define OFF_INVF  (OFF_AO   + 16777216)
#define SCR_TOTAL (OFF_INVF + 32)
__device__ float g_scr[SCR_TOTAL];
#define AOL_DELTA 8388608

// scale * log2(e), folded into Q so QK scores come out in log2 domain
#define QSCALE (0.17677669529663687f * 1.4426950408889634f)

// ---------------- helpers ----------------
__device__ __forceinline__ void ldsm4(u32& r0, u32& r1, u32& r2, u32& r3, u32 addr) {
    asm volatile("ldmatrix.sync.aligned.m8n8.x4.shared.b16 {%0,%1,%2,%3}, [%4];"
                 : "=r"(r0), "=r"(r1), "=r"(r2), "=r"(r3) : "r"(addr));
}
__device__ __forceinline__ void ldsm4t(u32& r0, u32& r1, u32& r2, u32& r3, u32 addr) {
    asm volatile("ldmatrix.sync.aligned.m8n8.x4.trans.shared.b16 {%0,%1,%2,%3}, [%4];"
                 : "=r"(r0), "=r"(r1), "=r"(r2), "=r"(r3) : "r"(addr));
}
__device__ __forceinline__ void ldsm2t(u32& r0, u32& r1, u32 addr) {
    asm volatile("ldmatrix.sync.aligned.m8n8.x2.trans.shared.b16 {%0,%1}, [%2];"
                 : "=r"(r0), "=r"(r1) : "r"(addr));
}
__device__ __forceinline__ void mma_f16(float* d, const u32* a, u32 b0, u32 b1) {
    asm volatile("mma.sync.aligned.m16n8k16.row.col.f32.f16.f16.f32 "
                 "{%0,%1,%2,%3}, {%4,%5,%6,%7}, {%8,%9}, {%0,%1,%2,%3};"
                 : "+f"(d[0]), "+f"(d[1]), "+f"(d[2]), "+f"(d[3])
                 : "r"(a[0]), "r"(a[1]), "r"(a[2]), "r"(a[3]), "r"(b0), "r"(b1));
}
__device__ __forceinline__ void f16pack2(float x, float y, u32& h) {
    asm("cvt.rn.f16x2.f32 %0, %1, %2;" : "=r"(h) : "f"(y), "f"(x));
}
__device__ __forceinline__ u32 ex2h2(u32 x) {
    u32 d;
    asm("ex2.approx.f16x2 %0, %1;" : "=r"(d) : "r"(x));
    return d;
}
__device__ __forceinline__ void f16split2(float x, float y, u32& hi, u32& lo) {
    f16pack2(x, y, hi);
    __half2 hv = *(__half2*)&hi;
    float hx = __low2float(hv), hy = __high2float(hv);
    f16pack2(x - hx, y - hy, lo);
}
__device__ __forceinline__ void ldA_mk(u32* f, u32 base, int stride, int m0, int k0, int lane) {
    int m = m0 + (lane & 15);
    int k = k0 + ((lane >> 4) << 3);
    ldsm4(f[0], f[1], f[2], f[3], base + (u32)((m * stride + k) * 2));
}
__device__ __forceinline__ void ldA_km(u32* f, u32 base, int stride, int k0, int m0, int lane) {
    int k = k0 + (lane & 7) + ((lane >> 4) << 3);
    int m = m0 + (((lane >> 3) & 1) << 3);
    ldsm4t(f[0], f[1], f[2], f[3], base + (u32)((k * stride + m) * 2));
}
__device__ __forceinline__ void ldB_kn(u32* f, u32 base, int stride, int k0, int n0, int lane) {
    int k = k0 + (lane & 7) + (((lane >> 3) & 1) << 3);
    int n = n0 + ((lane >> 4) << 3);
    ldsm4t(f[0], f[1], f[2], f[3], base + (u32)((k * stride + n) * 2));
}
// stage 32(k) x 128(cols) fp32 -> single fp16 [k][136]
__device__ __forceinline__ void stage_km_f16(const float* g, int gstride, char* smH, int t) {
    #pragma unroll
    for (int i = 0; i < 4; i++) {
        int lin = i * 256 + t;
        int kr = lin >> 5, mq = (lin & 31) * 4;
        float4 v = *(const float4*)(g + (size_t)kr * gstride + mq);
        u32 h0, h1;
        f16pack2(v.x, v.y, h0);
        f16pack2(v.z, v.w, h1);
        *(ull*)(smH + (size_t)(kr * 68 + (mq >> 1)) * 4) = (ull)h0 | ((ull)h1 << 32);
    }
}

// ---------------- rope inverse-frequency table ----------------
__global__ void init_invf_kernel() {
    int d = threadIdx.x;
    if (d < 32) {
        float e;
        if (d < 10)       e = (float)(2 * (d % 5)) / 10.f;
        else if (d < 20)  e = (float)(2 * ((d - 10) % 5)) / 10.f;
        else              e = (float)(2 * ((d - 20) % 6)) / 12.f;
        g_scr[OFF_INVF + d] = powf(10000.f, -e);
    }
}

// ---------------- fp32 text GEMMs ----------------
// mode: 0 = plain store, 1 = gelu store, 2 = scatter to VT [bh][s][d]
__device__ __forceinline__ void gemm32x64_body(const float* __restrict__ A,
                                               const float* __restrict__ W,
                                               const float* __restrict__ bias,
                                               float* __restrict__ Y,
                                               int K, int N, int mode,
                                               int m0, int j0,
                                               float* As, float* Ws) {
    int t = threadIdx.x;
    int tx = t & 15, ty = t >> 4;
    float acc[2][4] = {};
    for (int k0 = 0; k0 < K; k0 += 16) {
        if (t < 128) {
            int m = t >> 2, kq = (t & 3) * 4;
            float4 av = *(const float4*)&A[(size_t)(m0 + m) * K + k0 + kq];
            As[(kq + 0) * 33 + m] = av.x;
            As[(kq + 1) * 33 + m] = av.y;
            As[(kq + 2) * 33 + m] = av.z;
            As[(kq + 3) * 33 + m] = av.w;
        }
        {
            int kk = t >> 4, j4 = (t & 15) * 4;
            *(float4*)&Ws[kk * 64 + j4] = *(const float4*)&W[(size_t)(k0 + kk) * N + j0 + j4];
        }
        __syncthreads();
        #pragma unroll
        for (int kk = 0; kk < 16; kk++) {
            float a0 = As[kk * 33 + ty * 2], a1 = As[kk * 33 + ty * 2 + 1];
            #pragma unroll
            for (int j = 0; j < 4; j++) {
                float w = Ws[kk * 64 + tx + 16 * j];
                acc[0][j] += a0 * w;
                acc[1][j] += a1 * w;
            }
        }
        __syncthreads();
    }
    #pragma unroll
    for (int j = 0; j < 4; j++) {
        int jj = j0 + tx + 16 * j;
        float bv = bias[jj];
        #pragma unroll
        for (int i = 0; i < 2; i++) {
            float v = acc[i][j] + bv;
            int m = m0 + ty * 2 + i;
            if (mode == 1) v = 0.5f * v * (1.f + erff(v * 0.70710678118654752f));
            if (mode == 2) {
                int h = jj >> 5, d = jj & 31;
                int bb = m >> 8, ss = m & 255;
                Y[(size_t)((bb * NHD + h) * SS + ss) * HDIM + d] = v;
            } else {
                Y[(size_t)m * N + jj] = v;
            }
        }
    }
}

__global__ void text3_kernel(const float* __restrict__ text,
                             const float* __restrict__ kw, const float* __restrict__ kb,
                             const float* __restrict__ vw, const float* __restrict__ vb,
                             const float* __restrict__ m1w, const float* __restrict__ m1b) {
    __shared__ float As[16 * 33];
    __shared__ float Ws[16 * 64];
    const float *W, *bias;
    float* Y;
    int mode = 0;
    if (blockIdx.z == 0)      { W = kw;  bias = kb;  Y = g_scr + OFF_KRAW; }
    else if (blockIdx.z == 1) { W = vw;  bias = vb;  Y = g_scr + OFF_VT; mode = 2; }
    else                      { W = m1w; bias = m1b; Y = g_scr + OFF_H1; mode = 1; }
    gemm32x64_body(text, W, bias, Y, 512, 256, mode, blockIdx.y * 32, blockIdx.x * 64, As, Ws);
}

// phase GEMM fused with text rope: computes phase = H1@m2+b, then rotates kraw -> krot
__global__ void phase_rope_kernel(const float* __restrict__ m2w, const float* __restrict__ m2b) {
    __shared__ float As[16 * 33];
    __shared__ float Ws[16 * 64];
    const float* A = g_scr + OFF_H1;
    const float* kraw = g_scr + OFF_KRAW;
    float* krot = g_scr + OFF_KROT;
    int m0 = blockIdx.y * 32, j0 = blockIdx.x * 64;
    int t = threadIdx.x;
    int tx = t & 15, ty = t >> 4;
    float acc[2][4] = {};
    for (int k0 = 0; k0 < 256; k0 += 16) {
        if (t < 128) {
            int m = t >> 2, kq = (t & 3) * 4;
            float4 av = *(const float4*)&A[(size_t)(m0 + m) * 256 + k0 + kq];
            As[(kq + 0) * 33 + m] = av.x;
            As[(kq + 1) * 33 + m] = av.y;
            As[(kq + 2) * 33 + m] = av.z;
            As[(kq + 3) * 33 + m] = av.w;
        }
        {
            int kk = t >> 4, j4 = (t & 15) * 4;
            *(float4*)&Ws[kk * 64 + j4] = *(const float4*)&m2w[(size_t)(k0 + kk) * 256 + j0 + j4];
        }
        __syncthreads();
        #pragma unroll
        for (int kk = 0; kk < 16; kk++) {
            float a0 = As[kk * 33 + ty * 2], a1 = As[kk * 33 + ty * 2 + 1];
            #pragma unroll
            for (int j = 0; j < 4; j++) {
                float w = Ws[kk * 64 + tx + 16 * j];
                acc[0][j] += a0 * w;
                acc[1][j] += a1 * w;
            }
        }
        __syncthreads();
    }
    // epilogue: bias + rope on kraw, write krot [bh][d][s]
    #pragma unroll
    for (int i = 0; i < 2; i++) {
        int m = m0 + ty * 2 + i;
        int bb = m >> 8, ss = m & 255;
        #pragma unroll
        for (int jp = 0; jp < 2; jp++) {
            float p0 = acc[i][jp * 2]     + m2b[j0 + 32 * jp + tx];
            float p1 = acc[i][jp * 2 + 1] + m2b[j0 + 32 * jp + tx + 16];
            int h = (j0 >> 5) + jp;
            int base = m * 256 + h * HDIM + tx;
            float k0v = kraw[base], k1v = kraw[base + 16];
            float c0, s0, c1, s1;
            __sincosf(p0, &s0, &c0);
            __sincosf(p1, &s1, &c1);
            int kbase = ((bb * NHD + h) * HDIM + tx) * SS + ss;
            krot[kbase]            = k0v * c0 - k1v * s0;
            krot[kbase + 16 * SS]  = k1v * c1 + k0v * s1;
        }
    }
}

// ================= Q projection: fp16 mma, A cached in smem, 2 j-panels/block =================
#define QJ_B   69632                      // B region after A[256][136]f16
#define QJ_SMEM (QJ_B + 8704)
__global__ __launch_bounds__(256, 1) void qproj_mma_kernel(
        const float* __restrict__ A, const float* __restrict__ W,
        const float* __restrict__ bias) {
    extern __shared__ char sm[];
    u32* qp = (u32*)(g_scr + OFF_Q);
    const float* invf = g_scr + OFF_INVF;
    int b = blockIdx.z;
    int n0 = blockIdx.y * 128;
    int t = threadIdx.x;
    int w = t >> 5, lane = t & 31;
    int wm = w & 1, wn = w >> 1;
    int mu = lane & 3, r = lane >> 2;
    const float* Ab = A + (size_t)b * CC * NTOK;
    u32 aH = (u32)__cvta_generic_to_shared(sm);
    u32 bH = (u32)__cvta_generic_to_shared(sm + QJ_B);
    // stage FULL A panel [256 k][128 n] as fp16, stride 136 halfs
    #pragma unroll 8
    for (int i = 0; i < 32; i++) {
        int lin = i * 256 + t;
        int kr = lin >> 5, mq = (lin & 31) * 4;
        float4 v = *(const float4*)(Ab + (size_t)kr * NTOK + n0 + mq);
        u32 h0, h1;
        f16pack2(v.x, v.y, h0);
        f16pack2(v.z, v.w, h1);
        *(ull*)(sm + (size_t)(kr * 68 + (mq >> 1)) * 4) = (ull)h0 | ((ull)h1 << 32);
    }
    __syncthreads();
    for (int jp = 0; jp < 2; jp++) {
        int j0 = jp * 128;
        float acc[4][4][4] = {};
        for (int k0 = 0; k0 < CC; k0 += 32) {
            stage_km_f16(W + (size_t)k0 * CC + j0, CC, sm + QJ_B, t);
            __syncthreads();
            #pragma unroll
            for (int kt = 0; kt < 2; kt++) {
                u32 ah[4][4];
                #pragma unroll
                for (int mt = 0; mt < 4; mt++)
                    ldA_km(ah[mt], aH, 136, k0 + kt * 16, wm * 64 + mt * 16, lane);
                #pragma unroll
                for (int ng = 0; ng < 2; ng++) {
                    u32 bh[4];
                    ldB_kn(bh, bH, 136, kt * 16, wn * 32 + ng * 16, lane);
                    #pragma unroll
                    for (int mt = 0; mt < 4; mt++) {
                        mma_f16(acc[mt][ng * 2],     ah[mt], bh[0], bh[1]);
                        mma_f16(acc[mt][ng * 2 + 1], ah[mt], bh[2], bh[3]);
                    }
                }
            }
            __syncthreads();
        }
        // epilogue: bias + rope, pack fp16 with QSCALE folded
        float blo[2][2], bhi[2][2], fl0[2][2], fl1[2][2];
        int zsel[2][2], xsel[2][2];
        #pragma unroll
        for (int tn = 0; tn < 2; tn++)
            #pragma unroll
            for (int cc = 0; cc < 2; cc++) {
                int d = tn * 8 + 2 * mu + cc;
                blo[tn][cc] = bias[j0 + wn * 32 + d];
                bhi[tn][cc] = bias[j0 + wn * 32 + d + 16];
                fl0[tn][cc] = invf[d];
                fl1[tn][cc] = invf[d + 16];
                zsel[tn][cc] = (d < 10);
                xsel[tn][cc] = (d + 16 >= 20);
            }
        #pragma unroll
        for (int mt = 0; mt < 4; mt++)
            #pragma unroll
            for (int half = 0; half < 2; half++) {
                int n = n0 + wm * 64 + mt * 16 + r + half * 8;
                float wx = (float)(n & 31), hy = (float)((n >> 5) & 31), dz = (float)(n >> 10);
                u32* yp = qp + (size_t)(b * NTOK + n) * 128 + (j0 + wn * 32) / 2;
                #pragma unroll
                for (int tn = 0; tn < 2; tn++) {
                    float v0[2], v1[2];
                    #pragma unroll
                    for (int cc = 0; cc < 2; cc++) {
                        float q0 = acc[mt][tn][half * 2 + cc] + blo[tn][cc];
                        float q1 = acc[mt][tn + 2][half * 2 + cc] + bhi[tn][cc];
                        float f0 = (zsel[tn][cc] ? dz : hy) * fl0[tn][cc];
                        float f1 = (xsel[tn][cc] ? wx : hy) * fl1[tn][cc];
                        float s0, c0, s1, c1;
                        __sincosf(f0, &s0, &c0);
                        __sincosf(f1, &s1, &c1);
                        v0[cc] = (q0 * c0 - q1 * s0) * QSCALE;
                        v1[cc] = (q1 * c1 + q0 * s1) * QSCALE;
                    }
                    u32 u0, u1;
                    f16pack2(v0[0], v0[1], u0);
                    f16pack2(v1[0], v1[1], u1);
                    yp[tn * 4 + mu]     = u0;
                    yp[tn * 4 + mu + 8] = u1;
                }
            }
    }
}

// ================= attention: QK fp16, fp16 softmax (ex2.f16x2), PV 1-term + sum-MMA =================
#define AT_QH 0
#define AT_KH 10240
#define AT_VH 27136
#define AT_SMEM 47616
__global__ __launch_bounds__(256, 1) void attn_mma_kernel() {
    extern __shared__ char sm[];
    const u32* qp = (const u32*)(g_scr + OFF_Q);
    const float* krot = g_scr + OFF_KROT;
    const float* vt   = g_scr + OFF_VT;
    u32* aoh = (u32*)(g_scr + OFF_AO);
    u32* aol = aoh + AOL_DELTA;
    int b = blockIdx.z, h = blockIdx.y;
    int n0 = blockIdx.x * 128;
    int t = threadIdx.x;
    int w = t >> 5, lane = t & 31;
    int mu = lane & 3, r = lane >> 2;
    u32* QHu = (u32*)(sm + AT_QH);
    u32* KHu = (u32*)(sm + AT_KH);
    u32* VHu = (u32*)(sm + AT_VH);
    // stage Q (fp16, QSCALE pre-folded): plain copy
    #pragma unroll
    for (int i = 0; i < 8; i++) {
        int lin = i * 256 + t;
        int row = lin >> 4, dp = lin & 15;
        QHu[row * 20 + dp] = qp[(size_t)(b * NTOK + n0 + row) * 128 + h * 16 + dp];
    }
    // stage K [d][s] single fp16
    size_t kb = (size_t)(b * NHD + h) * HDIM * SS;
    #pragma unroll
    for (int i = 0; i < 16; i++) {
        int lin = i * 256 + t;
        int d = lin >> 7, sp = lin & 127;
        float2 v = *(const float2*)&krot[kb + (size_t)d * SS + sp * 2];
        u32 hh;
        f16pack2(v.x, v.y, hh);
        KHu[d * 132 + sp] = hh;
    }
    // stage V [s][d] single fp16; pad cols 32..39: col32 = 1.0 (row-sum trick)
    size_t vb = (size_t)(b * NHD + h) * SS * HDIM;
    #pragma unroll
    for (int i = 0; i < 16; i++) {
        int lin = i * 256 + t;
        int s = lin >> 4, dp = lin & 15;
        float2 v = *(const float2*)&vt[vb + (size_t)s * HDIM + dp * 2];
        u32 hh;
        f16pack2(v.x, v.y, hh);
        VHu[s * 20 + dp] = hh;
    }
    #pragma unroll
    for (int i = 0; i < 4; i++) {
        int lin = i * 256 + t;
        int s = lin >> 2, c = lin & 3;
        VHu[s * 20 + 16 + c] = (c == 0) ? 0x00003C00u : 0u;
    }
    __syncthreads();
    u32 aQH = (u32)__cvta_generic_to_shared(sm + AT_QH);
    u32 aKH = (u32)__cvta_generic_to_shared(sm + AT_KH);
    u32 aVH = (u32)__cvta_generic_to_shared(sm + AT_VH);
    // QK^T single-term fp16 (acc = score * log2e)
    float acc[32][4];
    #pragma unroll
    for (int i = 0; i < 32; i++)
        #pragma unroll
        for (int j = 0; j < 4; j++) acc[i][j] = 0.f;
    #pragma unroll
    for (int kt = 0; kt < 2; kt++) {
        u32 qh[4];
        ldA_mk(qh, aQH, 40, w * 16, kt * 16, lane);
        #pragma unroll
        for (int sg = 0; sg < 16; sg++) {
            u32 kh[4];
            ldB_kn(kh, aKH, 264, kt * 16, sg * 16, lane);
            mma_f16(acc[sg * 2],     qh, kh[0], kh[1]);
            mma_f16(acc[sg * 2 + 1], qh, kh[2], kh[3]);
        }
    }
    // max reduction (log2 domain)
    float mx0 = -CUDART_INF_F, mx1 = -CUDART_INF_F;
    #pragma unroll
    for (int i = 0; i < 32; i++) {
        mx0 = fmaxf(mx0, fmaxf(acc[i][0], acc[i][1]));
        mx1 = fmaxf(mx1, fmaxf(acc[i][2], acc[i][3]));
    }
    mx0 = fmaxf(mx0, __shfl_xor_sync(0xffffffffu, mx0, 1));
    mx0 = fmaxf(mx0, __shfl_xor_sync(0xffffffffu, mx0, 2));
    mx1 = fmaxf(mx1, __shfl_xor_sync(0xffffffffu, mx1, 1));
    mx1 = fmaxf(mx1, __shfl_xor_sync(0xffffffffu, mx1, 2));
    // P = exp2(acc - mx) directly in packed fp16 (these ARE the PV A-fragments)
    u32 p0[32], p1[32];
    #pragma unroll
    for (int i = 0; i < 32; i++) {
        u32 a0, a1;
        f16pack2(acc[i][0] - mx0, acc[i][1] - mx0, a0);
        f16pack2(acc[i][2] - mx1, acc[i][3] - mx1, a1);
        p0[i] = ex2h2(a0);
        p1[i] = ex2h2(a1);
    }
    // PV single-term + row-sum via ones-column MMA
    float oacc[4][4] = {};
    float osum[4] = {};
    #pragma unroll
    for (int kt = 0; kt < 16; kt++) {
        u32 ah[4] = {p0[2 * kt], p1[2 * kt], p0[2 * kt + 1], p1[2 * kt + 1]};
        u32 vh[2][4];
        ldB_kn(vh[0], aVH, 40, kt * 16, 0, lane);
        ldB_kn(vh[1], aVH, 40, kt * 16, 16, lane);
        u32 s0f, s1f;
        ldsm2t(s0f, s1f, aVH + (u32)(((kt * 16 + (lane & 15)) * 40 + 32) * 2));
        mma_f16(oacc[0], ah, vh[0][0], vh[0][1]);
        mma_f16(oacc[1], ah, vh[0][2], vh[0][3]);
        mma_f16(oacc[2], ah, vh[1][0], vh[1][1]);
        mma_f16(oacc[3], ah, vh[1][2], vh[1][3]);
        mma_f16(osum, ah, s0f, s1f);
    }
    float sm0 = __shfl_sync(0xffffffffu, osum[0], lane & ~3);
    float sm1 = __shfl_sync(0xffffffffu, osum[2], lane & ~3);
    float zi0 = 1.f / sm0, zi1 = 1.f / sm1;
    // output: AO as fp16 hi/lo pairs
    #pragma unroll
    for (int dt = 0; dt < 4; dt++) {
        size_t i0 = (size_t)(b * NTOK + n0 + w * 16 + r) * 128 + h * 16 + dt * 4 + mu;
        size_t i1 = (size_t)(b * NTOK + n0 + w * 16 + r + 8) * 128 + h * 16 + dt * 4 + mu;
        u32 hh, ll;
        f16split2(oacc[dt][0] * zi0, oacc[dt][1] * zi0, hh, ll);
        aoh[i0] = hh; aol[i0] = ll;
        f16split2(oacc[dt][2] * zi1, oacc[dt][3] * zi1, hh, ll);
        aoh[i1] = hh; aol[i1] = ll;
    }
}

// ================= O projection: 2-term fp16 (A compensated) + transpose =================
#define OP_AH 0
#define OP_AL 10240
#define OP_BH 20480
#define OP_SMEM 67584
__global__ __launch_bounds__(256, 1) void oproj_mma_kernel(
        const float* __restrict__ W, const float* __restrict__ bias,
        float* __restrict__ Out) {
    extern __shared__ char sm[];
    const u32* aoh = (const u32*)(g_scr + OFF_AO);
    const u32* aol = aoh + AOL_DELTA;
    int b = blockIdx.z;
    int n0 = blockIdx.y * 128, j0 = blockIdx.x * 128;
    int t = threadIdx.x;
    int w = t >> 5, lane = t & 31;
    int wm = w & 1, wn = w >> 1;
    int mu = lane & 3, r = lane >> 2;
    u32* AHs = (u32*)(sm + OP_AH);
    u32* ALs = (u32*)(sm + OP_AL);
    u32 aH = (u32)__cvta_generic_to_shared(sm + OP_AH);
    u32 aL = (u32)__cvta_generic_to_shared(sm + OP_AL);
    u32 bH = (u32)__cvta_generic_to_shared(sm + OP_BH);
    float acc[4][4][4] = {};
    for (int k0 = 0; k0 < CC; k0 += 32) {
        #pragma unroll
        for (int i = 0; i < 8; i++) {
            int lin = i * 256 + t;
            int m = lin >> 4, j = lin & 15;
            size_t gidx = (size_t)(b * NTOK + n0 + m) * 128 + (k0 >> 1) + j;
            AHs[m * 20 + j] = aoh[gidx];
            ALs[m * 20 + j] = aol[gidx];
        }
        stage_km_f16(W + (size_t)k0 * CC + j0, CC, sm + OP_BH, t);
        __syncthreads();
        #pragma unroll
        for (int kt = 0; kt < 2; kt++) {
            u32 ah[4][4], al[4][4];
            #pragma unroll
            for (int mt = 0; mt < 4; mt++) {
                ldA_mk(ah[mt], aH, 40, wm * 64 + mt * 16, kt * 16, lane);
                ldA_mk(al[mt], aL, 40, wm * 64 + mt * 16, kt * 16, lane);
            }
            #pragma unroll
            for (int ng = 0; ng < 2; ng++) {
                u32 bh[4];
                ldB_kn(bh, bH, 136, kt * 16, wn * 32 + ng * 16, lane);
                #pragma unroll
                for (int mt = 0; mt < 4; mt++) {
                    mma_f16(acc[mt][ng * 2],     ah[mt], bh[0], bh[1]);
                    mma_f16(acc[mt][ng * 2 + 1], ah[mt], bh[2], bh[3]);
                }
                #pragma unroll
                for (int mt = 0; mt < 4; mt++) {
                    mma_f16(acc[mt][ng * 2],     al[mt], bh[0], bh[1]);
                    mma_f16(acc[mt][ng * 2 + 1], al[mt], bh[2], bh[3]);
                }
            }
        }
        __syncthreads();
    }
    float* Cs = (float*)sm;
    #pragma unroll
    for (int mt = 0; mt < 4; mt++)
        #pragma unroll
        for (int tn = 0; tn < 4; tn++)
            #pragma unroll
            for (int half = 0; half < 2; half++) {
                int ml = wm * 64 + mt * 16 + r + half * 8;
                int jl = wn * 32 + tn * 8 + 2 * mu;
                Cs[jl * 132 + ml]       = acc[mt][tn][half * 2];
                Cs[(jl + 1) * 132 + ml] = acc[mt][tn][half * 2 + 1];
            }
    __syncthreads();
    #pragma unroll
    for (int i = 0; i < 16; i++) {
        int lin = i * 256 + t;
        int j = lin >> 5, mq = (lin & 31) * 4;
        float4 v = *(float4*)&Cs[j * 132 + mq];
        float bv = bias[j0 + j];
        v.x += bv; v.y += bv; v.z += bv; v.w += bv;
        *(float4*)&Out[((size_t)b * CC + j0 + j) * NTOK + n0 + mq] = v;
    }
}

// ---------------- launch ----------------
extern "C" void kernel_launch(void* const* d_in, const int* in_sizes, int n_in,
                              void* d_out, int out_size) {
    const float* fv   = (const float*)d_in[0];
    const float* text = (const float*)d_in[1];
    const float* q_w  = (const float*)d_in[2];
    const float* q_b  = (const float*)d_in[3];
    const float* k_w  = (const float*)d_in[4];
    const float* k_b  = (const float*)d_in[5];
    const float* v_w  = (const float*)d_in[6];
    const float* v_b  = (const float*)d_in[7];
    const float* o_w  = (const float*)d_in[8];
    const float* o_b  = (const float*)d_in[9];
    const float* m1_w = (const float*)d_in[10];
    const float* m1_b = (const float*)d_in[11];
    const float* m2_w = (const float*)d_in[12];
    const float* m2_b = (const float*)d_in[13];
    float* out = (float*)d_out;

    init_invf_kernel<<<1, 32>>>();
    text3_kernel<<<dim3(4, 16, 3), 256>>>(text, k_w, k_b, v_w, v_b, m1_w, m1_b);
    phase_rope_kernel<<<dim3(4, 16), 256>>>(m2_w, m2_b);

    cudaFuncSetAttribute(qproj_mma_kernel, cudaFuncAttributeMaxDynamicSharedMemorySize, QJ_SMEM);
    qproj_mma_kernel<<<dim3(1, 256, 2), 256, QJ_SMEM>>>(fv, q_w, q_b);

    cudaFuncSetAttribute(attn_mma_kernel, cudaFuncAttributeMaxDynamicSharedMemorySize, AT_SMEM);
    attn_mma_kernel<<<dim3(256, 8, 2), 256, AT_SMEM>>>();

    cudaFuncSetAttribute(oproj_mma_kernel, cudaFuncAttributeMaxDynamicSharedMemorySize, OP_SMEM);
    oproj_mma_kernel<<<dim3(2, 256, 2), 256, OP_SMEM>>>(o_w, o_b, out);
}

// round 11
// speedup vs baseline: 6.4555x; 1.0103x over previous
#include <cuda_runtime.h>
#include <cuda_bf16.h>
#include <cuda_fp16.h>
#include <math.h>
#include <math_constants.h>

#define BB    2
#define CC    256
#define NTOK  32768
#define SS    256
#define TDIM  512
#define NHD   8
#define HDIM  32

typedef unsigned u32;
typedef unsigned long long ull;

// ---------------- scratch ----------------
#define OFF_H1    0
#define OFF_KRAW  (OFF_H1   + 131072)
#define OFF_VRAW  (OFF_KRAW + 131072)
#define OFF_PHASE (OFF_VRAW + 131072)
#define OFF_KROT  (OFF_PHASE+ 131072)      // fp32 [b,h][d=32][s=256]
#define OFF_VT    (OFF_KROT + 131072)      // fp32 [b,h][s=256][d=32]
#define OFF_Q     (OFF_VT   + 131072)      // fp16x2 u32 [b][n][128] (scale*log2e folded)
#define OFF_AO    (OFF_Q    + 16777216)    // AOH u32 [b][n][128] ; AOL at +8388608
#define OFF_INVF  (OFF_AO   + 16777216)
#define SCR_TOTAL (OFF_INVF + 32)
__device__ float g_scr[SCR_TOTAL];
#define AOL_DELTA 8388608

// scale * log2(e), folded into Q so QK scores come out in log2 domain
#define QSCALE (0.17677669529663687f * 1.4426950408889634f)

// ---------------- helpers ----------------
__device__ __forceinline__ void ldsm4(u32& r0, u32& r1, u32& r2, u32& r3, u32 addr) {
    asm volatile("ldmatrix.sync.aligned.m8n8.x4.shared.b16 {%0,%1,%2,%3}, [%4];"
                 : "=r"(r0), "=r"(r1), "=r"(r2), "=r"(r3) : "r"(addr));
}
__device__ __forceinline__ void ldsm4t(u32& r0, u32& r1, u32& r2, u32& r3, u32 addr) {
    asm volatile("ldmatrix.sync.aligned.m8n8.x4.trans.shared.b16 {%0,%1,%2,%3}, [%4];"
                 : "=r"(r0), "=r"(r1), "=r"(r2), "=r"(r3) : "r"(addr));
}
__device__ __forceinline__ void ldsm2t(u32& r0, u32& r1, u32 addr) {
    asm volatile("ldmatrix.sync.aligned.m8n8.x2.trans.shared.b16 {%0,%1}, [%2];"
                 : "=r"(r0), "=r"(r1) : "r"(addr));
}
__device__ __forceinline__ void mma_f16(float* d, const u32* a, u32 b0, u32 b1) {
    asm volatile("mma.sync.aligned.m16n8k16.row.col.f32.f16.f16.f32 "
                 "{%0,%1,%2,%3}, {%4,%5,%6,%7}, {%8,%9}, {%0,%1,%2,%3};"
                 : "+f"(d[0]), "+f"(d[1]), "+f"(d[2]), "+f"(d[3])
                 : "r"(a[0]), "r"(a[1]), "r"(a[2]), "r"(a[3]), "r"(b0), "r"(b1));
}
__device__ __forceinline__ void f16pack2(float x, float y, u32& h) {
    asm("cvt.rn.f16x2.f32 %0, %1, %2;" : "=r"(h) : "f"(y), "f"(x));
}
__device__ __forceinline__ u32 ex2h2(u32 x) {
    u32 d;
    asm("ex2.approx.f16x2 %0, %1;" : "=r"(d) : "r"(x));
    return d;
}
__device__ __forceinline__ void f16split2(float x, float y, u32& hi, u32& lo) {
    f16pack2(x, y, hi);
    __half2 hv = *(__half2*)&hi;
    float hx = __low2float(hv), hy = __high2float(hv);
    f16pack2(x - hx, y - hy, lo);
}
__device__ __forceinline__ void ldA_mk(u32* f, u32 base, int stride, int m0, int k0, int lane) {
    int m = m0 + (lane & 15);
    int k = k0 + ((lane >> 4) << 3);
    ldsm4(f[0], f[1], f[2], f[3], base + (u32)((m * stride + k) * 2));
}
__device__ __forceinline__ void ldA_km(u32* f, u32 base, int stride, int k0, int m0, int lane) {
    int k = k0 + (lane & 7) + ((lane >> 4) << 3);
    int m = m0 + (((lane >> 3) & 1) << 3);
    ldsm4t(f[0], f[1], f[2], f[3], base + (u32)((k * stride + m) * 2));
}
__device__ __forceinline__ void ldB_kn(u32* f, u32 base, int stride, int k0, int n0, int lane) {
    int k = k0 + (lane & 7) + (((lane >> 3) & 1) << 3);
    int n = n0 + ((lane >> 4) << 3);
    ldsm4t(f[0], f[1], f[2], f[3], base + (u32)((k * stride + n) * 2));
}
// stage 32(k) x 128(cols) fp32 -> single fp16 [k][136]  (256-thread version)
__device__ __forceinline__ void stage_km_f16(const float* g, int gstride, char* smH, int t) {
    #pragma unroll
    for (int i = 0; i < 4; i++) {
        int lin = i * 256 + t;
        int kr = lin >> 5, mq = (lin & 31) * 4;
        float4 v = *(const float4*)(g + (size_t)kr * gstride + mq);
        u32 h0, h1;
        f16pack2(v.x, v.y, h0);
        f16pack2(v.z, v.w, h1);
        *(ull*)(smH + (size_t)(kr * 68 + (mq >> 1)) * 4) = (ull)h0 | ((ull)h1 << 32);
    }
}
// same, 512-thread version
__device__ __forceinline__ void stage_km_f16_512(const float* g, int gstride, char* smH, int t) {
    #pragma unroll
    for (int i = 0; i < 2; i++) {
        int lin = i * 512 + t;
        int kr = lin >> 5, mq = (lin & 31) * 4;
        float4 v = *(const float4*)(g + (size_t)kr * gstride + mq);
        u32 h0, h1;
        f16pack2(v.x, v.y, h0);
        f16pack2(v.z, v.w, h1);
        *(ull*)(smH + (size_t)(kr * 68 + (mq >> 1)) * 4) = (ull)h0 | ((ull)h1 << 32);
    }
}

// ---------------- rope inverse-frequency table ----------------
__global__ void init_invf_kernel() {
    int d = threadIdx.x;
    if (d < 32) {
        float e;
        if (d < 10)       e = (float)(2 * (d % 5)) / 10.f;
        else if (d < 20)  e = (float)(2 * ((d - 10) % 5)) / 10.f;
        else              e = (float)(2 * ((d - 20) % 6)) / 12.f;
        g_scr[OFF_INVF + d] = powf(10000.f, -e);
    }
}

// ---------------- fp32 text GEMMs ----------------
__device__ __forceinline__ void gemm32x64_body(const float* __restrict__ A,
                                               const float* __restrict__ W,
                                               const float* __restrict__ bias,
                                               float* __restrict__ Y,
                                               int K, int N, int mode,
                                               int m0, int j0,
                                               float* As, float* Ws) {
    int t = threadIdx.x;
    int tx = t & 15, ty = t >> 4;
    float acc[2][4] = {};
    for (int k0 = 0; k0 < K; k0 += 16) {
        if (t < 128) {
            int m = t >> 2, kq = (t & 3) * 4;
            float4 av = *(const float4*)&A[(size_t)(m0 + m) * K + k0 + kq];
            As[(kq + 0) * 33 + m] = av.x;
            As[(kq + 1) * 33 + m] = av.y;
            As[(kq + 2) * 33 + m] = av.z;
            As[(kq + 3) * 33 + m] = av.w;
        }
        {
            int kk = t >> 4, j4 = (t & 15) * 4;
            *(float4*)&Ws[kk * 64 + j4] = *(const float4*)&W[(size_t)(k0 + kk) * N + j0 + j4];
        }
        __syncthreads();
        #pragma unroll
        for (int kk = 0; kk < 16; kk++) {
            float a0 = As[kk * 33 + ty * 2], a1 = As[kk * 33 + ty * 2 + 1];
            #pragma unroll
            for (int j = 0; j < 4; j++) {
                float w = Ws[kk * 64 + tx + 16 * j];
                acc[0][j] += a0 * w;
                acc[1][j] += a1 * w;
            }
        }
        __syncthreads();
    }
    #pragma unroll
    for (int j = 0; j < 4; j++) {
        int jj = j0 + tx + 16 * j;
        float bv = bias[jj];
        #pragma unroll
        for (int i = 0; i < 2; i++) {
            float v = acc[i][j] + bv;
            int m = m0 + ty * 2 + i;
            if (mode == 1) v = 0.5f * v * (1.f + erff(v * 0.70710678118654752f));
            if (mode == 2) {
                int h = jj >> 5, d = jj & 31;
                int bb = m >> 8, ss = m & 255;
                Y[(size_t)((bb * NHD + h) * SS + ss) * HDIM + d] = v;
            } else {
                Y[(size_t)m * N + jj] = v;
            }
        }
    }
}

__global__ void text3_kernel(const float* __restrict__ text,
                             const float* __restrict__ kw, const float* __restrict__ kb,
                             const float* __restrict__ vw, const float* __restrict__ vb,
                             const float* __restrict__ m1w, const float* __restrict__ m1b) {
    __shared__ float As[16 * 33];
    __shared__ float Ws[16 * 64];
    const float *W, *bias;
    float* Y;
    int mode = 0;
    if (blockIdx.z == 0)      { W = kw;  bias = kb;  Y = g_scr + OFF_KRAW; }
    else if (blockIdx.z == 1) { W = vw;  bias = vb;  Y = g_scr + OFF_VT; mode = 2; }
    else                      { W = m1w; bias = m1b; Y = g_scr + OFF_H1; mode = 1; }
    gemm32x64_body(text, W, bias, Y, 512, 256, mode, blockIdx.y * 32, blockIdx.x * 64, As, Ws);
}

// phase GEMM fused with text rope
__global__ void phase_rope_kernel(const float* __restrict__ m2w, const float* __restrict__ m2b) {
    __shared__ float As[16 * 33];
    __shared__ float Ws[16 * 64];
    const float* A = g_scr + OFF_H1;
    const float* kraw = g_scr + OFF_KRAW;
    float* krot = g_scr + OFF_KROT;
    int m0 = blockIdx.y * 32, j0 = blockIdx.x * 64;
    int t = threadIdx.x;
    int tx = t & 15, ty = t >> 4;
    float acc[2][4] = {};
    for (int k0 = 0; k0 < 256; k0 += 16) {
        if (t < 128) {
            int m = t >> 2, kq = (t & 3) * 4;
            float4 av = *(const float4*)&A[(size_t)(m0 + m) * 256 + k0 + kq];
            As[(kq + 0) * 33 + m] = av.x;
            As[(kq + 1) * 33 + m] = av.y;
            As[(kq + 2) * 33 + m] = av.z;
            As[(kq + 3) * 33 + m] = av.w;
        }
        {
            int kk = t >> 4, j4 = (t & 15) * 4;
            *(float4*)&Ws[kk * 64 + j4] = *(const float4*)&m2w[(size_t)(k0 + kk) * 256 + j0 + j4];
        }
        __syncthreads();
        #pragma unroll
        for (int kk = 0; kk < 16; kk++) {
            float a0 = As[kk * 33 + ty * 2], a1 = As[kk * 33 + ty * 2 + 1];
            #pragma unroll
            for (int j = 0; j < 4; j++) {
                float w = Ws[kk * 64 + tx + 16 * j];
                acc[0][j] += a0 * w;
                acc[1][j] += a1 * w;
            }
        }
        __syncthreads();
    }
    #pragma unroll
    for (int i = 0; i < 2; i++) {
        int m = m0 + ty * 2 + i;
        int bb = m >> 8, ss = m & 255;
        #pragma unroll
        for (int jp = 0; jp < 2; jp++) {
            float p0 = acc[i][jp * 2]     + m2b[j0 + 32 * jp + tx];
            float p1 = acc[i][jp * 2 + 1] + m2b[j0 + 32 * jp + tx + 16];
            int h = (j0 >> 5) + jp;
            int base = m * 256 + h * HDIM + tx;
            float k0v = kraw[base], k1v = kraw[base + 16];
            float c0, s0, c1, s1;
            __sincosf(p0, &s0, &c0);
            __sincosf(p1, &s1, &c1);
            int kbase = ((bb * NHD + h) * HDIM + tx) * SS + ss;
            krot[kbase]            = k0v * c0 - k1v * s0;
            krot[kbase + 16 * SS]  = k1v * c1 + k0v * s1;
        }
    }
}

// ================= Q projection: fp16 mma, 512 thr, warp-tile 32x32, streaming K =================
#define QP_A 0
#define QP_B 8704
#define QP_SMEM 17408
__global__ __launch_bounds__(512, 1) void qproj_mma_kernel(
        const float* __restrict__ A, const float* __restrict__ W,
        const float* __restrict__ bias) {
    __shared__ char sm[QP_SMEM];
    u32* qp = (u32*)(g_scr + OFF_Q);
    const float* invf = g_scr + OFF_INVF;
    int b = blockIdx.z;
    int n0 = blockIdx.y * 128, j0 = blockIdx.x * 128;
    int t = threadIdx.x;
    int w = t >> 5, lane = t & 31;
    int wm = w & 3, wn = w >> 2;
    int mu = lane & 3, r = lane >> 2;
    const float* Ab = A + (size_t)b * CC * NTOK;
    u32 aH = (u32)__cvta_generic_to_shared(sm + QP_A);
    u32 bH = (u32)__cvta_generic_to_shared(sm + QP_B);
    float acc[2][4][4] = {};
    for (int k0 = 0; k0 < CC; k0 += 32) {
        stage_km_f16_512(Ab + (size_t)k0 * NTOK + n0, NTOK, sm + QP_A, t);
        stage_km_f16_512(W + (size_t)k0 * CC + j0, CC, sm + QP_B, t);
        __syncthreads();
        #pragma unroll
        for (int kt = 0; kt < 2; kt++) {
            u32 ah[2][4];
            #pragma unroll
            for (int mt = 0; mt < 2; mt++)
                ldA_km(ah[mt], aH, 136, kt * 16, wm * 32 + mt * 16, lane);
            #pragma unroll
            for (int ng = 0; ng < 2; ng++) {
                u32 bh[4];
                ldB_kn(bh, bH, 136, kt * 16, wn * 32 + ng * 16, lane);
                #pragma unroll
                for (int mt = 0; mt < 2; mt++) {
                    mma_f16(acc[mt][ng * 2],     ah[mt], bh[0], bh[1]);
                    mma_f16(acc[mt][ng * 2 + 1], ah[mt], bh[2], bh[3]);
                }
            }
        }
        __syncthreads();
    }
    // epilogue: bias + rope, pack fp16 with QSCALE folded
    float blo[2][2], bhi[2][2], fl0[2][2], fl1[2][2];
    int zsel[2][2], xsel[2][2];
    #pragma unroll
    for (int jj = 0; jj < 2; jj++)
        #pragma unroll
        for (int cc = 0; cc < 2; cc++) {
            int d = jj * 8 + 2 * mu + cc;
            blo[jj][cc] = bias[j0 + wn * 32 + d];
            bhi[jj][cc] = bias[j0 + wn * 32 + d + 16];
            fl0[jj][cc] = invf[d];
            fl1[jj][cc] = invf[d + 16];
            zsel[jj][cc] = (d < 10);
            xsel[jj][cc] = (d + 16 >= 20);
        }
    #pragma unroll
    for (int mt = 0; mt < 2; mt++)
        #pragma unroll
        for (int half = 0; half < 2; half++) {
            int n = n0 + wm * 32 + mt * 16 + r + half * 8;
            float wx = (float)(n & 31), hy = (float)((n >> 5) & 31), dz = (float)(n >> 10);
            u32* yp = qp + (size_t)(b * NTOK + n) * 128 + (j0 + wn * 32) / 2;
            #pragma unroll
            for (int jj = 0; jj < 2; jj++) {
                float v0[2], v1[2];
                #pragma unroll
                for (int cc = 0; cc < 2; cc++) {
                    float q0 = acc[mt][jj][half * 2 + cc] + blo[jj][cc];
                    float q1 = acc[mt][jj + 2][half * 2 + cc] + bhi[jj][cc];
                    float f0 = (zsel[jj][cc] ? dz : hy) * fl0[jj][cc];
                    float f1 = (xsel[jj][cc] ? wx : hy) * fl1[jj][cc];
                    float s0, c0, s1, c1;
                    __sincosf(f0, &s0, &c0);
                    __sincosf(f1, &s1, &c1);
                    v0[cc] = (q0 * c0 - q1 * s0) * QSCALE;
                    v1[cc] = (q1 * c1 + q0 * s1) * QSCALE;
                }
                u32 u0, u1;
                f16pack2(v0[0], v0[1], u0);
                f16pack2(v1[0], v1[1], u1);
                yp[jj * 4 + mu]     = u0;
                yp[jj * 4 + mu + 8] = u1;
            }
        }
}

// ================= attention: QK fp16, fp16 softmax (ex2.f16x2), PV 1-term + sum-MMA =================
#define AT_QH 0
#define AT_KH 10240
#define AT_VH 27136
#define AT_SMEM 47616
__global__ __launch_bounds__(256, 1) void attn_mma_kernel() {
    extern __shared__ char sm[];
    const u32* qp = (const u32*)(g_scr + OFF_Q);
    const float* krot = g_scr + OFF_KROT;
    const float* vt   = g_scr + OFF_VT;
    u32* aoh = (u32*)(g_scr + OFF_AO);
    u32* aol = aoh + AOL_DELTA;
    int b = blockIdx.z, h = blockIdx.y;
    int n0 = blockIdx.x * 128;
    int t = threadIdx.x;
    int w = t >> 5, lane = t & 31;
    int mu = lane & 3, r = lane >> 2;
    u32* QHu = (u32*)(sm + AT_QH);
    u32* KHu = (u32*)(sm + AT_KH);
    u32* VHu = (u32*)(sm + AT_VH);
    #pragma unroll
    for (int i = 0; i < 8; i++) {
        int lin = i * 256 + t;
        int row = lin >> 4, dp = lin & 15;
        QHu[row * 20 + dp] = qp[(size_t)(b * NTOK + n0 + row) * 128 + h * 16 + dp];
    }
    size_t kb = (size_t)(b * NHD + h) * HDIM * SS;
    #pragma unroll
    for (int i = 0; i < 16; i++) {
        int lin = i * 256 + t;
        int d = lin >> 7, sp = lin & 127;
        float2 v = *(const float2*)&krot[kb + (size_t)d * SS + sp * 2];
        u32 hh;
        f16pack2(v.x, v.y, hh);
        KHu[d * 132 + sp] = hh;
    }
    size_t vb = (size_t)(b * NHD + h) * SS * HDIM;
    #pragma unroll
    for (int i = 0; i < 16; i++) {
        int lin = i * 256 + t;
        int s = lin >> 4, dp = lin & 15;
        float2 v = *(const float2*)&vt[vb + (size_t)s * HDIM + dp * 2];
        u32 hh;
        f16pack2(v.x, v.y, hh);
        VHu[s * 20 + dp] = hh;
    }
    #pragma unroll
    for (int i = 0; i < 4; i++) {
        int lin = i * 256 + t;
        int s = lin >> 2, c = lin & 3;
        VHu[s * 20 + 16 + c] = (c == 0) ? 0x00003C00u : 0u;
    }
    __syncthreads();
    u32 aQH = (u32)__cvta_generic_to_shared(sm + AT_QH);
    u32 aKH = (u32)__cvta_generic_to_shared(sm + AT_KH);
    u32 aVH = (u32)__cvta_generic_to_shared(sm + AT_VH);
    float acc[32][4];
    #pragma unroll
    for (int i = 0; i < 32; i++)
        #pragma unroll
        for (int j = 0; j < 4; j++) acc[i][j] = 0.f;
    #pragma unroll
    for (int kt = 0; kt < 2; kt++) {
        u32 qh[4];
        ldA_mk(qh, aQH, 40, w * 16, kt * 16, lane);
        #pragma unroll
        for (int sg = 0; sg < 16; sg++) {
            u32 kh[4];
            ldB_kn(kh, aKH, 264, kt * 16, sg * 16, lane);
            mma_f16(acc[sg * 2],     qh, kh[0], kh[1]);
            mma_f16(acc[sg * 2 + 1], qh, kh[2], kh[3]);
        }
    }
    float mx0 = -CUDART_INF_F, mx1 = -CUDART_INF_F;
    #pragma unroll
    for (int i = 0; i < 32; i++) {
        mx0 = fmaxf(mx0, fmaxf(acc[i][0], acc[i][1]));
        mx1 = fmaxf(mx1, fmaxf(acc[i][2], acc[i][3]));
    }
    mx0 = fmaxf(mx0, __shfl_xor_sync(0xffffffffu, mx0, 1));
    mx0 = fmaxf(mx0, __shfl_xor_sync(0xffffffffu, mx0, 2));
    mx1 = fmaxf(mx1, __shfl_xor_sync(0xffffffffu, mx1, 1));
    mx1 = fmaxf(mx1, __shfl_xor_sync(0xffffffffu, mx1, 2));
    u32 p0[32], p1[32];
    #pragma unroll
    for (int i = 0; i < 32; i++) {
        u32 a0, a1;
        f16pack2(acc[i][0] - mx0, acc[i][1] - mx0, a0);
        f16pack2(acc[i][2] - mx1, acc[i][3] - mx1, a1);
        p0[i] = ex2h2(a0);
        p1[i] = ex2h2(a1);
    }
    float oacc[4][4] = {};
    float osum[4] = {};
    #pragma unroll
    for (int kt = 0; kt < 16; kt++) {
        u32 ah[4] = {p0[2 * kt], p1[2 * kt], p0[2 * kt + 1], p1[2 * kt + 1]};
        u32 vh[2][4];
        ldB_kn(vh[0], aVH, 40, kt * 16, 0, lane);
        ldB_kn(vh[1], aVH, 40, kt * 16, 16, lane);
        u32 s0f, s1f;
        ldsm2t(s0f, s1f, aVH + (u32)(((kt * 16 + (lane & 15)) * 40 + 32) * 2));
        mma_f16(oacc[0], ah, vh[0][0], vh[0][1]);
        mma_f16(oacc[1], ah, vh[0][2], vh[0][3]);
        mma_f16(oacc[2], ah, vh[1][0], vh[1][1]);
        mma_f16(oacc[3], ah, vh[1][2], vh[1][3]);
        mma_f16(osum, ah, s0f, s1f);
    }
    float sm0 = __shfl_sync(0xffffffffu, osum[0], lane & ~3);
    float sm1 = __shfl_sync(0xffffffffu, osum[2], lane & ~3);
    float zi0 = 1.f / sm0, zi1 = 1.f / sm1;
    #pragma unroll
    for (int dt = 0; dt < 4; dt++) {
        size_t i0 = (size_t)(b * NTOK + n0 + w * 16 + r) * 128 + h * 16 + dt * 4 + mu;
        size_t i1 = (size_t)(b * NTOK + n0 + w * 16 + r + 8) * 128 + h * 16 + dt * 4 + mu;
        u32 hh, ll;
        f16split2(oacc[dt][0] * zi0, oacc[dt][1] * zi0, hh, ll);
        aoh[i0] = hh; aol[i0] = ll;
        f16split2(oacc[dt][2] * zi1, oacc[dt][3] * zi1, hh, ll);
        aoh[i1] = hh; aol[i1] = ll;
    }
}

// ================= O projection: 2-term fp16, 512 thr, warp-tile 32x32 + transpose =================
#define OP_AH 0
#define OP_AL 10240
#define OP_BH 20480
#define OP_SMEM 67584
__global__ __launch_bounds__(512, 1) void oproj_mma_kernel(
        const float* __restrict__ W, const float* __restrict__ bias,
        float* __restrict__ Out) {
    extern __shared__ char sm[];
    const u32* aoh = (const u32*)(g_scr + OFF_AO);
    const u32* aol = aoh + AOL_DELTA;
    int b = blockIdx.z;
    int n0 = blockIdx.y * 128, j0 = blockIdx.x * 128;
    int t = threadIdx.x;
    int w = t >> 5, lane = t & 31;
    int wm = w & 3, wn = w >> 2;
    int mu = lane & 3, r = lane >> 2;
    u32* AHs = (u32*)(sm + OP_AH);
    u32* ALs = (u32*)(sm + OP_AL);
    u32 aH = (u32)__cvta_generic_to_shared(sm + OP_AH);
    u32 aL = (u32)__cvta_generic_to_shared(sm + OP_AL);
    u32 bH = (u32)__cvta_generic_to_shared(sm + OP_BH);
    float acc[2][4][4] = {};
    for (int k0 = 0; k0 < CC; k0 += 32) {
        #pragma unroll
        for (int i = 0; i < 4; i++) {
            int lin = i * 512 + t;
            int m = lin >> 4, j = lin & 15;
            size_t gidx = (size_t)(b * NTOK + n0 + m) * 128 + (k0 >> 1) + j;
            AHs[m * 20 + j] = aoh[gidx];
            ALs[m * 20 + j] = aol[gidx];
        }
        stage_km_f16_512(W + (size_t)k0 * CC + j0, CC, sm + OP_BH, t);
        __syncthreads();
        #pragma unroll
        for (int kt = 0; kt < 2; kt++) {
            u32 ah[2][4], al[2][4];
            #pragma unroll
            for (int mt = 0; mt < 2; mt++) {
                ldA_mk(ah[mt], aH, 40, wm * 32 + mt * 16, kt * 16, lane);
                ldA_mk(al[mt], aL, 40, wm * 32 + mt * 16, kt * 16, lane);
            }
            #pragma unroll
            for (int ng = 0; ng < 2; ng++) {
                u32 bh[4];
                ldB_kn(bh, bH, 136, kt * 16, wn * 32 + ng * 16, lane);
                #pragma unroll
                for (int mt = 0; mt < 2; mt++) {
                    mma_f16(acc[mt][ng * 2],     ah[mt], bh[0], bh[1]);
                    mma_f16(acc[mt][ng * 2 + 1], ah[mt], bh[2], bh[3]);
                }
                #pragma unroll
                for (int mt = 0; mt < 2; mt++) {
                    mma_f16(acc[mt][ng * 2],     al[mt], bh[0], bh[1]);
                    mma_f16(acc[mt][ng * 2 + 1], al[mt], bh[2], bh[3]);
                }
            }
        }
        __syncthreads();
    }
    float* Cs = (float*)sm;
    #pragma unroll
    for (int mt = 0; mt < 2; mt++)
        #pragma unroll
        for (int j = 0; j < 4; j++)
            #pragma unroll
            for (int half = 0; half < 2; half++) {
                int ml = wm * 32 + mt * 16 + r + half * 8;
                int jl = wn * 32 + j * 8 + 2 * mu;
                Cs[jl * 132 + ml]       = acc[mt][j][half * 2];
                Cs[(jl + 1) * 132 + ml] = acc[mt][j][half * 2 + 1];
            }
    __syncthreads();
    #pragma unroll
    for (int i = 0; i < 8; i++) {
        int lin = i * 512 + t;
        int j = lin >> 5, mq = (lin & 31) * 4;
        float4 v = *(float4*)&Cs[j * 132 + mq];
        float bv = bias[j0 + j];
        v.x += bv; v.y += bv; v.z += bv; v.w += bv;
        *(float4*)&Out[((size_t)b * CC + j0 + j) * NTOK + n0 + mq] = v;
    }
}

// ---------------- launch ----------------
extern "C" void kernel_launch(void* const* d_in, const int* in_sizes, int n_in,
                              void* d_out, int out_size) {
    const float* fv   = (const float*)d_in[0];
    const float* text = (const float*)d_in[1];
    const float* q_w  = (const float*)d_in[2];
    const float* q_b  = (const float*)d_in[3];
    const float* k_w  = (const float*)d_in[4];
    const float* k_b  = (const float*)d_in[5];
    const float* v_w  = (const float*)d_in[6];
    const float* v_b  = (const float*)d_in[7];
    const float* o_w  = (const float*)d_in[8];
    const float* o_b  = (const float*)d_in[9];
    const float* m1_w = (const float*)d_in[10];
    const float* m1_b = (const float*)d_in[11];
    const float* m2_w = (const float*)d_in[12];
    const float* m2_b = (const float*)d_in[13];
    float* out = (float*)d_out;

    init_invf_kernel<<<1, 32>>>();
    text3_kernel<<<dim3(4, 16, 3), 256>>>(text, k_w, k_b, v_w, v_b, m1_w, m1_b);
    phase_rope_kernel<<<dim3(4, 16), 256>>>(m2_w, m2_b);

    qproj_mma_kernel<<<dim3(2, 256, 2), 512>>>(fv, q_w, q_b);

    cudaFuncSetAttribute(attn_mma_kernel, cudaFuncAttributeMaxDynamicSharedMemorySize, AT_SMEM);
    attn_mma_kernel<<<dim3(256, 8, 2), 256, AT_SMEM>>>();

    cudaFuncSetAttribute(oproj_mma_kernel, cudaFuncAttributeMaxDynamicSharedMemorySize, OP_SMEM);
    oproj_mma_kernel<<<dim3(2, 256, 2), 512, OP_SMEM>>>(o_w, o_b, out);
}

// round 12
// speedup vs baseline: 8.2120x; 1.2721x over previous
#include <cuda_runtime.h>
#include <cuda_bf16.h>
#include <cuda_fp16.h>
#include <math.h>
#include <math_constants.h>

#define BB    2
#define CC    256
#define NTOK  32768
#define SS    256
#define TDIM  512
#define NHD   8
#define HDIM  32

typedef unsigned u32;
typedef unsigned long long ull;

// ---------------- scratch ----------------
#define OFF_H1    0
#define OFF_KRAW  (OFF_H1   + 131072)
#define OFF_VRAW  (OFF_KRAW + 131072)
#define OFF_PHASE (OFF_VRAW + 131072)
#define OFF_KROT  (OFF_PHASE+ 131072)      // fp32 [b,h][d=32][s=256]
#define OFF_VT    (OFF_KROT + 131072)      // fp32 [b,h][s=256][d=32]
#define OFF_Q     (OFF_VT   + 131072)      // fp16x2 u32 [b][n][128] (scale*log2e folded)
#define OFF_AO    (OFF_Q    + 16777216)    // fp16x2 u32 [b][n][128]
#define OFF_INVF  (OFF_AO   + 16777216)
#define SCR_TOTAL (OFF_INVF + 32)
__device__ float g_scr[SCR_TOTAL];

// scale * log2(e), folded into Q so QK scores come out in log2 domain
#define QSCALE (0.17677669529663687f * 1.4426950408889634f)

// ---------------- helpers ----------------
__device__ __forceinline__ void ldsm4(u32& r0, u32& r1, u32& r2, u32& r3, u32 addr) {
    asm volatile("ldmatrix.sync.aligned.m8n8.x4.shared.b16 {%0,%1,%2,%3}, [%4];"
                 : "=r"(r0), "=r"(r1), "=r"(r2), "=r"(r3) : "r"(addr));
}
__device__ __forceinline__ void ldsm4t(u32& r0, u32& r1, u32& r2, u32& r3, u32 addr) {
    asm volatile("ldmatrix.sync.aligned.m8n8.x4.trans.shared.b16 {%0,%1,%2,%3}, [%4];"
                 : "=r"(r0), "=r"(r1), "=r"(r2), "=r"(r3) : "r"(addr));
}
__device__ __forceinline__ void ldsm2t(u32& r0, u32& r1, u32 addr) {
    asm volatile("ldmatrix.sync.aligned.m8n8.x2.trans.shared.b16 {%0,%1}, [%2];"
                 : "=r"(r0), "=r"(r1) : "r"(addr));
}
__device__ __forceinline__ void mma_f16(float* d, const u32* a, u32 b0, u32 b1) {
    asm volatile("mma.sync.aligned.m16n8k16.row.col.f32.f16.f16.f32 "
                 "{%0,%1,%2,%3}, {%4,%5,%6,%7}, {%8,%9}, {%0,%1,%2,%3};"
                 : "+f"(d[0]), "+f"(d[1]), "+f"(d[2]), "+f"(d[3])
                 : "r"(a[0]), "r"(a[1]), "r"(a[2]), "r"(a[3]), "r"(b0), "r"(b1));
}
__device__ __forceinline__ void f16pack2(float x, float y, u32& h) {
    asm("cvt.rn.f16x2.f32 %0, %1, %2;" : "=r"(h) : "f"(y), "f"(x));
}
__device__ __forceinline__ u32 ex2h2(u32 x) {
    u32 d;
    asm("ex2.approx.f16x2 %0, %1;" : "=r"(d) : "r"(x));
    return d;
}
__device__ __forceinline__ void ldA_mk(u32* f, u32 base, int stride, int m0, int k0, int lane) {
    int m = m0 + (lane & 15);
    int k = k0 + ((lane >> 4) << 3);
    ldsm4(f[0], f[1], f[2], f[3], base + (u32)((m * stride + k) * 2));
}
__device__ __forceinline__ void ldA_km(u32* f, u32 base, int stride, int k0, int m0, int lane) {
    int k = k0 + (lane & 7) + ((lane >> 4) << 3);
    int m = m0 + (((lane >> 3) & 1) << 3);
    ldsm4t(f[0], f[1], f[2], f[3], base + (u32)((k * stride + m) * 2));
}
__device__ __forceinline__ void ldB_kn(u32* f, u32 base, int stride, int k0, int n0, int lane) {
    int k = k0 + (lane & 7) + (((lane >> 3) & 1) << 3);
    int n = n0 + ((lane >> 4) << 3);
    ldsm4t(f[0], f[1], f[2], f[3], base + (u32)((k * stride + n) * 2));
}
// pipelined staging: LDG+cvt into 4 regs (512-thread, 32x128 fp32 panel)
__device__ __forceinline__ void ldg_cvt_512(const float* g, int gstride, int t, u32* p) {
    #pragma unroll
    for (int i = 0; i < 2; i++) {
        int lin = i * 512 + t;
        int kr = lin >> 5, mq = (lin & 31) * 4;
        float4 v = *(const float4*)(g + (size_t)kr * gstride + mq);
        f16pack2(v.x, v.y, p[2 * i]);
        f16pack2(v.z, v.w, p[2 * i + 1]);
    }
}
__device__ __forceinline__ void sts_512(char* smH, int t, const u32* p) {
    #pragma unroll
    for (int i = 0; i < 2; i++) {
        int lin = i * 512 + t;
        int kr = lin >> 5, mq = (lin & 31) * 4;
        *(ull*)(smH + (size_t)(kr * 68 + (mq >> 1)) * 4) = (ull)p[2 * i] | ((ull)p[2 * i + 1] << 32);
    }
}

// ---------------- rope inverse-frequency table ----------------
__global__ void init_invf_kernel() {
    int d = threadIdx.x;
    if (d < 32) {
        float e;
        if (d < 10)       e = (float)(2 * (d % 5)) / 10.f;
        else if (d < 20)  e = (float)(2 * ((d - 10) % 5)) / 10.f;
        else              e = (float)(2 * ((d - 20) % 6)) / 12.f;
        g_scr[OFF_INVF + d] = powf(10000.f, -e);
    }
}

// ---------------- fp32 text GEMMs ----------------
__device__ __forceinline__ void gemm32x64_body(const float* __restrict__ A,
                                               const float* __restrict__ W,
                                               const float* __restrict__ bias,
                                               float* __restrict__ Y,
                                               int K, int N, int mode,
                                               int m0, int j0,
                                               float* As, float* Ws) {
    int t = threadIdx.x;
    int tx = t & 15, ty = t >> 4;
    float acc[2][4] = {};
    for (int k0 = 0; k0 < K; k0 += 16) {
        if (t < 128) {
            int m = t >> 2, kq = (t & 3) * 4;
            float4 av = *(const float4*)&A[(size_t)(m0 + m) * K + k0 + kq];
            As[(kq + 0) * 33 + m] = av.x;
            As[(kq + 1) * 33 + m] = av.y;
            As[(kq + 2) * 33 + m] = av.z;
            As[(kq + 3) * 33 + m] = av.w;
        }
        {
            int kk = t >> 4, j4 = (t & 15) * 4;
            *(float4*)&Ws[kk * 64 + j4] = *(const float4*)&W[(size_t)(k0 + kk) * N + j0 + j4];
        }
        __syncthreads();
        #pragma unroll
        for (int kk = 0; kk < 16; kk++) {
            float a0 = As[kk * 33 + ty * 2], a1 = As[kk * 33 + ty * 2 + 1];
            #pragma unroll
            for (int j = 0; j < 4; j++) {
                float w = Ws[kk * 64 + tx + 16 * j];
                acc[0][j] += a0 * w;
                acc[1][j] += a1 * w;
            }
        }
        __syncthreads();
    }
    #pragma unroll
    for (int j = 0; j < 4; j++) {
        int jj = j0 + tx + 16 * j;
        float bv = bias[jj];
        #pragma unroll
        for (int i = 0; i < 2; i++) {
            float v = acc[i][j] + bv;
            int m = m0 + ty * 2 + i;
            if (mode == 1) v = 0.5f * v * (1.f + erff(v * 0.70710678118654752f));
            if (mode == 2) {
                int h = jj >> 5, d = jj & 31;
                int bb = m >> 8, ss = m & 255;
                Y[(size_t)((bb * NHD + h) * SS + ss) * HDIM + d] = v;
            } else {
                Y[(size_t)m * N + jj] = v;
            }
        }
    }
}

__global__ void text3_kernel(const float* __restrict__ text,
                             const float* __restrict__ kw, const float* __restrict__ kb,
                             const float* __restrict__ vw, const float* __restrict__ vb,
                             const float* __restrict__ m1w, const float* __restrict__ m1b) {
    __shared__ float As[16 * 33];
    __shared__ float Ws[16 * 64];
    const float *W, *bias;
    float* Y;
    int mode = 0;
    if (blockIdx.z == 0)      { W = kw;  bias = kb;  Y = g_scr + OFF_KRAW; }
    else if (blockIdx.z == 1) { W = vw;  bias = vb;  Y = g_scr + OFF_VT; mode = 2; }
    else                      { W = m1w; bias = m1b; Y = g_scr + OFF_H1; mode = 1; }
    gemm32x64_body(text, W, bias, Y, 512, 256, mode, blockIdx.y * 32, blockIdx.x * 64, As, Ws);
}

// phase GEMM fused with text rope
__global__ void phase_rope_kernel(const float* __restrict__ m2w, const float* __restrict__ m2b) {
    __shared__ float As[16 * 33];
    __shared__ float Ws[16 * 64];
    const float* A = g_scr + OFF_H1;
    const float* kraw = g_scr + OFF_KRAW;
    float* krot = g_scr + OFF_KROT;
    int m0 = blockIdx.y * 32, j0 = blockIdx.x * 64;
    int t = threadIdx.x;
    int tx = t & 15, ty = t >> 4;
    float acc[2][4] = {};
    for (int k0 = 0; k0 < 256; k0 += 16) {
        if (t < 128) {
            int m = t >> 2, kq = (t & 3) * 4;
            float4 av = *(const float4*)&A[(size_t)(m0 + m) * 256 + k0 + kq];
            As[(kq + 0) * 33 + m] = av.x;
            As[(kq + 1) * 33 + m] = av.y;
            As[(kq + 2) * 33 + m] = av.z;
            As[(kq + 3) * 33 + m] = av.w;
        }
        {
            int kk = t >> 4, j4 = (t & 15) * 4;
            *(float4*)&Ws[kk * 64 + j4] = *(const float4*)&m2w[(size_t)(k0 + kk) * 256 + j0 + j4];
        }
        __syncthreads();
        #pragma unroll
        for (int kk = 0; kk < 16; kk++) {
            float a0 = As[kk * 33 + ty * 2], a1 = As[kk * 33 + ty * 2 + 1];
            #pragma unroll
            for (int j = 0; j < 4; j++) {
                float w = Ws[kk * 64 + tx + 16 * j];
                acc[0][j] += a0 * w;
                acc[1][j] += a1 * w;
            }
        }
        __syncthreads();
    }
    #pragma unroll
    for (int i = 0; i < 2; i++) {
        int m = m0 + ty * 2 + i;
        int bb = m >> 8, ss = m & 255;
        #pragma unroll
        for (int jp = 0; jp < 2; jp++) {
            float p0 = acc[i][jp * 2]     + m2b[j0 + 32 * jp + tx];
            float p1 = acc[i][jp * 2 + 1] + m2b[j0 + 32 * jp + tx + 16];
            int h = (j0 >> 5) + jp;
            int base = m * 256 + h * HDIM + tx;
            float k0v = kraw[base], k1v = kraw[base + 16];
            float c0, s0, c1, s1;
            __sincosf(p0, &s0, &c0);
            __sincosf(p1, &s1, &c1);
            int kbase = ((bb * NHD + h) * HDIM + tx) * SS + ss;
            krot[kbase]            = k0v * c0 - k1v * s0;
            krot[kbase + 16 * SS]  = k1v * c1 + k0v * s1;
        }
    }
}

// ================= Q projection: fp16 mma, double-buffered staging =================
#define QP_STG 17408                      // per-stage: A 8704 + B 8704
__global__ __launch_bounds__(512, 1) void qproj_mma_kernel(
        const float* __restrict__ A, const float* __restrict__ W,
        const float* __restrict__ bias) {
    __shared__ char sm[2 * QP_STG];
    u32* qp = (u32*)(g_scr + OFF_Q);
    const float* invf = g_scr + OFF_INVF;
    int b = blockIdx.z;
    int n0 = blockIdx.y * 128, j0 = blockIdx.x * 128;
    int t = threadIdx.x;
    int w = t >> 5, lane = t & 31;
    int wm = w & 3, wn = w >> 2;
    int mu = lane & 3, r = lane >> 2;
    const float* Ab = A + (size_t)b * CC * NTOK;
    u32 smb = (u32)__cvta_generic_to_shared(sm);
    float acc[2][4][4] = {};
    u32 pa[4], pb[4];
    ldg_cvt_512(Ab + n0, NTOK, t, pa);
    ldg_cvt_512(W + j0, CC, t, pb);
    sts_512(sm, t, pa);
    sts_512(sm + 8704, t, pb);
    __syncthreads();
    for (int kp = 0; kp < 8; kp++) {
        if (kp < 7) {
            ldg_cvt_512(Ab + (size_t)(kp + 1) * 32 * NTOK + n0, NTOK, t, pa);
            ldg_cvt_512(W + (size_t)(kp + 1) * 32 * CC + j0, CC, t, pb);
        }
        u32 aBuf = smb + (u32)((kp & 1) * QP_STG);
        u32 bBuf = aBuf + 8704;
        #pragma unroll
        for (int kt = 0; kt < 2; kt++) {
            u32 ah[2][4];
            #pragma unroll
            for (int mt = 0; mt < 2; mt++)
                ldA_km(ah[mt], aBuf, 136, kt * 16, wm * 32 + mt * 16, lane);
            #pragma unroll
            for (int ng = 0; ng < 2; ng++) {
                u32 bh[4];
                ldB_kn(bh, bBuf, 136, kt * 16, wn * 32 + ng * 16, lane);
                #pragma unroll
                for (int mt = 0; mt < 2; mt++) {
                    mma_f16(acc[mt][ng * 2],     ah[mt], bh[0], bh[1]);
                    mma_f16(acc[mt][ng * 2 + 1], ah[mt], bh[2], bh[3]);
                }
            }
        }
        if (kp < 7) {
            char* nxt = sm + ((kp + 1) & 1) * QP_STG;
            sts_512(nxt, t, pa);
            sts_512(nxt + 8704, t, pb);
        }
        __syncthreads();
    }
    // epilogue: bias + rope, pack fp16 with QSCALE folded
    float blo[2][2], bhi[2][2], fl0[2][2], fl1[2][2];
    int zsel[2][2], xsel[2][2];
    #pragma unroll
    for (int jj = 0; jj < 2; jj++)
        #pragma unroll
        for (int cc = 0; cc < 2; cc++) {
            int d = jj * 8 + 2 * mu + cc;
            blo[jj][cc] = bias[j0 + wn * 32 + d];
            bhi[jj][cc] = bias[j0 + wn * 32 + d + 16];
            fl0[jj][cc] = invf[d];
            fl1[jj][cc] = invf[d + 16];
            zsel[jj][cc] = (d < 10);
            xsel[jj][cc] = (d + 16 >= 20);
        }
    #pragma unroll
    for (int mt = 0; mt < 2; mt++)
        #pragma unroll
        for (int half = 0; half < 2; half++) {
            int n = n0 + wm * 32 + mt * 16 + r + half * 8;
            float wx = (float)(n & 31), hy = (float)((n >> 5) & 31), dz = (float)(n >> 10);
            u32* yp = qp + (size_t)(b * NTOK + n) * 128 + (j0 + wn * 32) / 2;
            #pragma unroll
            for (int jj = 0; jj < 2; jj++) {
                float v0[2], v1[2];
                #pragma unroll
                for (int cc = 0; cc < 2; cc++) {
                    float q0 = acc[mt][jj][half * 2 + cc] + blo[jj][cc];
                    float q1 = acc[mt][jj + 2][half * 2 + cc] + bhi[jj][cc];
                    float f0 = (zsel[jj][cc] ? dz : hy) * fl0[jj][cc];
                    float f1 = (xsel[jj][cc] ? wx : hy) * fl1[jj][cc];
                    float s0, c0, s1, c1;
                    __sincosf(f0, &s0, &c0);
                    __sincosf(f1, &s1, &c1);
                    v0[cc] = (q0 * c0 - q1 * s0) * QSCALE;
                    v1[cc] = (q1 * c1 + q0 * s1) * QSCALE;
                }
                u32 u0, u1;
                f16pack2(v0[0], v0[1], u0);
                f16pack2(v1[0], v1[1], u1);
                yp[jj * 4 + mu]     = u0;
                yp[jj * 4 + mu + 8] = u1;
            }
        }
}

// ================= attention: QK fp16, fp16 softmax (ex2.f16x2), PV 1-term + sum-MMA =================
#define AT_QH 0
#define AT_KH 10240
#define AT_VH 27136
#define AT_SMEM 47616
__global__ __launch_bounds__(256, 1) void attn_mma_kernel() {
    extern __shared__ char sm[];
    const u32* qp = (const u32*)(g_scr + OFF_Q);
    const float* krot = g_scr + OFF_KROT;
    const float* vt   = g_scr + OFF_VT;
    u32* aoh = (u32*)(g_scr + OFF_AO);
    int b = blockIdx.z, h = blockIdx.y;
    int n0 = blockIdx.x * 128;
    int t = threadIdx.x;
    int w = t >> 5, lane = t & 31;
    int mu = lane & 3, r = lane >> 2;
    u32* QHu = (u32*)(sm + AT_QH);
    u32* KHu = (u32*)(sm + AT_KH);
    u32* VHu = (u32*)(sm + AT_VH);
    #pragma unroll
    for (int i = 0; i < 8; i++) {
        int lin = i * 256 + t;
        int row = lin >> 4, dp = lin & 15;
        QHu[row * 20 + dp] = qp[(size_t)(b * NTOK + n0 + row) * 128 + h * 16 + dp];
    }
    size_t kb = (size_t)(b * NHD + h) * HDIM * SS;
    #pragma unroll
    for (int i = 0; i < 16; i++) {
        int lin = i * 256 + t;
        int d = lin >> 7, sp = lin & 127;
        float2 v = *(const float2*)&krot[kb + (size_t)d * SS + sp * 2];
        u32 hh;
        f16pack2(v.x, v.y, hh);
        KHu[d * 132 + sp] = hh;
    }
    size_t vb = (size_t)(b * NHD + h) * SS * HDIM;
    #pragma unroll
    for (int i = 0; i < 16; i++) {
        int lin = i * 256 + t;
        int s = lin >> 4, dp = lin & 15;
        float2 v = *(const float2*)&vt[vb + (size_t)s * HDIM + dp * 2];
        u32 hh;
        f16pack2(v.x, v.y, hh);
        VHu[s * 20 + dp] = hh;
    }
    #pragma unroll
    for (int i = 0; i < 4; i++) {
        int lin = i * 256 + t;
        int s = lin >> 2, c = lin & 3;
        VHu[s * 20 + 16 + c] = (c == 0) ? 0x00003C00u : 0u;
    }
    __syncthreads();
    u32 aQH = (u32)__cvta_generic_to_shared(sm + AT_QH);
    u32 aKH = (u32)__cvta_generic_to_shared(sm + AT_KH);
    u32 aVH = (u32)__cvta_generic_to_shared(sm + AT_VH);
    float acc[32][4];
    #pragma unroll
    for (int i = 0; i < 32; i++)
        #pragma unroll
        for (int j = 0; j < 4; j++) acc[i][j] = 0.f;
    #pragma unroll
    for (int kt = 0; kt < 2; kt++) {
        u32 qh[4];
        ldA_mk(qh, aQH, 40, w * 16, kt * 16, lane);
        #pragma unroll
        for (int sg = 0; sg < 16; sg++) {
            u32 kh[4];
            ldB_kn(kh, aKH, 264, kt * 16, sg * 16, lane);
            mma_f16(acc[sg * 2],     qh, kh[0], kh[1]);
            mma_f16(acc[sg * 2 + 1], qh, kh[2], kh[3]);
        }
    }
    float mx0 = -CUDART_INF_F, mx1 = -CUDART_INF_F;
    #pragma unroll
    for (int i = 0; i < 32; i++) {
        mx0 = fmaxf(mx0, fmaxf(acc[i][0], acc[i][1]));
        mx1 = fmaxf(mx1, fmaxf(acc[i][2], acc[i][3]));
    }
    mx0 = fmaxf(mx0, __shfl_xor_sync(0xffffffffu, mx0, 1));
    mx0 = fmaxf(mx0, __shfl_xor_sync(0xffffffffu, mx0, 2));
    mx1 = fmaxf(mx1, __shfl_xor_sync(0xffffffffu, mx1, 1));
    mx1 = fmaxf(mx1, __shfl_xor_sync(0xffffffffu, mx1, 2));
    u32 p0[32], p1[32];
    #pragma unroll
    for (int i = 0; i < 32; i++) {
        u32 a0, a1;
        f16pack2(acc[i][0] - mx0, acc[i][1] - mx0, a0);
        f16pack2(acc[i][2] - mx1, acc[i][3] - mx1, a1);
        p0[i] = ex2h2(a0);
        p1[i] = ex2h2(a1);
    }
    float oacc[4][4] = {};
    float osum[4] = {};
    #pragma unroll
    for (int kt = 0; kt < 16; kt++) {
        u32 ah[4] = {p0[2 * kt], p1[2 * kt], p0[2 * kt + 1], p1[2 * kt + 1]};
        u32 vh[2][4];
        ldB_kn(vh[0], aVH, 40, kt * 16, 0, lane);
        ldB_kn(vh[1], aVH, 40, kt * 16, 16, lane);
        u32 s0f, s1f;
        ldsm2t(s0f, s1f, aVH + (u32)(((kt * 16 + (lane & 15)) * 40 + 32) * 2));
        mma_f16(oacc[0], ah, vh[0][0], vh[0][1]);
        mma_f16(oacc[1], ah, vh[0][2], vh[0][3]);
        mma_f16(oacc[2], ah, vh[1][0], vh[1][1]);
        mma_f16(oacc[3], ah, vh[1][2], vh[1][3]);
        mma_f16(osum, ah, s0f, s1f);
    }
    float sm0 = __shfl_sync(0xffffffffu, osum[0], lane & ~3);
    float sm1 = __shfl_sync(0xffffffffu, osum[2], lane & ~3);
    float zi0 = 1.f / sm0, zi1 = 1.f / sm1;
    #pragma unroll
    for (int dt = 0; dt < 4; dt++) {
        size_t i0 = (size_t)(b * NTOK + n0 + w * 16 + r) * 128 + h * 16 + dt * 4 + mu;
        size_t i1 = (size_t)(b * NTOK + n0 + w * 16 + r + 8) * 128 + h * 16 + dt * 4 + mu;
        u32 hh;
        f16pack2(oacc[dt][0] * zi0, oacc[dt][1] * zi0, hh);
        aoh[i0] = hh;
        f16pack2(oacc[dt][2] * zi1, oacc[dt][3] * zi1, hh);
        aoh[i1] = hh;
    }
}

// ================= O projection: single-term fp16, double-buffered + transpose =================
#define OP_STG 18944                      // per-stage: A 10240 + B 8704
#define OP_SMEM 67584                     // >= 2*OP_STG (37888) and Cs (67584)
__global__ __launch_bounds__(512, 1) void oproj_mma_kernel(
        const float* __restrict__ W, const float* __restrict__ bias,
        float* __restrict__ Out) {
    extern __shared__ char sm[];
    const u32* aoh = (const u32*)(g_scr + OFF_AO);
    int b = blockIdx.z;
    int n0 = blockIdx.y * 128, j0 = blockIdx.x * 128;
    int t = threadIdx.x;
    int w = t >> 5, lane = t & 31;
    int wm = w & 3, wn = w >> 2;
    int mu = lane & 3, r = lane >> 2;
    u32 smb = (u32)__cvta_generic_to_shared(sm);
    float acc[2][4][4] = {};
    u32 pa[4], pb[4];
    // prologue: stage panel 0
    #pragma unroll
    for (int i = 0; i < 4; i++) {
        int lin = i * 512 + t;
        int m = lin >> 4, j = lin & 15;
        pa[i] = aoh[(size_t)(b * NTOK + n0 + m) * 128 + j];
    }
    ldg_cvt_512(W + j0, CC, t, pb);
    {
        u32* AHs = (u32*)sm;
        #pragma unroll
        for (int i = 0; i < 4; i++) {
            int lin = i * 512 + t;
            int m = lin >> 4, j = lin & 15;
            AHs[m * 20 + j] = pa[i];
        }
        sts_512(sm + 10240, t, pb);
    }
    __syncthreads();
    for (int kp = 0; kp < 8; kp++) {
        if (kp < 7) {
            #pragma unroll
            for (int i = 0; i < 4; i++) {
                int lin = i * 512 + t;
                int m = lin >> 4, j = lin & 15;
                pa[i] = aoh[(size_t)(b * NTOK + n0 + m) * 128 + (kp + 1) * 16 + j];
            }
            ldg_cvt_512(W + (size_t)(kp + 1) * 32 * CC + j0, CC, t, pb);
        }
        u32 aBuf = smb + (u32)((kp & 1) * OP_STG);
        u32 bBuf = aBuf + 10240;
        #pragma unroll
        for (int kt = 0; kt < 2; kt++) {
            u32 ah[2][4];
            #pragma unroll
            for (int mt = 0; mt < 2; mt++)
                ldA_mk(ah[mt], aBuf, 40, wm * 32 + mt * 16, kt * 16, lane);
            #pragma unroll
            for (int ng = 0; ng < 2; ng++) {
                u32 bh[4];
                ldB_kn(bh, bBuf, 136, kt * 16, wn * 32 + ng * 16, lane);
                #pragma unroll
                for (int mt = 0; mt < 2; mt++) {
                    mma_f16(acc[mt][ng * 2],     ah[mt], bh[0], bh[1]);
                    mma_f16(acc[mt][ng * 2 + 1], ah[mt], bh[2], bh[3]);
                }
            }
        }
        if (kp < 7) {
            char* nxt = sm + ((kp + 1) & 1) * OP_STG;
            u32* AHs = (u32*)nxt;
            #pragma unroll
            for (int i = 0; i < 4; i++) {
                int lin = i * 512 + t;
                int m = lin >> 4, j = lin & 15;
                AHs[m * 20 + j] = pa[i];
            }
            sts_512(nxt + 10240, t, pb);
        }
        __syncthreads();
    }
    float* Cs = (float*)sm;
    __syncthreads();
    #pragma unroll
    for (int mt = 0; mt < 2; mt++)
        #pragma unroll
        for (int j = 0; j < 4; j++)
            #pragma unroll
            for (int half = 0; half < 2; half++) {
                int ml = wm * 32 + mt * 16 + r + half * 8;
                int jl = wn * 32 + j * 8 + 2 * mu;
                Cs[jl * 132 + ml]       = acc[mt][j][half * 2];
                Cs[(jl + 1) * 132 + ml] = acc[mt][j][half * 2 + 1];
            }
    __syncthreads();
    #pragma unroll
    for (int i = 0; i < 8; i++) {
        int lin = i * 512 + t;
        int j = lin >> 5, mq = (lin & 31) * 4;
        float4 v = *(float4*)&Cs[j * 132 + mq];
        float bv = bias[j0 + j];
        v.x += bv; v.y += bv; v.z += bv; v.w += bv;
        *(float4*)&Out[((size_t)b * CC + j0 + j) * NTOK + n0 + mq] = v;
    }
}

// ---------------- launch ----------------
extern "C" void kernel_launch(void* const* d_in, const int* in_sizes, int n_in,
                              void* d_out, int out_size) {
    const float* fv   = (const float*)d_in[0];
    const float* text = (const float*)d_in[1];
    const float* q_w  = (const float*)d_in[2];
    const float* q_b  = (const float*)d_in[3];
    const float* k_w  = (const float*)d_in[4];
    const float* k_b  = (const float*)d_in[5];
    const float* v_w  = (const float*)d_in[6];
    const float* v_b  = (const float*)d_in[7];
    const float* o_w  = (const float*)d_in[8];
    const float* o_b  = (const float*)d_in[9];
    const float* m1_w = (const float*)d_in[10];
    const float* m1_b = (const float*)d_in[11];
    const float* m2_w = (const float*)d_in[12];
    const float* m2_b = (const float*)d_in[13];
    float* out = (float*)d_out;

    init_invf_kernel<<<1, 32>>>();
    text3_kernel<<<dim3(4, 16, 3), 256>>>(text, k_w, k_b, v_w, v_b, m1_w, m1_b);
    phase_rope_kernel<<<dim3(4, 16), 256>>>(m2_w, m2_b);

    qproj_mma_kernel<<<dim3(2, 256, 2), 512>>>(fv, q_w, q_b);

    cudaFuncSetAttribute(attn_mma_kernel, cudaFuncAttributeMaxDynamicSharedMemorySize, AT_SMEM);
    attn_mma_kernel<<<dim3(256, 8, 2), 256, AT_SMEM>>>();

    cudaFuncSetAttribute(oproj_mma_kernel, cudaFuncAttributeMaxDynamicSharedMemorySize, OP_SMEM);
    oproj_mma_kernel<<<dim3(2, 256, 2), 512, OP_SMEM>>>(o_w, o_b, out);
}